// round 8
// baseline (speedup 1.0000x reference)
#include <cuda_runtime.h>
#include <cuda_bf16.h>
#include <math.h>
#include <stdint.h>

// Problem constants
#define B_ 2
#define S_ 2048
#define H_ 4096
#define NH 32
#define HD 128
#define BS_ (B_ * S_)          // 4096 rows
#define QKV_N (3 * H_)         // 12288

// ---------------------------------------------------------------------------
// Scratch (static device globals)
// ---------------------------------------------------------------------------
__device__ float g_qkv[(size_t)BS_ * QKV_N];
__device__ __nv_bfloat16 g_xh[(size_t)BS_ * H_];
__device__ __nv_bfloat16 g_xl[(size_t)BS_ * H_];
__device__ __nv_bfloat16 g_wqh[(size_t)QKV_N * H_];
__device__ __nv_bfloat16 g_wql[(size_t)QKV_N * H_];
__device__ __nv_bfloat16 g_woh[(size_t)H_ * H_];
__device__ __nv_bfloat16 g_wol[(size_t)H_ * H_];
__device__ __nv_bfloat16 g_ch[(size_t)BS_ * H_];
__device__ __nv_bfloat16 g_cl[(size_t)BS_ * H_];
__device__ __nv_bfloat16 g_qh[(size_t)BS_ * H_];
__device__ __nv_bfloat16 g_ql[(size_t)BS_ * H_];
__device__ __nv_bfloat16 g_kh[(size_t)BS_ * H_];
__device__ __nv_bfloat16 g_kl[(size_t)BS_ * H_];
__device__ __nv_bfloat16 g_vth[(size_t)BS_ * H_];
__device__ __nv_bfloat16 g_vtl[(size_t)BS_ * H_];
__device__ float g_rcos[S_ * 64];
__device__ float g_rsin[S_ * 64];

// ---------------------------------------------------------------------------
// mma.sync + cp.async helpers
// ---------------------------------------------------------------------------
__device__ __forceinline__ uint32_t smem_u32(const void* p) {
    uint32_t a;
    asm("{ .reg .u64 t; cvta.to.shared.u64 t, %1; cvt.u32.u64 %0, t; }"
        : "=r"(a) : "l"(p));
    return a;
}

#define CP_ASYNC16(dst, src) \
    asm volatile("cp.async.cg.shared.global [%0], [%1], 16;" \
                 :: "r"(dst), "l"(src) : "memory")
#define CP_COMMIT() asm volatile("cp.async.commit_group;" ::: "memory")
#define CP_WAIT1()  asm volatile("cp.async.wait_group 1;" ::: "memory")
#define CP_WAIT0()  asm volatile("cp.async.wait_group 0;" ::: "memory")

__device__ __forceinline__ void mma_bf16(float* d, const uint32_t* a,
                                         uint32_t b0, uint32_t b1) {
    asm volatile(
        "mma.sync.aligned.m16n8k16.row.col.f32.bf16.bf16.f32 "
        "{%0,%1,%2,%3}, {%4,%5,%6,%7}, {%8,%9}, {%0,%1,%2,%3};"
        : "+f"(d[0]), "+f"(d[1]), "+f"(d[2]), "+f"(d[3])
        : "r"(a[0]), "r"(a[1]), "r"(a[2]), "r"(a[3]), "r"(b0), "r"(b1));
}

__device__ __forceinline__ uint32_t packbf(float a, float b) {
    uint32_t lo = __bfloat16_as_ushort(__float2bfloat16(a));
    uint32_t hi = __bfloat16_as_ushort(__float2bfloat16(b));
    return lo | (hi << 16);
}

// ---------------------------------------------------------------------------
// bf16x3 mma.sync GEMM:  C[M,N] = A * B^T  (A [M,K], B [N,K])
// Tile 128x128, BK=32, 128 threads (4 warps; warp tile 64x64),
// 2-stage cp.async, 2 CTAs/SM for cross-CTA latency hiding.
// C = Ah*Bh + Al*Bh + Ah*Bl.
// ---------------------------------------------------------------------------
#define SA_STRIDE 80
#define OFF_AH 0
#define OFF_AL 10240
#define OFF_BH 20480
#define OFF_BL 30720
#define STAGE_BYTES 40960
#define GEMM_SMEM (2 * STAGE_BYTES)   // 81920 per CTA; 2 CTAs = 163840/SM

__global__ __launch_bounds__(128, 2) void gemm_bf16x3mma(
    const __nv_bfloat16* __restrict__ Ah, const __nv_bfloat16* __restrict__ Al,
    const __nv_bfloat16* __restrict__ Bh, const __nv_bfloat16* __restrict__ Bl,
    float* __restrict__ C, int Nglob, int K)
{
    extern __shared__ char smem[];
    const int tid  = threadIdx.x;
    const int lane = tid & 31;
    const int wid  = tid >> 5;          // 0..3
    const int wm = wid & 1;             // 64-row half
    const int wn = wid >> 1;            // 64-col half
    const int bm = blockIdx.x * 128;
    const int bn = blockIdx.y * 128;

    const uint32_t sb = smem_u32(smem);
    const int nchunk = K >> 5;          // BK=32

    auto load_chunk = [&](int c, int s) {
        const int k0 = c << 5;
        const uint32_t st = sb + s * STAGE_BYTES;
        #pragma unroll
        for (int i = 0; i < 4; i++) {
            const int idx = tid + i * 128;          // 0..511
            const int r = idx >> 2, seg = idx & 3;
            const uint32_t so = r * SA_STRIDE + seg * 16;
            const size_t goA = (size_t)(bm + r) * K + k0 + seg * 8;
            CP_ASYNC16(st + OFF_AH + so, Ah + goA);
            CP_ASYNC16(st + OFF_AL + so, Al + goA);
            const size_t goB = (size_t)(bn + r) * K + k0 + seg * 8;
            CP_ASYNC16(st + OFF_BH + so, Bh + goB);
            CP_ASYNC16(st + OFF_BL + so, Bl + goB);
        }
        CP_COMMIT();
    };

    float acc[4][8][4];
    #pragma unroll
    for (int mt = 0; mt < 4; mt++)
        #pragma unroll
        for (int nt = 0; nt < 8; nt++)
            #pragma unroll
            for (int j = 0; j < 4; j++) acc[mt][nt][j] = 0.f;

    load_chunk(0, 0);
    if (nchunk > 1) load_chunk(1, 1);

    const int arow = wm * 64 + (lane >> 2);
    const int brow = wn * 64 + (lane >> 2);
    const int acol = (lane & 3) * 4;

    for (int c = 0; c < nchunk; c++) {
        if (c + 1 < nchunk) { CP_WAIT1(); } else { CP_WAIT0(); }
        __syncthreads();

        const char* st = smem + (c & 1) * STAGE_BYTES;
        const char* pAh = st + OFF_AH;
        const char* pAl = st + OFF_AL;
        const char* pBh = st + OFF_BH;
        const char* pBl = st + OFF_BL;

        #pragma unroll
        for (int ks = 0; ks < 2; ks++) {
            const int cb = ks * 32 + acol;
            uint32_t ah[4][4], al[4][4];
            #pragma unroll
            for (int mt = 0; mt < 4; mt++) {
                const int r0 = (arow + mt * 16) * SA_STRIDE;
                const int r8 = r0 + 8 * SA_STRIDE;
                ah[mt][0] = *(const uint32_t*)(pAh + r0 + cb);
                ah[mt][1] = *(const uint32_t*)(pAh + r8 + cb);
                ah[mt][2] = *(const uint32_t*)(pAh + r0 + cb + 16);
                ah[mt][3] = *(const uint32_t*)(pAh + r8 + cb + 16);
                al[mt][0] = *(const uint32_t*)(pAl + r0 + cb);
                al[mt][1] = *(const uint32_t*)(pAl + r8 + cb);
                al[mt][2] = *(const uint32_t*)(pAl + r0 + cb + 16);
                al[mt][3] = *(const uint32_t*)(pAl + r8 + cb + 16);
            }
            uint32_t bhf[8][2];
            #pragma unroll
            for (int nt = 0; nt < 8; nt++) {
                const int rb = (brow + nt * 8) * SA_STRIDE;
                bhf[nt][0] = *(const uint32_t*)(pBh + rb + cb);
                bhf[nt][1] = *(const uint32_t*)(pBh + rb + cb + 16);
            }
            #pragma unroll
            for (int nt = 0; nt < 8; nt++)
                #pragma unroll
                for (int mt = 0; mt < 4; mt++)
                    mma_bf16(acc[mt][nt], ah[mt], bhf[nt][0], bhf[nt][1]);
            #pragma unroll
            for (int nt = 0; nt < 8; nt++)
                #pragma unroll
                for (int mt = 0; mt < 4; mt++)
                    mma_bf16(acc[mt][nt], al[mt], bhf[nt][0], bhf[nt][1]);
            #pragma unroll
            for (int nt = 0; nt < 8; nt++) {
                const int rb = (brow + nt * 8) * SA_STRIDE;
                const uint32_t bl0 = *(const uint32_t*)(pBl + rb + cb);
                const uint32_t bl1 = *(const uint32_t*)(pBl + rb + cb + 16);
                #pragma unroll
                for (int mt = 0; mt < 4; mt++)
                    mma_bf16(acc[mt][nt], ah[mt], bl0, bl1);
            }
        }
        __syncthreads();
        if (c + 2 < nchunk) load_chunk(c + 2, c & 1);
    }

    #pragma unroll
    for (int mt = 0; mt < 4; mt++) {
        const int row = bm + wm * 64 + mt * 16 + (lane >> 2);
        float* cp0 = C + (size_t)row * Nglob + bn + wn * 64 + (lane & 3) * 2;
        float* cp8 = cp0 + 8 * (size_t)Nglob;
        #pragma unroll
        for (int nt = 0; nt < 8; nt++) {
            *(float2*)(cp0 + nt * 8) = make_float2(acc[mt][nt][0], acc[mt][nt][1]);
            *(float2*)(cp8 + nt * 8) = make_float2(acc[mt][nt][2], acc[mt][nt][3]);
        }
    }
}

// ---------------------------------------------------------------------------
// Elementwise fp32 -> (bf16 hi, bf16 lo) split
// ---------------------------------------------------------------------------
__global__ void split_kernel(const float4* __restrict__ in,
                             uint2* __restrict__ h, uint2* __restrict__ l, int n4)
{
    const int i = blockIdx.x * blockDim.x + threadIdx.x;
    if (i >= n4) return;
    const float4 v = in[i];
    __nv_bfloat16 h0 = __float2bfloat16(v.x), h1 = __float2bfloat16(v.y);
    __nv_bfloat16 h2 = __float2bfloat16(v.z), h3 = __float2bfloat16(v.w);
    __nv_bfloat16 l0 = __float2bfloat16(v.x - __bfloat162float(h0));
    __nv_bfloat16 l1 = __float2bfloat16(v.y - __bfloat162float(h1));
    __nv_bfloat16 l2 = __float2bfloat16(v.z - __bfloat162float(h2));
    __nv_bfloat16 l3 = __float2bfloat16(v.w - __bfloat162float(h3));
    uint2 hh, ll;
    hh.x = (uint32_t)__bfloat16_as_ushort(h0) | ((uint32_t)__bfloat16_as_ushort(h1) << 16);
    hh.y = (uint32_t)__bfloat16_as_ushort(h2) | ((uint32_t)__bfloat16_as_ushort(h3) << 16);
    ll.x = (uint32_t)__bfloat16_as_ushort(l0) | ((uint32_t)__bfloat16_as_ushort(l1) << 16);
    ll.y = (uint32_t)__bfloat16_as_ushort(l2) | ((uint32_t)__bfloat16_as_ushort(l3) << 16);
    h[i] = hh; l[i] = ll;
}

// ---------------------------------------------------------------------------
// Transpose + split: W [K,N] fp32 -> Wt hi/lo [N,K] bf16
// ---------------------------------------------------------------------------
__global__ void transpose_split(const float* __restrict__ W,
                                __nv_bfloat16* __restrict__ Th,
                                __nv_bfloat16* __restrict__ Tl, int K, int N)
{
    __shared__ float t[32][33];
    const int tx = threadIdx.x, ty = threadIdx.y;
    const int nx = blockIdx.x * 32;
    const int ky = blockIdx.y * 32;
    #pragma unroll
    for (int j = 0; j < 32; j += 8)
        t[ty + j][tx] = W[(size_t)(ky + ty + j) * N + nx + tx];
    __syncthreads();
    #pragma unroll
    for (int j = 0; j < 32; j += 8) {
        const float v = t[tx][ty + j];
        const __nv_bfloat16 hi = __float2bfloat16(v);
        const __nv_bfloat16 lo = __float2bfloat16(v - __bfloat162float(hi));
        const size_t o = (size_t)(nx + ty + j) * K + ky + tx;
        Th[o] = hi; Tl[o] = lo;
    }
}

// ---------------------------------------------------------------------------
// RoPE cos/sin tables
// ---------------------------------------------------------------------------
__global__ void rope_tab(float* __restrict__ c, float* __restrict__ s)
{
    const int i = blockIdx.x * blockDim.x + threadIdx.x;
    const int t = i >> 6, p = i & 63;
    const float inv_freq = powf(10000.0f, -(float)p * (1.0f / 64.0f));
    float sn, cs;
    sincosf((float)t * inv_freq, &sn, &cs);
    c[i] = cs; s[i] = sn;
}

// ---------------------------------------------------------------------------
// prep_qkv: RoPE + scale + split hi/lo head-major; v transpose+split.
// ---------------------------------------------------------------------------
#define PREP_SMEM (128 * 133 * 4)

__global__ __launch_bounds__(256, 1) void prep_qkv(
    const float* __restrict__ qkv,
    const float* __restrict__ rc, const float* __restrict__ rs,
    __nv_bfloat16* __restrict__ Qh, __nv_bfloat16* __restrict__ Ql,
    __nv_bfloat16* __restrict__ Kh, __nv_bfloat16* __restrict__ Kl,
    __nv_bfloat16* __restrict__ Vh, __nv_bfloat16* __restrict__ Vl)
{
    extern __shared__ float ps[];
    const int tid = threadIdx.x;
    const int bh = blockIdx.y;
    const int b = bh >> 5, h = bh & 31;
    const int s0 = blockIdx.x * 128;
    const float scale = 0.08838834764831843f;

    #pragma unroll 4
    for (int i = 0; i < 32; i++) {
        const int idx = tid + i * 256;
        const int sr = idx >> 6, p = idx & 63;
        const int sg = s0 + sr;
        const size_t base = ((size_t)b * S_ + sg) * QKV_N + h * HD;
        const float cs = rc[sg * 64 + p], sn = rs[sg * 64 + p];
        const float q1 = qkv[base + p],        q2 = qkv[base + p + 64];
        const float k1 = qkv[base + H_ + p],   k2 = qkv[base + H_ + p + 64];
        const float qa = (q1 * cs - q2 * sn) * scale;
        const float qb = (q2 * cs + q1 * sn) * scale;
        const float ka = k1 * cs - k2 * sn;
        const float kb = k2 * cs + k1 * sn;
        const size_t ob = ((size_t)bh * S_ + sg) * HD;
        __nv_bfloat16 t;
        t = __float2bfloat16(qa); Qh[ob + p] = t;      Ql[ob + p]      = __float2bfloat16(qa - __bfloat162float(t));
        t = __float2bfloat16(qb); Qh[ob + p + 64] = t; Ql[ob + p + 64] = __float2bfloat16(qb - __bfloat162float(t));
        t = __float2bfloat16(ka); Kh[ob + p] = t;      Kl[ob + p]      = __float2bfloat16(ka - __bfloat162float(t));
        t = __float2bfloat16(kb); Kh[ob + p + 64] = t; Kl[ob + p + 64] = __float2bfloat16(kb - __bfloat162float(t));
    }

    #pragma unroll 4
    for (int i = 0; i < 64; i++) {
        const int idx = tid + i * 256;
        const int sr = idx >> 7, p = idx & 127;
        ps[sr * 133 + p] = qkv[((size_t)b * S_ + s0 + sr) * QKV_N + h * HD + 2 * H_ + p];
    }
    __syncthreads();
    #pragma unroll 4
    for (int i = 0; i < 64; i++) {
        const int idx = tid + i * 256;
        const int d = idx >> 7, sr = idx & 127;
        const float v = ps[sr * 133 + d];
        const __nv_bfloat16 hi = __float2bfloat16(v);
        const size_t o = ((size_t)bh * HD + d) * S_ + s0 + sr;
        Vh[o] = hi;
        Vl[o] = __float2bfloat16(v - __bfloat162float(hi));
    }
}

// ---------------------------------------------------------------------------
// Flash attention, mma.sync bf16x3 (unchanged)
// ---------------------------------------------------------------------------
#define FQ_LD 136
#define FV_LD 72
#define SQ_ELEMS (128 * FQ_LD)
#define SK_ELEMS (64 * FQ_LD)
#define SV_ELEMS (128 * FV_LD)
#define FSTAGE (2 * SK_ELEMS + 2 * SV_ELEMS)
#define FLASH_SMEM ((2 * SQ_ELEMS + 2 * FSTAGE) * 2)

__global__ __launch_bounds__(256, 1) void flash_mma(
    const __nv_bfloat16* __restrict__ Qh, const __nv_bfloat16* __restrict__ Ql,
    const __nv_bfloat16* __restrict__ Kh, const __nv_bfloat16* __restrict__ Kl,
    const __nv_bfloat16* __restrict__ Vh, const __nv_bfloat16* __restrict__ Vl,
    __nv_bfloat16* __restrict__ Ch, __nv_bfloat16* __restrict__ Cl)
{
    extern __shared__ __nv_bfloat16 fs[];
    const int tid = threadIdx.x;
    const int lane = tid & 31;
    const int w = tid >> 5;
    const int qblk = blockIdx.x;
    const int bh = blockIdx.y;
    const int b = bh >> 5, h = bh & 31;
    const int q0 = qblk * 128;
    const uint32_t sb = smem_u32(fs);

    const size_t hoff = (size_t)bh * S_ * HD;
    const size_t voff = (size_t)bh * HD * S_;

    #pragma unroll
    for (int i = 0; i < 8; i++) {
        const int idx = tid + i * 256;
        const int r = idx >> 4, seg = idx & 15;
        const size_t go = hoff + (size_t)(q0 + r) * HD + seg * 8;
        const uint32_t so = (r * FQ_LD + seg * 8) * 2;
        CP_ASYNC16(sb + so, Qh + go);
        CP_ASYNC16(sb + SQ_ELEMS * 2 + so, Ql + go);
    }

    auto load_kv = [&](int t, int s) {
        const int k0 = t * 64;
        const uint32_t st = sb + (2 * SQ_ELEMS + s * FSTAGE) * 2;
        #pragma unroll
        for (int i = 0; i < 4; i++) {
            const int idx = tid + i * 256;
            const int r = idx >> 4, seg = idx & 15;
            const size_t go = hoff + (size_t)(k0 + r) * HD + seg * 8;
            const uint32_t so = (r * FQ_LD + seg * 8) * 2;
            CP_ASYNC16(st + so, Kh + go);
            CP_ASYNC16(st + SK_ELEMS * 2 + so, Kl + go);
        }
        #pragma unroll
        for (int i = 0; i < 4; i++) {
            const int idx = tid + i * 256;
            const int r = idx >> 3, seg = idx & 7;
            const size_t go = voff + (size_t)r * S_ + k0 + seg * 8;
            const uint32_t so = (2 * SK_ELEMS + r * FV_LD + seg * 8) * 2;
            CP_ASYNC16(st + so, Vh + go);
            CP_ASYNC16(st + SV_ELEMS * 2 + so, Vl + go);
        }
        CP_COMMIT();
    };

    load_kv(0, 0);

    float O[16][4];
    #pragma unroll
    for (int i = 0; i < 16; i++)
        #pragma unroll
        for (int j = 0; j < 4; j++) O[i][j] = 0.f;
    float m0 = -1e30f, m1 = -1e30f, l0 = 0.f, l1 = 0.f;

    const int r0 = w * 16 + (lane >> 2);
    const int cq = (lane & 3) * 2;
    const int ntiles = 2 * qblk + 2;

    for (int t = 0; t < ntiles; t++) {
        if (t + 1 < ntiles) { load_kv(t + 1, (t + 1) & 1); CP_WAIT1(); }
        else                { CP_WAIT0(); }
        __syncthreads();

        const __nv_bfloat16* sQh = fs;
        const __nv_bfloat16* sQl = fs + SQ_ELEMS;
        const __nv_bfloat16* sKh = fs + 2 * SQ_ELEMS + (t & 1) * FSTAGE;
        const __nv_bfloat16* sKl = sKh + SK_ELEMS;
        const __nv_bfloat16* sVh = sKl + SK_ELEMS;
        const __nv_bfloat16* sVl = sVh + SV_ELEMS;

        float Sf[8][4];
        #pragma unroll
        for (int nt = 0; nt < 8; nt++)
            #pragma unroll
            for (int j = 0; j < 4; j++) Sf[nt][j] = 0.f;

        #pragma unroll
        for (int kk = 0; kk < 8; kk++) {
            uint32_t ah[4], al[4];
            const __nv_bfloat16* qp = sQh + r0 * FQ_LD + kk * 16 + cq;
            const __nv_bfloat16* qp2 = sQl + r0 * FQ_LD + kk * 16 + cq;
            ah[0] = *(const uint32_t*)(qp);
            ah[1] = *(const uint32_t*)(qp + 8 * FQ_LD);
            ah[2] = *(const uint32_t*)(qp + 8);
            ah[3] = *(const uint32_t*)(qp + 8 * FQ_LD + 8);
            al[0] = *(const uint32_t*)(qp2);
            al[1] = *(const uint32_t*)(qp2 + 8 * FQ_LD);
            al[2] = *(const uint32_t*)(qp2 + 8);
            al[3] = *(const uint32_t*)(qp2 + 8 * FQ_LD + 8);
            uint32_t khf[8][2];
            #pragma unroll
            for (int nt = 0; nt < 8; nt++) {
                const int n = nt * 8 + (lane >> 2);
                const __nv_bfloat16* kp = sKh + n * FQ_LD + kk * 16 + cq;
                khf[nt][0] = *(const uint32_t*)(kp);
                khf[nt][1] = *(const uint32_t*)(kp + 8);
            }
            #pragma unroll
            for (int nt = 0; nt < 8; nt++)
                mma_bf16(Sf[nt], ah, khf[nt][0], khf[nt][1]);
            #pragma unroll
            for (int nt = 0; nt < 8; nt++)
                mma_bf16(Sf[nt], al, khf[nt][0], khf[nt][1]);
            #pragma unroll
            for (int nt = 0; nt < 8; nt++) {
                const int n = nt * 8 + (lane >> 2);
                const __nv_bfloat16* kp2 = sKl + n * FQ_LD + kk * 16 + cq;
                mma_bf16(Sf[nt], ah, *(const uint32_t*)(kp2),
                                     *(const uint32_t*)(kp2 + 8));
            }
        }

        const int k0 = t * 64;
        const int qg0 = q0 + r0, qg1 = qg0 + 8;
        if (k0 + 63 > q0 + w * 16) {
            #pragma unroll
            for (int nt = 0; nt < 8; nt++) {
                const int kv = k0 + nt * 8 + cq;
                if (kv     > qg0) Sf[nt][0] = -1e30f;
                if (kv + 1 > qg0) Sf[nt][1] = -1e30f;
                if (kv     > qg1) Sf[nt][2] = -1e30f;
                if (kv + 1 > qg1) Sf[nt][3] = -1e30f;
            }
        }
        float mx0 = -1e30f, mx1 = -1e30f;
        #pragma unroll
        for (int nt = 0; nt < 8; nt++) {
            mx0 = fmaxf(mx0, fmaxf(Sf[nt][0], Sf[nt][1]));
            mx1 = fmaxf(mx1, fmaxf(Sf[nt][2], Sf[nt][3]));
        }
        mx0 = fmaxf(mx0, __shfl_xor_sync(0xffffffffu, mx0, 1));
        mx0 = fmaxf(mx0, __shfl_xor_sync(0xffffffffu, mx0, 2));
        mx1 = fmaxf(mx1, __shfl_xor_sync(0xffffffffu, mx1, 1));
        mx1 = fmaxf(mx1, __shfl_xor_sync(0xffffffffu, mx1, 2));

        const float mn0 = fmaxf(m0, mx0), mn1 = fmaxf(m1, mx1);
        const float a0 = __expf(m0 - mn0), a1 = __expf(m1 - mn1);
        m0 = mn0; m1 = mn1;

        float s0 = 0.f, s1 = 0.f;
        uint32_t Ph[8][2], Pl[8][2];
        #pragma unroll
        for (int nt = 0; nt < 8; nt++) {
            const float p00 = __expf(Sf[nt][0] - mn0);
            const float p01 = __expf(Sf[nt][1] - mn0);
            const float p10 = __expf(Sf[nt][2] - mn1);
            const float p11 = __expf(Sf[nt][3] - mn1);
            s0 += p00 + p01; s1 += p10 + p11;
            const __nv_bfloat16 h00 = __float2bfloat16(p00);
            const __nv_bfloat16 h01 = __float2bfloat16(p01);
            const __nv_bfloat16 h10 = __float2bfloat16(p10);
            const __nv_bfloat16 h11 = __float2bfloat16(p11);
            Ph[nt][0] = (uint32_t)__bfloat16_as_ushort(h00) | ((uint32_t)__bfloat16_as_ushort(h01) << 16);
            Ph[nt][1] = (uint32_t)__bfloat16_as_ushort(h10) | ((uint32_t)__bfloat16_as_ushort(h11) << 16);
            Pl[nt][0] = packbf(p00 - __bfloat162float(h00), p01 - __bfloat162float(h01));
            Pl[nt][1] = packbf(p10 - __bfloat162float(h10), p11 - __bfloat162float(h11));
        }
        s0 += __shfl_xor_sync(0xffffffffu, s0, 1);
        s0 += __shfl_xor_sync(0xffffffffu, s0, 2);
        s1 += __shfl_xor_sync(0xffffffffu, s1, 1);
        s1 += __shfl_xor_sync(0xffffffffu, s1, 2);
        l0 = l0 * a0 + s0;
        l1 = l1 * a1 + s1;

        #pragma unroll
        for (int i = 0; i < 16; i++) {
            O[i][0] *= a0; O[i][1] *= a0; O[i][2] *= a1; O[i][3] *= a1;
        }

        #pragma unroll
        for (int ks = 0; ks < 4; ks++) {
            const uint32_t ah[4] = {Ph[2 * ks][0], Ph[2 * ks][1],
                                    Ph[2 * ks + 1][0], Ph[2 * ks + 1][1]};
            const uint32_t al[4] = {Pl[2 * ks][0], Pl[2 * ks][1],
                                    Pl[2 * ks + 1][0], Pl[2 * ks + 1][1]};
            #pragma unroll
            for (int nt2 = 0; nt2 < 16; nt2++) {
                const int nd = nt2 * 8 + (lane >> 2);
                const __nv_bfloat16* vp = sVh + nd * FV_LD + ks * 16 + cq;
                mma_bf16(O[nt2], ah, *(const uint32_t*)(vp),
                                     *(const uint32_t*)(vp + 8));
            }
            #pragma unroll
            for (int nt2 = 0; nt2 < 16; nt2++) {
                const int nd = nt2 * 8 + (lane >> 2);
                const __nv_bfloat16* vp2 = sVl + nd * FV_LD + ks * 16 + cq;
                mma_bf16(O[nt2], ah, *(const uint32_t*)(vp2),
                                     *(const uint32_t*)(vp2 + 8));
            }
            #pragma unroll
            for (int nt2 = 0; nt2 < 16; nt2++) {
                const int nd = nt2 * 8 + (lane >> 2);
                const __nv_bfloat16* vp = sVh + nd * FV_LD + ks * 16 + cq;
                mma_bf16(O[nt2], al, *(const uint32_t*)(vp),
                                     *(const uint32_t*)(vp + 8));
            }
        }
        __syncthreads();
    }

    const float inv0 = 1.f / l0, inv1 = 1.f / l1;
    const int row0 = q0 + w * 16 + (lane >> 2);
    const size_t o0 = ((size_t)b * S_ + row0) * H_ + h * HD + cq;
    const size_t o1 = o0 + 8 * (size_t)H_;
    #pragma unroll
    for (int nt2 = 0; nt2 < 16; nt2++) {
        const float f0 = O[nt2][0] * inv0, f1 = O[nt2][1] * inv0;
        const float f2 = O[nt2][2] * inv1, f3 = O[nt2][3] * inv1;
        const __nv_bfloat16 h0 = __float2bfloat16(f0), h1 = __float2bfloat16(f1);
        const __nv_bfloat16 h2 = __float2bfloat16(f2), h3 = __float2bfloat16(f3);
        *(uint32_t*)&Ch[o0 + nt2 * 8] =
            (uint32_t)__bfloat16_as_ushort(h0) | ((uint32_t)__bfloat16_as_ushort(h1) << 16);
        *(uint32_t*)&Ch[o1 + nt2 * 8] =
            (uint32_t)__bfloat16_as_ushort(h2) | ((uint32_t)__bfloat16_as_ushort(h3) << 16);
        *(uint32_t*)&Cl[o0 + nt2 * 8] =
            packbf(f0 - __bfloat162float(h0), f1 - __bfloat162float(h1));
        *(uint32_t*)&Cl[o1 + nt2 * 8] =
            packbf(f2 - __bfloat162float(h2), f3 - __bfloat162float(h3));
    }
}

// ---------------------------------------------------------------------------
// Launch
// ---------------------------------------------------------------------------
extern "C" void kernel_launch(void* const* d_in, const int* in_sizes, int n_in,
                              void* d_out, int out_size)
{
    const float* x    = (const float*)d_in[0];
    const float* Wqkv = (const float*)d_in[1];
    const float* Wo   = (const float*)d_in[2];
    float* out = (float*)d_out;

    float *qkv, *rc, *rs;
    __nv_bfloat16 *xh, *xl, *wqh, *wql, *woh, *wol, *ch, *cl;
    __nv_bfloat16 *qh, *ql, *kh, *kl, *vth, *vtl;
    cudaGetSymbolAddress((void**)&qkv, g_qkv);
    cudaGetSymbolAddress((void**)&rc, g_rcos);
    cudaGetSymbolAddress((void**)&rs, g_rsin);
    cudaGetSymbolAddress((void**)&xh, g_xh);
    cudaGetSymbolAddress((void**)&xl, g_xl);
    cudaGetSymbolAddress((void**)&wqh, g_wqh);
    cudaGetSymbolAddress((void**)&wql, g_wql);
    cudaGetSymbolAddress((void**)&woh, g_woh);
    cudaGetSymbolAddress((void**)&wol, g_wol);
    cudaGetSymbolAddress((void**)&ch, g_ch);
    cudaGetSymbolAddress((void**)&cl, g_cl);
    cudaGetSymbolAddress((void**)&qh, g_qh);
    cudaGetSymbolAddress((void**)&ql, g_ql);
    cudaGetSymbolAddress((void**)&kh, g_kh);
    cudaGetSymbolAddress((void**)&kl, g_kl);
    cudaGetSymbolAddress((void**)&vth, g_vth);
    cudaGetSymbolAddress((void**)&vtl, g_vtl);

    cudaFuncSetAttribute(gemm_bf16x3mma,
                         cudaFuncAttributeMaxDynamicSharedMemorySize, GEMM_SMEM);
    cudaFuncSetAttribute(prep_qkv,
                         cudaFuncAttributeMaxDynamicSharedMemorySize, PREP_SMEM);
    cudaFuncSetAttribute(flash_mma,
                         cudaFuncAttributeMaxDynamicSharedMemorySize, FLASH_SMEM);

    {
        const int n4 = (BS_ * H_) / 4;
        split_kernel<<<n4 / 256, 256>>>((const float4*)x, (uint2*)xh, (uint2*)xl, n4);
    }
    {
        dim3 grid(QKV_N / 32, H_ / 32), blk(32, 8);
        transpose_split<<<grid, blk>>>(Wqkv, wqh, wql, H_, QKV_N);
    }
    {
        dim3 grid(H_ / 32, H_ / 32), blk(32, 8);
        transpose_split<<<grid, blk>>>(Wo, woh, wol, H_, H_);
    }
    rope_tab<<<(S_ * 64) / 256, 256>>>(rc, rs);

    {
        dim3 grid(BS_ / 128, QKV_N / 128);
        gemm_bf16x3mma<<<grid, 128, GEMM_SMEM>>>(xh, xl, wqh, wql, qkv, QKV_N, H_);
    }
    {
        dim3 grid(S_ / 128, B_ * NH);
        prep_qkv<<<grid, 256, PREP_SMEM>>>(qkv, rc, rs, qh, ql, kh, kl, vth, vtl);
    }
    {
        dim3 grid(S_ / 128, B_ * NH);
        flash_mma<<<grid, 256, FLASH_SMEM>>>(qh, ql, kh, kl, vth, vtl, ch, cl);
    }
    {
        dim3 grid(BS_ / 128, H_ / 128);
        gemm_bf16x3mma<<<grid, 128, GEMM_SMEM>>>(ch, cl, woh, wol, out, H_, H_);
    }
}

// round 9
// speedup vs baseline: 1.0427x; 1.0427x over previous
#include <cuda_runtime.h>
#include <cuda_bf16.h>
#include <math.h>
#include <stdint.h>

// Problem constants
#define B_ 2
#define S_ 2048
#define H_ 4096
#define NH 32
#define HD 128
#define BS_ (B_ * S_)          // 4096 rows
#define QKV_N (3 * H_)         // 12288

// ---------------------------------------------------------------------------
// Scratch (static device globals)
// ---------------------------------------------------------------------------
__device__ float g_qkv[(size_t)BS_ * QKV_N];
__device__ __nv_bfloat16 g_xh[(size_t)BS_ * H_];
__device__ __nv_bfloat16 g_xl[(size_t)BS_ * H_];
__device__ __nv_bfloat16 g_wqh[(size_t)QKV_N * H_];
__device__ __nv_bfloat16 g_wql[(size_t)QKV_N * H_];
__device__ __nv_bfloat16 g_woh[(size_t)H_ * H_];
__device__ __nv_bfloat16 g_wol[(size_t)H_ * H_];
__device__ __nv_bfloat16 g_ch[(size_t)BS_ * H_];
__device__ __nv_bfloat16 g_cl[(size_t)BS_ * H_];
__device__ __nv_bfloat16 g_qh[(size_t)BS_ * H_];
__device__ __nv_bfloat16 g_ql[(size_t)BS_ * H_];
__device__ __nv_bfloat16 g_kh[(size_t)BS_ * H_];
__device__ __nv_bfloat16 g_kl[(size_t)BS_ * H_];
__device__ __nv_bfloat16 g_vth[(size_t)BS_ * H_];
__device__ __nv_bfloat16 g_vtl[(size_t)BS_ * H_];
__device__ float g_rcos[S_ * 64];
__device__ float g_rsin[S_ * 64];

// ---------------------------------------------------------------------------
// mma.sync + cp.async helpers
// ---------------------------------------------------------------------------
__device__ __forceinline__ uint32_t smem_u32(const void* p) {
    uint32_t a;
    asm("{ .reg .u64 t; cvta.to.shared.u64 t, %1; cvt.u32.u64 %0, t; }"
        : "=r"(a) : "l"(p));
    return a;
}

#define CP_ASYNC16(dst, src) \
    asm volatile("cp.async.cg.shared.global [%0], [%1], 16;" \
                 :: "r"(dst), "l"(src) : "memory")
#define CP_COMMIT() asm volatile("cp.async.commit_group;" ::: "memory")
#define CP_WAIT1()  asm volatile("cp.async.wait_group 1;" ::: "memory")
#define CP_WAIT0()  asm volatile("cp.async.wait_group 0;" ::: "memory")

__device__ __forceinline__ void mma_bf16(float* d, const uint32_t* a,
                                         uint32_t b0, uint32_t b1) {
    asm volatile(
        "mma.sync.aligned.m16n8k16.row.col.f32.bf16.bf16.f32 "
        "{%0,%1,%2,%3}, {%4,%5,%6,%7}, {%8,%9}, {%0,%1,%2,%3};"
        : "+f"(d[0]), "+f"(d[1]), "+f"(d[2]), "+f"(d[3])
        : "r"(a[0]), "r"(a[1]), "r"(a[2]), "r"(a[3]), "r"(b0), "r"(b1));
}

__device__ __forceinline__ uint32_t packbf(float a, float b) {
    uint32_t lo = __bfloat16_as_ushort(__float2bfloat16(a));
    uint32_t hi = __bfloat16_as_ushort(__float2bfloat16(b));
    return lo | (hi << 16);
}

// pack two f32 -> bf16x2 in ONE instruction (lo = first arg)
#define CVTBF2(r, flo, fhi) \
    asm("cvt.rn.bf16x2.f32 %0, %1, %2;" : "=r"(r) : "f"(fhi), "f"(flo))

// ---------------------------------------------------------------------------
// bf16x3 mma.sync GEMM (R7 config):  C[M,N] = A * B^T  (A [M,K], B [N,K])
// Tile 128x256, BK=64, 256 threads (8 warps; warp tile 64x64), 2-stage.
// ---------------------------------------------------------------------------
#define SA_STRIDE 144
#define OFF_AH 0
#define OFF_AL (128 * SA_STRIDE)
#define OFF_BH (2 * 128 * SA_STRIDE)
#define OFF_BL (2 * 128 * SA_STRIDE + 256 * SA_STRIDE)
#define STAGE_BYTES (2 * 128 * SA_STRIDE + 2 * 256 * SA_STRIDE)  // 110592
#define GEMM_SMEM (2 * STAGE_BYTES)             // 221184

__global__ __launch_bounds__(256, 1) void gemm_bf16x3mma(
    const __nv_bfloat16* __restrict__ Ah, const __nv_bfloat16* __restrict__ Al,
    const __nv_bfloat16* __restrict__ Bh, const __nv_bfloat16* __restrict__ Bl,
    float* __restrict__ C, int Nglob, int K)
{
    extern __shared__ char smem[];
    const int tid  = threadIdx.x;
    const int lane = tid & 31;
    const int wid  = tid >> 5;
    const int wm = wid & 1;
    const int wn = wid >> 1;
    const int bm = blockIdx.x * 128;
    const int bn = blockIdx.y * 256;

    const uint32_t sb = smem_u32(smem);
    const int nchunk = K >> 6;

    auto load_chunk = [&](int c, int s) {
        const int k0 = c << 6;
        const uint32_t st = sb + s * STAGE_BYTES;
        #pragma unroll
        for (int i = 0; i < 4; i++) {
            const int idx = tid + i * 256;
            const int r = idx >> 3, seg = idx & 7;
            const size_t go = (size_t)(bm + r) * K + k0 + seg * 8;
            const uint32_t so = r * SA_STRIDE + seg * 16;
            CP_ASYNC16(st + OFF_AH + so, Ah + go);
            CP_ASYNC16(st + OFF_AL + so, Al + go);
        }
        #pragma unroll
        for (int i = 0; i < 8; i++) {
            const int idx = tid + i * 256;
            const int r = idx >> 3, seg = idx & 7;
            const size_t go = (size_t)(bn + r) * K + k0 + seg * 8;
            const uint32_t so = r * SA_STRIDE + seg * 16;
            CP_ASYNC16(st + OFF_BH + so, Bh + go);
            CP_ASYNC16(st + OFF_BL + so, Bl + go);
        }
        CP_COMMIT();
    };

    float acc[4][8][4];
    #pragma unroll
    for (int mt = 0; mt < 4; mt++)
        #pragma unroll
        for (int nt = 0; nt < 8; nt++)
            #pragma unroll
            for (int j = 0; j < 4; j++) acc[mt][nt][j] = 0.f;

    load_chunk(0, 0);
    if (nchunk > 1) load_chunk(1, 1);

    const int arow = wm * 64 + (lane >> 2);
    const int brow = wn * 64 + (lane >> 2);
    const int acol = (lane & 3) * 4;

    for (int c = 0; c < nchunk; c++) {
        if (c + 1 < nchunk) { CP_WAIT1(); } else { CP_WAIT0(); }
        __syncthreads();

        const char* st = smem + (c & 1) * STAGE_BYTES;
        const char* pAh = st + OFF_AH;
        const char* pAl = st + OFF_AL;
        const char* pBh = st + OFF_BH;
        const char* pBl = st + OFF_BL;

        #pragma unroll
        for (int ks = 0; ks < 4; ks++) {
            const int cb = ks * 32 + acol;
            uint32_t ah[4][4], al[4][4];
            #pragma unroll
            for (int mt = 0; mt < 4; mt++) {
                const int r0 = (arow + mt * 16) * SA_STRIDE;
                const int r8 = r0 + 8 * SA_STRIDE;
                ah[mt][0] = *(const uint32_t*)(pAh + r0 + cb);
                ah[mt][1] = *(const uint32_t*)(pAh + r8 + cb);
                ah[mt][2] = *(const uint32_t*)(pAh + r0 + cb + 16);
                ah[mt][3] = *(const uint32_t*)(pAh + r8 + cb + 16);
                al[mt][0] = *(const uint32_t*)(pAl + r0 + cb);
                al[mt][1] = *(const uint32_t*)(pAl + r8 + cb);
                al[mt][2] = *(const uint32_t*)(pAl + r0 + cb + 16);
                al[mt][3] = *(const uint32_t*)(pAl + r8 + cb + 16);
            }
            uint32_t bhf[8][2];
            #pragma unroll
            for (int nt = 0; nt < 8; nt++) {
                const int rb = (brow + nt * 8) * SA_STRIDE;
                bhf[nt][0] = *(const uint32_t*)(pBh + rb + cb);
                bhf[nt][1] = *(const uint32_t*)(pBh + rb + cb + 16);
            }
            #pragma unroll
            for (int nt = 0; nt < 8; nt++)
                #pragma unroll
                for (int mt = 0; mt < 4; mt++)
                    mma_bf16(acc[mt][nt], ah[mt], bhf[nt][0], bhf[nt][1]);
            #pragma unroll
            for (int nt = 0; nt < 8; nt++)
                #pragma unroll
                for (int mt = 0; mt < 4; mt++)
                    mma_bf16(acc[mt][nt], al[mt], bhf[nt][0], bhf[nt][1]);
            #pragma unroll
            for (int nt = 0; nt < 8; nt++) {
                const int rb = (brow + nt * 8) * SA_STRIDE;
                const uint32_t bl0 = *(const uint32_t*)(pBl + rb + cb);
                const uint32_t bl1 = *(const uint32_t*)(pBl + rb + cb + 16);
                #pragma unroll
                for (int mt = 0; mt < 4; mt++)
                    mma_bf16(acc[mt][nt], ah[mt], bl0, bl1);
            }
        }
        __syncthreads();
        if (c + 2 < nchunk) load_chunk(c + 2, c & 1);
    }

    #pragma unroll
    for (int mt = 0; mt < 4; mt++) {
        const int row = bm + wm * 64 + mt * 16 + (lane >> 2);
        float* cp0 = C + (size_t)row * Nglob + bn + wn * 64 + (lane & 3) * 2;
        float* cp8 = cp0 + 8 * (size_t)Nglob;
        #pragma unroll
        for (int nt = 0; nt < 8; nt++) {
            *(float2*)(cp0 + nt * 8) = make_float2(acc[mt][nt][0], acc[mt][nt][1]);
            *(float2*)(cp8 + nt * 8) = make_float2(acc[mt][nt][2], acc[mt][nt][3]);
        }
    }
}

// ---------------------------------------------------------------------------
// Elementwise fp32 -> (bf16 hi, bf16 lo) split
// ---------------------------------------------------------------------------
__global__ void split_kernel(const float4* __restrict__ in,
                             uint2* __restrict__ h, uint2* __restrict__ l, int n4)
{
    const int i = blockIdx.x * blockDim.x + threadIdx.x;
    if (i >= n4) return;
    const float4 v = in[i];
    __nv_bfloat16 h0 = __float2bfloat16(v.x), h1 = __float2bfloat16(v.y);
    __nv_bfloat16 h2 = __float2bfloat16(v.z), h3 = __float2bfloat16(v.w);
    __nv_bfloat16 l0 = __float2bfloat16(v.x - __bfloat162float(h0));
    __nv_bfloat16 l1 = __float2bfloat16(v.y - __bfloat162float(h1));
    __nv_bfloat16 l2 = __float2bfloat16(v.z - __bfloat162float(h2));
    __nv_bfloat16 l3 = __float2bfloat16(v.w - __bfloat162float(h3));
    uint2 hh, ll;
    hh.x = (uint32_t)__bfloat16_as_ushort(h0) | ((uint32_t)__bfloat16_as_ushort(h1) << 16);
    hh.y = (uint32_t)__bfloat16_as_ushort(h2) | ((uint32_t)__bfloat16_as_ushort(h3) << 16);
    ll.x = (uint32_t)__bfloat16_as_ushort(l0) | ((uint32_t)__bfloat16_as_ushort(l1) << 16);
    ll.y = (uint32_t)__bfloat16_as_ushort(l2) | ((uint32_t)__bfloat16_as_ushort(l3) << 16);
    h[i] = hh; l[i] = ll;
}

// ---------------------------------------------------------------------------
// Transpose + split: W [K,N] fp32 -> Wt hi/lo [N,K] bf16
// ---------------------------------------------------------------------------
__global__ void transpose_split(const float* __restrict__ W,
                                __nv_bfloat16* __restrict__ Th,
                                __nv_bfloat16* __restrict__ Tl, int K, int N)
{
    __shared__ float t[32][33];
    const int tx = threadIdx.x, ty = threadIdx.y;
    const int nx = blockIdx.x * 32;
    const int ky = blockIdx.y * 32;
    #pragma unroll
    for (int j = 0; j < 32; j += 8)
        t[ty + j][tx] = W[(size_t)(ky + ty + j) * N + nx + tx];
    __syncthreads();
    #pragma unroll
    for (int j = 0; j < 32; j += 8) {
        const float v = t[tx][ty + j];
        const __nv_bfloat16 hi = __float2bfloat16(v);
        const __nv_bfloat16 lo = __float2bfloat16(v - __bfloat162float(hi));
        const size_t o = (size_t)(nx + ty + j) * K + ky + tx;
        Th[o] = hi; Tl[o] = lo;
    }
}

// ---------------------------------------------------------------------------
// RoPE cos/sin tables
// ---------------------------------------------------------------------------
__global__ void rope_tab(float* __restrict__ c, float* __restrict__ s)
{
    const int i = blockIdx.x * blockDim.x + threadIdx.x;
    const int t = i >> 6, p = i & 63;
    const float inv_freq = powf(10000.0f, -(float)p * (1.0f / 64.0f));
    float sn, cs;
    sincosf((float)t * inv_freq, &sn, &cs);
    c[i] = cs; s[i] = sn;
}

// ---------------------------------------------------------------------------
// prep_qkv: RoPE + scale + split hi/lo head-major; v transpose+split.
// ---------------------------------------------------------------------------
#define PREP_SMEM (128 * 133 * 4)

__global__ __launch_bounds__(256, 1) void prep_qkv(
    const float* __restrict__ qkv,
    const float* __restrict__ rc, const float* __restrict__ rs,
    __nv_bfloat16* __restrict__ Qh, __nv_bfloat16* __restrict__ Ql,
    __nv_bfloat16* __restrict__ Kh, __nv_bfloat16* __restrict__ Kl,
    __nv_bfloat16* __restrict__ Vh, __nv_bfloat16* __restrict__ Vl)
{
    extern __shared__ float ps[];
    const int tid = threadIdx.x;
    const int bh = blockIdx.y;
    const int b = bh >> 5, h = bh & 31;
    const int s0 = blockIdx.x * 128;
    const float scale = 0.08838834764831843f;

    #pragma unroll 4
    for (int i = 0; i < 32; i++) {
        const int idx = tid + i * 256;
        const int sr = idx >> 6, p = idx & 63;
        const int sg = s0 + sr;
        const size_t base = ((size_t)b * S_ + sg) * QKV_N + h * HD;
        const float cs = rc[sg * 64 + p], sn = rs[sg * 64 + p];
        const float q1 = qkv[base + p],        q2 = qkv[base + p + 64];
        const float k1 = qkv[base + H_ + p],   k2 = qkv[base + H_ + p + 64];
        const float qa = (q1 * cs - q2 * sn) * scale;
        const float qb = (q2 * cs + q1 * sn) * scale;
        const float ka = k1 * cs - k2 * sn;
        const float kb = k2 * cs + k1 * sn;
        const size_t ob = ((size_t)bh * S_ + sg) * HD;
        __nv_bfloat16 t;
        t = __float2bfloat16(qa); Qh[ob + p] = t;      Ql[ob + p]      = __float2bfloat16(qa - __bfloat162float(t));
        t = __float2bfloat16(qb); Qh[ob + p + 64] = t; Ql[ob + p + 64] = __float2bfloat16(qb - __bfloat162float(t));
        t = __float2bfloat16(ka); Kh[ob + p] = t;      Kl[ob + p]      = __float2bfloat16(ka - __bfloat162float(t));
        t = __float2bfloat16(kb); Kh[ob + p + 64] = t; Kl[ob + p + 64] = __float2bfloat16(kb - __bfloat162float(t));
    }

    #pragma unroll 4
    for (int i = 0; i < 64; i++) {
        const int idx = tid + i * 256;
        const int sr = idx >> 7, p = idx & 127;
        ps[sr * 133 + p] = qkv[((size_t)b * S_ + s0 + sr) * QKV_N + h * HD + 2 * H_ + p];
    }
    __syncthreads();
    #pragma unroll 4
    for (int i = 0; i < 64; i++) {
        const int idx = tid + i * 256;
        const int d = idx >> 7, sr = idx & 127;
        const float v = ps[sr * 133 + d];
        const __nv_bfloat16 hi = __float2bfloat16(v);
        const size_t o = ((size_t)bh * HD + d) * S_ + s0 + sr;
        Vh[o] = hi;
        Vl[o] = __float2bfloat16(v - __bfloat162float(hi));
    }
}

// ---------------------------------------------------------------------------
// Flash attention, mma.sync. QK: bf16x3. PV: quantized-P (2 terms),
// self-consistent l-sum over the bf16-rounded probabilities.
// ---------------------------------------------------------------------------
#define FQ_LD 136
#define FV_LD 72
#define SQ_ELEMS (128 * FQ_LD)
#define SK_ELEMS (64 * FQ_LD)
#define SV_ELEMS (128 * FV_LD)
#define FSTAGE (2 * SK_ELEMS + 2 * SV_ELEMS)
#define FLASH_SMEM ((2 * SQ_ELEMS + 2 * FSTAGE) * 2)

__global__ __launch_bounds__(256, 1) void flash_mma(
    const __nv_bfloat16* __restrict__ Qh, const __nv_bfloat16* __restrict__ Ql,
    const __nv_bfloat16* __restrict__ Kh, const __nv_bfloat16* __restrict__ Kl,
    const __nv_bfloat16* __restrict__ Vh, const __nv_bfloat16* __restrict__ Vl,
    __nv_bfloat16* __restrict__ Ch, __nv_bfloat16* __restrict__ Cl)
{
    extern __shared__ __nv_bfloat16 fs[];
    const int tid = threadIdx.x;
    const int lane = tid & 31;
    const int w = tid >> 5;
    const int qblk = blockIdx.x;
    const int bh = blockIdx.y;
    const int b = bh >> 5, h = bh & 31;
    const int q0 = qblk * 128;
    const uint32_t sb = smem_u32(fs);

    const size_t hoff = (size_t)bh * S_ * HD;
    const size_t voff = (size_t)bh * HD * S_;

    #pragma unroll
    for (int i = 0; i < 8; i++) {
        const int idx = tid + i * 256;
        const int r = idx >> 4, seg = idx & 15;
        const size_t go = hoff + (size_t)(q0 + r) * HD + seg * 8;
        const uint32_t so = (r * FQ_LD + seg * 8) * 2;
        CP_ASYNC16(sb + so, Qh + go);
        CP_ASYNC16(sb + SQ_ELEMS * 2 + so, Ql + go);
    }

    auto load_kv = [&](int t, int s) {
        const int k0 = t * 64;
        const uint32_t st = sb + (2 * SQ_ELEMS + s * FSTAGE) * 2;
        #pragma unroll
        for (int i = 0; i < 4; i++) {
            const int idx = tid + i * 256;
            const int r = idx >> 4, seg = idx & 15;
            const size_t go = hoff + (size_t)(k0 + r) * HD + seg * 8;
            const uint32_t so = (r * FQ_LD + seg * 8) * 2;
            CP_ASYNC16(st + so, Kh + go);
            CP_ASYNC16(st + SK_ELEMS * 2 + so, Kl + go);
        }
        #pragma unroll
        for (int i = 0; i < 4; i++) {
            const int idx = tid + i * 256;
            const int r = idx >> 3, seg = idx & 7;
            const size_t go = voff + (size_t)r * S_ + k0 + seg * 8;
            const uint32_t so = (2 * SK_ELEMS + r * FV_LD + seg * 8) * 2;
            CP_ASYNC16(st + so, Vh + go);
            CP_ASYNC16(st + SV_ELEMS * 2 + so, Vl + go);
        }
        CP_COMMIT();
    };

    load_kv(0, 0);

    float O[16][4];
    #pragma unroll
    for (int i = 0; i < 16; i++)
        #pragma unroll
        for (int j = 0; j < 4; j++) O[i][j] = 0.f;
    float m0 = -1e30f, m1 = -1e30f, l0 = 0.f, l1 = 0.f;

    const int r0 = w * 16 + (lane >> 2);
    const int cq = (lane & 3) * 2;
    const int ntiles = 2 * qblk + 2;

    for (int t = 0; t < ntiles; t++) {
        if (t + 1 < ntiles) { load_kv(t + 1, (t + 1) & 1); CP_WAIT1(); }
        else                { CP_WAIT0(); }
        __syncthreads();

        const __nv_bfloat16* sQh = fs;
        const __nv_bfloat16* sQl = fs + SQ_ELEMS;
        const __nv_bfloat16* sKh = fs + 2 * SQ_ELEMS + (t & 1) * FSTAGE;
        const __nv_bfloat16* sKl = sKh + SK_ELEMS;
        const __nv_bfloat16* sVh = sKl + SK_ELEMS;
        const __nv_bfloat16* sVl = sVh + SV_ELEMS;

        // ---- S = Q K^T (bf16x3) ----
        float Sf[8][4];
        #pragma unroll
        for (int nt = 0; nt < 8; nt++)
            #pragma unroll
            for (int j = 0; j < 4; j++) Sf[nt][j] = 0.f;

        #pragma unroll
        for (int kk = 0; kk < 8; kk++) {
            uint32_t ah[4], al[4];
            const __nv_bfloat16* qp = sQh + r0 * FQ_LD + kk * 16 + cq;
            const __nv_bfloat16* qp2 = sQl + r0 * FQ_LD + kk * 16 + cq;
            ah[0] = *(const uint32_t*)(qp);
            ah[1] = *(const uint32_t*)(qp + 8 * FQ_LD);
            ah[2] = *(const uint32_t*)(qp + 8);
            ah[3] = *(const uint32_t*)(qp + 8 * FQ_LD + 8);
            al[0] = *(const uint32_t*)(qp2);
            al[1] = *(const uint32_t*)(qp2 + 8 * FQ_LD);
            al[2] = *(const uint32_t*)(qp2 + 8);
            al[3] = *(const uint32_t*)(qp2 + 8 * FQ_LD + 8);
            uint32_t khf[8][2];
            #pragma unroll
            for (int nt = 0; nt < 8; nt++) {
                const int n = nt * 8 + (lane >> 2);
                const __nv_bfloat16* kp = sKh + n * FQ_LD + kk * 16 + cq;
                khf[nt][0] = *(const uint32_t*)(kp);
                khf[nt][1] = *(const uint32_t*)(kp + 8);
            }
            #pragma unroll
            for (int nt = 0; nt < 8; nt++)
                mma_bf16(Sf[nt], ah, khf[nt][0], khf[nt][1]);
            #pragma unroll
            for (int nt = 0; nt < 8; nt++)
                mma_bf16(Sf[nt], al, khf[nt][0], khf[nt][1]);
            #pragma unroll
            for (int nt = 0; nt < 8; nt++) {
                const int n = nt * 8 + (lane >> 2);
                const __nv_bfloat16* kp2 = sKl + n * FQ_LD + kk * 16 + cq;
                mma_bf16(Sf[nt], ah, *(const uint32_t*)(kp2),
                                     *(const uint32_t*)(kp2 + 8));
            }
        }

        // ---- mask + online softmax ----
        const int k0 = t * 64;
        const int qg0 = q0 + r0, qg1 = qg0 + 8;
        if (k0 + 63 > q0 + w * 16) {
            #pragma unroll
            for (int nt = 0; nt < 8; nt++) {
                const int kv = k0 + nt * 8 + cq;
                if (kv     > qg0) Sf[nt][0] = -1e30f;
                if (kv + 1 > qg0) Sf[nt][1] = -1e30f;
                if (kv     > qg1) Sf[nt][2] = -1e30f;
                if (kv + 1 > qg1) Sf[nt][3] = -1e30f;
            }
        }
        float mx0 = -1e30f, mx1 = -1e30f;
        #pragma unroll
        for (int nt = 0; nt < 8; nt++) {
            mx0 = fmaxf(mx0, fmaxf(Sf[nt][0], Sf[nt][1]));
            mx1 = fmaxf(mx1, fmaxf(Sf[nt][2], Sf[nt][3]));
        }
        mx0 = fmaxf(mx0, __shfl_xor_sync(0xffffffffu, mx0, 1));
        mx0 = fmaxf(mx0, __shfl_xor_sync(0xffffffffu, mx0, 2));
        mx1 = fmaxf(mx1, __shfl_xor_sync(0xffffffffu, mx1, 1));
        mx1 = fmaxf(mx1, __shfl_xor_sync(0xffffffffu, mx1, 2));

        const float mn0 = fmaxf(m0, mx0), mn1 = fmaxf(m1, mx1);
        const float a0 = __expf(m0 - mn0), a1 = __expf(m1 - mn1);
        m0 = mn0; m1 = mn1;

        // exp -> bf16 quantize; l-sum over the QUANTIZED probs (self-consistent)
        float s0 = 0.f, s1 = 0.f;
        uint32_t Ph[8][2];
        #pragma unroll
        for (int nt = 0; nt < 8; nt++) {
            const float p00 = __expf(Sf[nt][0] - mn0);
            const float p01 = __expf(Sf[nt][1] - mn0);
            const float p10 = __expf(Sf[nt][2] - mn1);
            const float p11 = __expf(Sf[nt][3] - mn1);
            CVTBF2(Ph[nt][0], p00, p01);
            CVTBF2(Ph[nt][1], p10, p11);
            s0 += __uint_as_float(Ph[nt][0] << 16)
                + __uint_as_float(Ph[nt][0] & 0xffff0000u);
            s1 += __uint_as_float(Ph[nt][1] << 16)
                + __uint_as_float(Ph[nt][1] & 0xffff0000u);
        }
        s0 += __shfl_xor_sync(0xffffffffu, s0, 1);
        s0 += __shfl_xor_sync(0xffffffffu, s0, 2);
        s1 += __shfl_xor_sync(0xffffffffu, s1, 1);
        s1 += __shfl_xor_sync(0xffffffffu, s1, 2);
        l0 = l0 * a0 + s0;
        l1 = l1 * a1 + s1;

        #pragma unroll
        for (int i = 0; i < 16; i++) {
            O[i][0] *= a0; O[i][1] *= a0; O[i][2] *= a1; O[i][3] *= a1;
        }

        // ---- O += P V  (P quantized; V hi + V lo = 2 passes) ----
        #pragma unroll
        for (int ks = 0; ks < 4; ks++) {
            const uint32_t ah[4] = {Ph[2 * ks][0], Ph[2 * ks][1],
                                    Ph[2 * ks + 1][0], Ph[2 * ks + 1][1]};
            #pragma unroll
            for (int nt2 = 0; nt2 < 16; nt2++) {
                const int nd = nt2 * 8 + (lane >> 2);
                const __nv_bfloat16* vp = sVh + nd * FV_LD + ks * 16 + cq;
                mma_bf16(O[nt2], ah, *(const uint32_t*)(vp),
                                     *(const uint32_t*)(vp + 8));
            }
            #pragma unroll
            for (int nt2 = 0; nt2 < 16; nt2++) {
                const int nd = nt2 * 8 + (lane >> 2);
                const __nv_bfloat16* vp2 = sVl + nd * FV_LD + ks * 16 + cq;
                mma_bf16(O[nt2], ah, *(const uint32_t*)(vp2),
                                     *(const uint32_t*)(vp2 + 8));
            }
        }
        __syncthreads();
    }

    // ---- epilogue: normalize, split hi/lo, write ch/cl ----
    const float inv0 = 1.f / l0, inv1 = 1.f / l1;
    const int row0 = q0 + w * 16 + (lane >> 2);
    const size_t o0 = ((size_t)b * S_ + row0) * H_ + h * HD + cq;
    const size_t o1 = o0 + 8 * (size_t)H_;
    #pragma unroll
    for (int nt2 = 0; nt2 < 16; nt2++) {
        const float f0 = O[nt2][0] * inv0, f1 = O[nt2][1] * inv0;
        const float f2 = O[nt2][2] * inv1, f3 = O[nt2][3] * inv1;
        uint32_t hh0, hh1;
        CVTBF2(hh0, f0, f1);
        CVTBF2(hh1, f2, f3);
        *(uint32_t*)&Ch[o0 + nt2 * 8] = hh0;
        *(uint32_t*)&Ch[o1 + nt2 * 8] = hh1;
        const float r0f = f0 - __uint_as_float(hh0 << 16);
        const float r1f = f1 - __uint_as_float(hh0 & 0xffff0000u);
        const float r2f = f2 - __uint_as_float(hh1 << 16);
        const float r3f = f3 - __uint_as_float(hh1 & 0xffff0000u);
        uint32_t ll0, ll1;
        CVTBF2(ll0, r0f, r1f);
        CVTBF2(ll1, r2f, r3f);
        *(uint32_t*)&Cl[o0 + nt2 * 8] = ll0;
        *(uint32_t*)&Cl[o1 + nt2 * 8] = ll1;
    }
}

// ---------------------------------------------------------------------------
// Launch
// ---------------------------------------------------------------------------
extern "C" void kernel_launch(void* const* d_in, const int* in_sizes, int n_in,
                              void* d_out, int out_size)
{
    const float* x    = (const float*)d_in[0];
    const float* Wqkv = (const float*)d_in[1];
    const float* Wo   = (const float*)d_in[2];
    float* out = (float*)d_out;

    float *qkv, *rc, *rs;
    __nv_bfloat16 *xh, *xl, *wqh, *wql, *woh, *wol, *ch, *cl;
    __nv_bfloat16 *qh, *ql, *kh, *kl, *vth, *vtl;
    cudaGetSymbolAddress((void**)&qkv, g_qkv);
    cudaGetSymbolAddress((void**)&rc, g_rcos);
    cudaGetSymbolAddress((void**)&rs, g_rsin);
    cudaGetSymbolAddress((void**)&xh, g_xh);
    cudaGetSymbolAddress((void**)&xl, g_xl);
    cudaGetSymbolAddress((void**)&wqh, g_wqh);
    cudaGetSymbolAddress((void**)&wql, g_wql);
    cudaGetSymbolAddress((void**)&woh, g_woh);
    cudaGetSymbolAddress((void**)&wol, g_wol);
    cudaGetSymbolAddress((void**)&ch, g_ch);
    cudaGetSymbolAddress((void**)&cl, g_cl);
    cudaGetSymbolAddress((void**)&qh, g_qh);
    cudaGetSymbolAddress((void**)&ql, g_ql);
    cudaGetSymbolAddress((void**)&kh, g_kh);
    cudaGetSymbolAddress((void**)&kl, g_kl);
    cudaGetSymbolAddress((void**)&vth, g_vth);
    cudaGetSymbolAddress((void**)&vtl, g_vtl);

    cudaFuncSetAttribute(gemm_bf16x3mma,
                         cudaFuncAttributeMaxDynamicSharedMemorySize, GEMM_SMEM);
    cudaFuncSetAttribute(prep_qkv,
                         cudaFuncAttributeMaxDynamicSharedMemorySize, PREP_SMEM);
    cudaFuncSetAttribute(flash_mma,
                         cudaFuncAttributeMaxDynamicSharedMemorySize, FLASH_SMEM);

    {
        const int n4 = (BS_ * H_) / 4;
        split_kernel<<<n4 / 256, 256>>>((const float4*)x, (uint2*)xh, (uint2*)xl, n4);
    }
    {
        dim3 grid(QKV_N / 32, H_ / 32), blk(32, 8);
        transpose_split<<<grid, blk>>>(Wqkv, wqh, wql, H_, QKV_N);
    }
    {
        dim3 grid(H_ / 32, H_ / 32), blk(32, 8);
        transpose_split<<<grid, blk>>>(Wo, woh, wol, H_, H_);
    }
    rope_tab<<<(S_ * 64) / 256, 256>>>(rc, rs);

    {
        dim3 grid(BS_ / 128, QKV_N / 256);
        gemm_bf16x3mma<<<grid, 256, GEMM_SMEM>>>(xh, xl, wqh, wql, qkv, QKV_N, H_);
    }
    {
        dim3 grid(S_ / 128, B_ * NH);
        prep_qkv<<<grid, 256, PREP_SMEM>>>(qkv, rc, rs, qh, ql, kh, kl, vth, vtl);
    }
    {
        dim3 grid(S_ / 128, B_ * NH);
        flash_mma<<<grid, 256, FLASH_SMEM>>>(qh, ql, kh, kl, vth, vtl, ch, cl);
    }
    {
        dim3 grid(BS_ / 128, H_ / 256);
        gemm_bf16x3mma<<<grid, 256, GEMM_SMEM>>>(ch, cl, woh, wol, out, H_, H_);
    }
}

// round 10
// speedup vs baseline: 1.0529x; 1.0098x over previous
#include <cuda_runtime.h>
#include <cuda_bf16.h>
#include <math.h>
#include <stdint.h>

// Problem constants
#define B_ 2
#define S_ 2048
#define H_ 4096
#define NH 32
#define HD 128
#define BS_ (B_ * S_)          // 4096 rows
#define QKV_N (3 * H_)         // 12288

// ---------------------------------------------------------------------------
// Scratch (static device globals)
// ---------------------------------------------------------------------------
__device__ float g_qkv[(size_t)BS_ * QKV_N];
__device__ __nv_bfloat16 g_xh[(size_t)BS_ * H_];
__device__ __nv_bfloat16 g_xl[(size_t)BS_ * H_];
__device__ __nv_bfloat16 g_wqh[(size_t)QKV_N * H_];
__device__ __nv_bfloat16 g_wql[(size_t)QKV_N * H_];
__device__ __nv_bfloat16 g_woh[(size_t)H_ * H_];
__device__ __nv_bfloat16 g_wol[(size_t)H_ * H_];
__device__ __nv_bfloat16 g_ch[(size_t)BS_ * H_];
__device__ __nv_bfloat16 g_cl[(size_t)BS_ * H_];
__device__ __nv_bfloat16 g_qh[(size_t)BS_ * H_];
__device__ __nv_bfloat16 g_ql[(size_t)BS_ * H_];
__device__ __nv_bfloat16 g_kh[(size_t)BS_ * H_];
__device__ __nv_bfloat16 g_kl[(size_t)BS_ * H_];
__device__ __nv_bfloat16 g_vth[(size_t)BS_ * H_];
__device__ __nv_bfloat16 g_vtl[(size_t)BS_ * H_];
__device__ float g_rcos[S_ * 64];
__device__ float g_rsin[S_ * 64];

// ---------------------------------------------------------------------------
// mma.sync + cp.async + ldmatrix helpers
// ---------------------------------------------------------------------------
__device__ __forceinline__ uint32_t smem_u32(const void* p) {
    uint32_t a;
    asm("{ .reg .u64 t; cvta.to.shared.u64 t, %1; cvt.u32.u64 %0, t; }"
        : "=r"(a) : "l"(p));
    return a;
}

#define CP_ASYNC16(dst, src) \
    asm volatile("cp.async.cg.shared.global [%0], [%1], 16;" \
                 :: "r"(dst), "l"(src) : "memory")
#define CP_COMMIT() asm volatile("cp.async.commit_group;" ::: "memory")
#define CP_WAIT1()  asm volatile("cp.async.wait_group 1;" ::: "memory")
#define CP_WAIT0()  asm volatile("cp.async.wait_group 0;" ::: "memory")

__device__ __forceinline__ void mma_bf16(float* d, const uint32_t* a,
                                         uint32_t b0, uint32_t b1) {
    asm volatile(
        "mma.sync.aligned.m16n8k16.row.col.f32.bf16.bf16.f32 "
        "{%0,%1,%2,%3}, {%4,%5,%6,%7}, {%8,%9}, {%0,%1,%2,%3};"
        : "+f"(d[0]), "+f"(d[1]), "+f"(d[2]), "+f"(d[3])
        : "r"(a[0]), "r"(a[1]), "r"(a[2]), "r"(a[3]), "r"(b0), "r"(b1));
}

#define LDSM4(r0, r1, r2, r3, addr) \
    asm volatile("ldmatrix.sync.aligned.m8n8.x4.shared.b16 {%0,%1,%2,%3}, [%4];" \
                 : "=r"(r0), "=r"(r1), "=r"(r2), "=r"(r3) : "r"(addr))

// pack two f32 -> bf16x2 in ONE instruction (lo = first arg)
#define CVTBF2(r, flo, fhi) \
    asm("cvt.rn.bf16x2.f32 %0, %1, %2;" : "=r"(r) : "f"(fhi), "f"(flo))

// ---------------------------------------------------------------------------
// bf16x3 mma.sync GEMM:  C[M,N] = A * B^T  (A [M,K], B [N,K])
// Tile 128x256, BK=64, 256 threads (8 warps; warp tile 64x64), 2-stage,
// ldmatrix fragment loads.
// ---------------------------------------------------------------------------
#define SA_STRIDE 144
#define OFF_AH 0
#define OFF_AL (128 * SA_STRIDE)
#define OFF_BH (2 * 128 * SA_STRIDE)
#define OFF_BL (2 * 128 * SA_STRIDE + 256 * SA_STRIDE)
#define STAGE_BYTES (2 * 128 * SA_STRIDE + 2 * 256 * SA_STRIDE)  // 110592
#define GEMM_SMEM (2 * STAGE_BYTES)             // 221184
#define MT_STEP (16 * SA_STRIDE)                // 2304 bytes per 16 rows

__global__ __launch_bounds__(256, 1) void gemm_bf16x3mma(
    const __nv_bfloat16* __restrict__ Ah, const __nv_bfloat16* __restrict__ Al,
    const __nv_bfloat16* __restrict__ Bh, const __nv_bfloat16* __restrict__ Bl,
    float* __restrict__ C, int Nglob, int K)
{
    extern __shared__ char smem[];
    const int tid  = threadIdx.x;
    const int lane = tid & 31;
    const int wid  = tid >> 5;
    const int wm = wid & 1;
    const int wn = wid >> 1;
    const int bm = blockIdx.x * 128;
    const int bn = blockIdx.y * 256;

    const uint32_t sb = smem_u32(smem);
    const int nchunk = K >> 6;

    auto load_chunk = [&](int c, int s) {
        const int k0 = c << 6;
        const uint32_t st = sb + s * STAGE_BYTES;
        #pragma unroll
        for (int i = 0; i < 4; i++) {
            const int idx = tid + i * 256;
            const int r = idx >> 3, seg = idx & 7;
            const size_t go = (size_t)(bm + r) * K + k0 + seg * 8;
            const uint32_t so = r * SA_STRIDE + seg * 16;
            CP_ASYNC16(st + OFF_AH + so, Ah + go);
            CP_ASYNC16(st + OFF_AL + so, Al + go);
        }
        #pragma unroll
        for (int i = 0; i < 8; i++) {
            const int idx = tid + i * 256;
            const int r = idx >> 3, seg = idx & 7;
            const size_t go = (size_t)(bn + r) * K + k0 + seg * 8;
            const uint32_t so = r * SA_STRIDE + seg * 16;
            CP_ASYNC16(st + OFF_BH + so, Bh + go);
            CP_ASYNC16(st + OFF_BL + so, Bl + go);
        }
        CP_COMMIT();
    };

    float acc[4][8][4];
    #pragma unroll
    for (int mt = 0; mt < 4; mt++)
        #pragma unroll
        for (int nt = 0; nt < 8; nt++)
            #pragma unroll
            for (int j = 0; j < 4; j++) acc[mt][nt][j] = 0.f;

    load_chunk(0, 0);
    if (nchunk > 1) load_chunk(1, 1);

    // ldmatrix per-lane offsets
    const int l7 = lane & 7, sel = lane >> 3;
    const uint32_t offA = (uint32_t)(wm * 64 + (sel & 1) * 8 + l7) * SA_STRIDE
                        + (uint32_t)(sel >> 1) * 16;
    const uint32_t offB = (uint32_t)(wn * 64 + (sel >> 1) * 8 + l7) * SA_STRIDE
                        + (uint32_t)(sel & 1) * 16;

    for (int c = 0; c < nchunk; c++) {
        if (c + 1 < nchunk) { CP_WAIT1(); } else { CP_WAIT0(); }
        __syncthreads();

        const uint32_t st = sb + (c & 1) * STAGE_BYTES;
        const uint32_t aAh = st + OFF_AH + offA;
        const uint32_t aAl = st + OFF_AL + offA;
        const uint32_t aBh = st + OFF_BH + offB;
        const uint32_t aBl = st + OFF_BL + offB;

        #pragma unroll
        for (int ks = 0; ks < 4; ks++) {
            const uint32_t cb = ks * 32;
            uint32_t ah[4][4], al[4][4];
            #pragma unroll
            for (int mt = 0; mt < 4; mt++) {
                LDSM4(ah[mt][0], ah[mt][1], ah[mt][2], ah[mt][3],
                      aAh + mt * MT_STEP + cb);
                LDSM4(al[mt][0], al[mt][1], al[mt][2], al[mt][3],
                      aAl + mt * MT_STEP + cb);
            }
            uint32_t bhf[8][2];
            #pragma unroll
            for (int j = 0; j < 4; j++) {
                LDSM4(bhf[2 * j][0], bhf[2 * j][1],
                      bhf[2 * j + 1][0], bhf[2 * j + 1][1],
                      aBh + j * MT_STEP + cb);
            }
            // pass 1: Ah * Bh
            #pragma unroll
            for (int nt = 0; nt < 8; nt++)
                #pragma unroll
                for (int mt = 0; mt < 4; mt++)
                    mma_bf16(acc[mt][nt], ah[mt], bhf[nt][0], bhf[nt][1]);
            // pass 2: Al * Bh
            #pragma unroll
            for (int nt = 0; nt < 8; nt++)
                #pragma unroll
                for (int mt = 0; mt < 4; mt++)
                    mma_bf16(acc[mt][nt], al[mt], bhf[nt][0], bhf[nt][1]);
            // pass 3: Ah * Bl
            #pragma unroll
            for (int j = 0; j < 4; j++) {
                uint32_t bl00, bl01, bl10, bl11;
                LDSM4(bl00, bl01, bl10, bl11, aBl + j * MT_STEP + cb);
                #pragma unroll
                for (int mt = 0; mt < 4; mt++) {
                    mma_bf16(acc[mt][2 * j],     ah[mt], bl00, bl01);
                    mma_bf16(acc[mt][2 * j + 1], ah[mt], bl10, bl11);
                }
            }
        }
        __syncthreads();
        if (c + 2 < nchunk) load_chunk(c + 2, c & 1);
    }

    #pragma unroll
    for (int mt = 0; mt < 4; mt++) {
        const int row = bm + wm * 64 + mt * 16 + (lane >> 2);
        float* cp0 = C + (size_t)row * Nglob + bn + wn * 64 + (lane & 3) * 2;
        float* cp8 = cp0 + 8 * (size_t)Nglob;
        #pragma unroll
        for (int nt = 0; nt < 8; nt++) {
            *(float2*)(cp0 + nt * 8) = make_float2(acc[mt][nt][0], acc[mt][nt][1]);
            *(float2*)(cp8 + nt * 8) = make_float2(acc[mt][nt][2], acc[mt][nt][3]);
        }
    }
}

// ---------------------------------------------------------------------------
// Elementwise fp32 -> (bf16 hi, bf16 lo) split
// ---------------------------------------------------------------------------
__global__ void split_kernel(const float4* __restrict__ in,
                             uint2* __restrict__ h, uint2* __restrict__ l, int n4)
{
    const int i = blockIdx.x * blockDim.x + threadIdx.x;
    if (i >= n4) return;
    const float4 v = in[i];
    __nv_bfloat16 h0 = __float2bfloat16(v.x), h1 = __float2bfloat16(v.y);
    __nv_bfloat16 h2 = __float2bfloat16(v.z), h3 = __float2bfloat16(v.w);
    __nv_bfloat16 l0 = __float2bfloat16(v.x - __bfloat162float(h0));
    __nv_bfloat16 l1 = __float2bfloat16(v.y - __bfloat162float(h1));
    __nv_bfloat16 l2 = __float2bfloat16(v.z - __bfloat162float(h2));
    __nv_bfloat16 l3 = __float2bfloat16(v.w - __bfloat162float(h3));
    uint2 hh, ll;
    hh.x = (uint32_t)__bfloat16_as_ushort(h0) | ((uint32_t)__bfloat16_as_ushort(h1) << 16);
    hh.y = (uint32_t)__bfloat16_as_ushort(h2) | ((uint32_t)__bfloat16_as_ushort(h3) << 16);
    ll.x = (uint32_t)__bfloat16_as_ushort(l0) | ((uint32_t)__bfloat16_as_ushort(l1) << 16);
    ll.y = (uint32_t)__bfloat16_as_ushort(l2) | ((uint32_t)__bfloat16_as_ushort(l3) << 16);
    h[i] = hh; l[i] = ll;
}

// ---------------------------------------------------------------------------
// Transpose + split: W [K,N] fp32 -> Wt hi/lo [N,K] bf16
// ---------------------------------------------------------------------------
__global__ void transpose_split(const float* __restrict__ W,
                                __nv_bfloat16* __restrict__ Th,
                                __nv_bfloat16* __restrict__ Tl, int K, int N)
{
    __shared__ float t[32][33];
    const int tx = threadIdx.x, ty = threadIdx.y;
    const int nx = blockIdx.x * 32;
    const int ky = blockIdx.y * 32;
    #pragma unroll
    for (int j = 0; j < 32; j += 8)
        t[ty + j][tx] = W[(size_t)(ky + ty + j) * N + nx + tx];
    __syncthreads();
    #pragma unroll
    for (int j = 0; j < 32; j += 8) {
        const float v = t[tx][ty + j];
        const __nv_bfloat16 hi = __float2bfloat16(v);
        const __nv_bfloat16 lo = __float2bfloat16(v - __bfloat162float(hi));
        const size_t o = (size_t)(nx + ty + j) * K + ky + tx;
        Th[o] = hi; Tl[o] = lo;
    }
}

// ---------------------------------------------------------------------------
// RoPE cos/sin tables
// ---------------------------------------------------------------------------
__global__ void rope_tab(float* __restrict__ c, float* __restrict__ s)
{
    const int i = blockIdx.x * blockDim.x + threadIdx.x;
    const int t = i >> 6, p = i & 63;
    const float inv_freq = powf(10000.0f, -(float)p * (1.0f / 64.0f));
    float sn, cs;
    sincosf((float)t * inv_freq, &sn, &cs);
    c[i] = cs; s[i] = sn;
}

// ---------------------------------------------------------------------------
// prep_qkv: RoPE + scale + split hi/lo head-major; v transpose+split.
// ---------------------------------------------------------------------------
#define PREP_SMEM (128 * 133 * 4)

__global__ __launch_bounds__(256, 1) void prep_qkv(
    const float* __restrict__ qkv,
    const float* __restrict__ rc, const float* __restrict__ rs,
    __nv_bfloat16* __restrict__ Qh, __nv_bfloat16* __restrict__ Ql,
    __nv_bfloat16* __restrict__ Kh, __nv_bfloat16* __restrict__ Kl,
    __nv_bfloat16* __restrict__ Vh, __nv_bfloat16* __restrict__ Vl)
{
    extern __shared__ float ps[];
    const int tid = threadIdx.x;
    const int bh = blockIdx.y;
    const int b = bh >> 5, h = bh & 31;
    const int s0 = blockIdx.x * 128;
    const float scale = 0.08838834764831843f;

    #pragma unroll 4
    for (int i = 0; i < 32; i++) {
        const int idx = tid + i * 256;
        const int sr = idx >> 6, p = idx & 63;
        const int sg = s0 + sr;
        const size_t base = ((size_t)b * S_ + sg) * QKV_N + h * HD;
        const float cs = rc[sg * 64 + p], sn = rs[sg * 64 + p];
        const float q1 = qkv[base + p],        q2 = qkv[base + p + 64];
        const float k1 = qkv[base + H_ + p],   k2 = qkv[base + H_ + p + 64];
        const float qa = (q1 * cs - q2 * sn) * scale;
        const float qb = (q2 * cs + q1 * sn) * scale;
        const float ka = k1 * cs - k2 * sn;
        const float kb = k2 * cs + k1 * sn;
        const size_t ob = ((size_t)bh * S_ + sg) * HD;
        __nv_bfloat16 t;
        t = __float2bfloat16(qa); Qh[ob + p] = t;      Ql[ob + p]      = __float2bfloat16(qa - __bfloat162float(t));
        t = __float2bfloat16(qb); Qh[ob + p + 64] = t; Ql[ob + p + 64] = __float2bfloat16(qb - __bfloat162float(t));
        t = __float2bfloat16(ka); Kh[ob + p] = t;      Kl[ob + p]      = __float2bfloat16(ka - __bfloat162float(t));
        t = __float2bfloat16(kb); Kh[ob + p + 64] = t; Kl[ob + p + 64] = __float2bfloat16(kb - __bfloat162float(t));
    }

    #pragma unroll 4
    for (int i = 0; i < 64; i++) {
        const int idx = tid + i * 256;
        const int sr = idx >> 7, p = idx & 127;
        ps[sr * 133 + p] = qkv[((size_t)b * S_ + s0 + sr) * QKV_N + h * HD + 2 * H_ + p];
    }
    __syncthreads();
    #pragma unroll 4
    for (int i = 0; i < 64; i++) {
        const int idx = tid + i * 256;
        const int d = idx >> 7, sr = idx & 127;
        const float v = ps[sr * 133 + d];
        const __nv_bfloat16 hi = __float2bfloat16(v);
        const size_t o = ((size_t)bh * HD + d) * S_ + s0 + sr;
        Vh[o] = hi;
        Vl[o] = __float2bfloat16(v - __bfloat162float(hi));
    }
}

// ---------------------------------------------------------------------------
// Flash attention, mma.sync. QK: bf16x3. PV: Ph*Vh + Ph*Vl + Pl*Vh
// (Pl = residual of bf16-quantized P; l-sum in fp32 over raw p).
// ---------------------------------------------------------------------------
#define FQ_LD 136
#define FV_LD 72
#define SQ_ELEMS (128 * FQ_LD)
#define SK_ELEMS (64 * FQ_LD)
#define SV_ELEMS (128 * FV_LD)
#define FSTAGE (2 * SK_ELEMS + 2 * SV_ELEMS)
#define FLASH_SMEM ((2 * SQ_ELEMS + 2 * FSTAGE) * 2)

__global__ __launch_bounds__(256, 1) void flash_mma(
    const __nv_bfloat16* __restrict__ Qh, const __nv_bfloat16* __restrict__ Ql,
    const __nv_bfloat16* __restrict__ Kh, const __nv_bfloat16* __restrict__ Kl,
    const __nv_bfloat16* __restrict__ Vh, const __nv_bfloat16* __restrict__ Vl,
    __nv_bfloat16* __restrict__ Ch, __nv_bfloat16* __restrict__ Cl)
{
    extern __shared__ __nv_bfloat16 fs[];
    const int tid = threadIdx.x;
    const int lane = tid & 31;
    const int w = tid >> 5;
    const int qblk = blockIdx.x;
    const int bh = blockIdx.y;
    const int b = bh >> 5, h = bh & 31;
    const int q0 = qblk * 128;
    const uint32_t sb = smem_u32(fs);

    const size_t hoff = (size_t)bh * S_ * HD;
    const size_t voff = (size_t)bh * HD * S_;

    #pragma unroll
    for (int i = 0; i < 8; i++) {
        const int idx = tid + i * 256;
        const int r = idx >> 4, seg = idx & 15;
        const size_t go = hoff + (size_t)(q0 + r) * HD + seg * 8;
        const uint32_t so = (r * FQ_LD + seg * 8) * 2;
        CP_ASYNC16(sb + so, Qh + go);
        CP_ASYNC16(sb + SQ_ELEMS * 2 + so, Ql + go);
    }

    auto load_kv = [&](int t, int s) {
        const int k0 = t * 64;
        const uint32_t st = sb + (2 * SQ_ELEMS + s * FSTAGE) * 2;
        #pragma unroll
        for (int i = 0; i < 4; i++) {
            const int idx = tid + i * 256;
            const int r = idx >> 4, seg = idx & 15;
            const size_t go = hoff + (size_t)(k0 + r) * HD + seg * 8;
            const uint32_t so = (r * FQ_LD + seg * 8) * 2;
            CP_ASYNC16(st + so, Kh + go);
            CP_ASYNC16(st + SK_ELEMS * 2 + so, Kl + go);
        }
        #pragma unroll
        for (int i = 0; i < 4; i++) {
            const int idx = tid + i * 256;
            const int r = idx >> 3, seg = idx & 7;
            const size_t go = voff + (size_t)r * S_ + k0 + seg * 8;
            const uint32_t so = (2 * SK_ELEMS + r * FV_LD + seg * 8) * 2;
            CP_ASYNC16(st + so, Vh + go);
            CP_ASYNC16(st + SV_ELEMS * 2 + so, Vl + go);
        }
        CP_COMMIT();
    };

    load_kv(0, 0);

    float O[16][4];
    #pragma unroll
    for (int i = 0; i < 16; i++)
        #pragma unroll
        for (int j = 0; j < 4; j++) O[i][j] = 0.f;
    float m0 = -1e30f, m1 = -1e30f, l0 = 0.f, l1 = 0.f;

    const int r0 = w * 16 + (lane >> 2);
    const int cq = (lane & 3) * 2;
    const int ntiles = 2 * qblk + 2;

    for (int t = 0; t < ntiles; t++) {
        if (t + 1 < ntiles) { load_kv(t + 1, (t + 1) & 1); CP_WAIT1(); }
        else                { CP_WAIT0(); }
        __syncthreads();

        const __nv_bfloat16* sQh = fs;
        const __nv_bfloat16* sQl = fs + SQ_ELEMS;
        const __nv_bfloat16* sKh = fs + 2 * SQ_ELEMS + (t & 1) * FSTAGE;
        const __nv_bfloat16* sKl = sKh + SK_ELEMS;
        const __nv_bfloat16* sVh = sKl + SK_ELEMS;
        const __nv_bfloat16* sVl = sVh + SV_ELEMS;

        // ---- S = Q K^T (bf16x3) ----
        float Sf[8][4];
        #pragma unroll
        for (int nt = 0; nt < 8; nt++)
            #pragma unroll
            for (int j = 0; j < 4; j++) Sf[nt][j] = 0.f;

        #pragma unroll
        for (int kk = 0; kk < 8; kk++) {
            uint32_t ah[4], al[4];
            const __nv_bfloat16* qp = sQh + r0 * FQ_LD + kk * 16 + cq;
            const __nv_bfloat16* qp2 = sQl + r0 * FQ_LD + kk * 16 + cq;
            ah[0] = *(const uint32_t*)(qp);
            ah[1] = *(const uint32_t*)(qp + 8 * FQ_LD);
            ah[2] = *(const uint32_t*)(qp + 8);
            ah[3] = *(const uint32_t*)(qp + 8 * FQ_LD + 8);
            al[0] = *(const uint32_t*)(qp2);
            al[1] = *(const uint32_t*)(qp2 + 8 * FQ_LD);
            al[2] = *(const uint32_t*)(qp2 + 8);
            al[3] = *(const uint32_t*)(qp2 + 8 * FQ_LD + 8);
            uint32_t khf[8][2];
            #pragma unroll
            for (int nt = 0; nt < 8; nt++) {
                const int n = nt * 8 + (lane >> 2);
                const __nv_bfloat16* kp = sKh + n * FQ_LD + kk * 16 + cq;
                khf[nt][0] = *(const uint32_t*)(kp);
                khf[nt][1] = *(const uint32_t*)(kp + 8);
            }
            #pragma unroll
            for (int nt = 0; nt < 8; nt++)
                mma_bf16(Sf[nt], ah, khf[nt][0], khf[nt][1]);
            #pragma unroll
            for (int nt = 0; nt < 8; nt++)
                mma_bf16(Sf[nt], al, khf[nt][0], khf[nt][1]);
            #pragma unroll
            for (int nt = 0; nt < 8; nt++) {
                const int n = nt * 8 + (lane >> 2);
                const __nv_bfloat16* kp2 = sKl + n * FQ_LD + kk * 16 + cq;
                mma_bf16(Sf[nt], ah, *(const uint32_t*)(kp2),
                                     *(const uint32_t*)(kp2 + 8));
            }
        }

        // ---- mask + online softmax ----
        const int k0 = t * 64;
        const int qg0 = q0 + r0, qg1 = qg0 + 8;
        if (k0 + 63 > q0 + w * 16) {
            #pragma unroll
            for (int nt = 0; nt < 8; nt++) {
                const int kv = k0 + nt * 8 + cq;
                if (kv     > qg0) Sf[nt][0] = -1e30f;
                if (kv + 1 > qg0) Sf[nt][1] = -1e30f;
                if (kv     > qg1) Sf[nt][2] = -1e30f;
                if (kv + 1 > qg1) Sf[nt][3] = -1e30f;
            }
        }
        float mx0 = -1e30f, mx1 = -1e30f;
        #pragma unroll
        for (int nt = 0; nt < 8; nt++) {
            mx0 = fmaxf(mx0, fmaxf(Sf[nt][0], Sf[nt][1]));
            mx1 = fmaxf(mx1, fmaxf(Sf[nt][2], Sf[nt][3]));
        }
        mx0 = fmaxf(mx0, __shfl_xor_sync(0xffffffffu, mx0, 1));
        mx0 = fmaxf(mx0, __shfl_xor_sync(0xffffffffu, mx0, 2));
        mx1 = fmaxf(mx1, __shfl_xor_sync(0xffffffffu, mx1, 1));
        mx1 = fmaxf(mx1, __shfl_xor_sync(0xffffffffu, mx1, 2));

        const float mn0 = fmaxf(m0, mx0), mn1 = fmaxf(m1, mx1);
        const float a0 = __expf(m0 - mn0), a1 = __expf(m1 - mn1);
        m0 = mn0; m1 = mn1;

        float s0 = 0.f, s1 = 0.f;
        uint32_t Ph[8][2], Pl[8][2];
        #pragma unroll
        for (int nt = 0; nt < 8; nt++) {
            const float p00 = __expf(Sf[nt][0] - mn0);
            const float p01 = __expf(Sf[nt][1] - mn0);
            const float p10 = __expf(Sf[nt][2] - mn1);
            const float p11 = __expf(Sf[nt][3] - mn1);
            s0 += p00 + p01; s1 += p10 + p11;
            CVTBF2(Ph[nt][0], p00, p01);
            CVTBF2(Ph[nt][1], p10, p11);
            const float t00 = p00 - __uint_as_float(Ph[nt][0] << 16);
            const float t01 = p01 - __uint_as_float(Ph[nt][0] & 0xffff0000u);
            const float t10 = p10 - __uint_as_float(Ph[nt][1] << 16);
            const float t11 = p11 - __uint_as_float(Ph[nt][1] & 0xffff0000u);
            CVTBF2(Pl[nt][0], t00, t01);
            CVTBF2(Pl[nt][1], t10, t11);
        }
        s0 += __shfl_xor_sync(0xffffffffu, s0, 1);
        s0 += __shfl_xor_sync(0xffffffffu, s0, 2);
        s1 += __shfl_xor_sync(0xffffffffu, s1, 1);
        s1 += __shfl_xor_sync(0xffffffffu, s1, 2);
        l0 = l0 * a0 + s0;
        l1 = l1 * a1 + s1;

        #pragma unroll
        for (int i = 0; i < 16; i++) {
            O[i][0] *= a0; O[i][1] *= a0; O[i][2] *= a1; O[i][3] *= a1;
        }

        // ---- O += P V  (Ph*Vh, Ph*Vl, Pl*Vh) ----
        #pragma unroll
        for (int ks = 0; ks < 4; ks++) {
            const uint32_t ah[4] = {Ph[2 * ks][0], Ph[2 * ks][1],
                                    Ph[2 * ks + 1][0], Ph[2 * ks + 1][1]};
            const uint32_t al[4] = {Pl[2 * ks][0], Pl[2 * ks][1],
                                    Pl[2 * ks + 1][0], Pl[2 * ks + 1][1]};
            #pragma unroll
            for (int nt2 = 0; nt2 < 16; nt2++) {
                const int nd = nt2 * 8 + (lane >> 2);
                const __nv_bfloat16* vp = sVh + nd * FV_LD + ks * 16 + cq;
                mma_bf16(O[nt2], ah, *(const uint32_t*)(vp),
                                     *(const uint32_t*)(vp + 8));
            }
            #pragma unroll
            for (int nt2 = 0; nt2 < 16; nt2++) {
                const int nd = nt2 * 8 + (lane >> 2);
                const __nv_bfloat16* vp2 = sVl + nd * FV_LD + ks * 16 + cq;
                mma_bf16(O[nt2], ah, *(const uint32_t*)(vp2),
                                     *(const uint32_t*)(vp2 + 8));
            }
            #pragma unroll
            for (int nt2 = 0; nt2 < 16; nt2++) {
                const int nd = nt2 * 8 + (lane >> 2);
                const __nv_bfloat16* vp = sVh + nd * FV_LD + ks * 16 + cq;
                mma_bf16(O[nt2], al, *(const uint32_t*)(vp),
                                     *(const uint32_t*)(vp + 8));
            }
        }
        __syncthreads();
    }

    // ---- epilogue: normalize, split hi/lo, write ch/cl ----
    const float inv0 = 1.f / l0, inv1 = 1.f / l1;
    const int row0 = q0 + w * 16 + (lane >> 2);
    const size_t o0 = ((size_t)b * S_ + row0) * H_ + h * HD + cq;
    const size_t o1 = o0 + 8 * (size_t)H_;
    #pragma unroll
    for (int nt2 = 0; nt2 < 16; nt2++) {
        const float f0 = O[nt2][0] * inv0, f1 = O[nt2][1] * inv0;
        const float f2 = O[nt2][2] * inv1, f3 = O[nt2][3] * inv1;
        uint32_t hh0, hh1;
        CVTBF2(hh0, f0, f1);
        CVTBF2(hh1, f2, f3);
        *(uint32_t*)&Ch[o0 + nt2 * 8] = hh0;
        *(uint32_t*)&Ch[o1 + nt2 * 8] = hh1;
        const float r0f = f0 - __uint_as_float(hh0 << 16);
        const float r1f = f1 - __uint_as_float(hh0 & 0xffff0000u);
        const float r2f = f2 - __uint_as_float(hh1 << 16);
        const float r3f = f3 - __uint_as_float(hh1 & 0xffff0000u);
        uint32_t ll0, ll1;
        CVTBF2(ll0, r0f, r1f);
        CVTBF2(ll1, r2f, r3f);
        *(uint32_t*)&Cl[o0 + nt2 * 8] = ll0;
        *(uint32_t*)&Cl[o1 + nt2 * 8] = ll1;
    }
}

// ---------------------------------------------------------------------------
// Launch
// ---------------------------------------------------------------------------
extern "C" void kernel_launch(void* const* d_in, const int* in_sizes, int n_in,
                              void* d_out, int out_size)
{
    const float* x    = (const float*)d_in[0];
    const float* Wqkv = (const float*)d_in[1];
    const float* Wo   = (const float*)d_in[2];
    float* out = (float*)d_out;

    float *qkv, *rc, *rs;
    __nv_bfloat16 *xh, *xl, *wqh, *wql, *woh, *wol, *ch, *cl;
    __nv_bfloat16 *qh, *ql, *kh, *kl, *vth, *vtl;
    cudaGetSymbolAddress((void**)&qkv, g_qkv);
    cudaGetSymbolAddress((void**)&rc, g_rcos);
    cudaGetSymbolAddress((void**)&rs, g_rsin);
    cudaGetSymbolAddress((void**)&xh, g_xh);
    cudaGetSymbolAddress((void**)&xl, g_xl);
    cudaGetSymbolAddress((void**)&wqh, g_wqh);
    cudaGetSymbolAddress((void**)&wql, g_wql);
    cudaGetSymbolAddress((void**)&woh, g_woh);
    cudaGetSymbolAddress((void**)&wol, g_wol);
    cudaGetSymbolAddress((void**)&ch, g_ch);
    cudaGetSymbolAddress((void**)&cl, g_cl);
    cudaGetSymbolAddress((void**)&qh, g_qh);
    cudaGetSymbolAddress((void**)&ql, g_ql);
    cudaGetSymbolAddress((void**)&kh, g_kh);
    cudaGetSymbolAddress((void**)&kl, g_kl);
    cudaGetSymbolAddress((void**)&vth, g_vth);
    cudaGetSymbolAddress((void**)&vtl, g_vtl);

    cudaFuncSetAttribute(gemm_bf16x3mma,
                         cudaFuncAttributeMaxDynamicSharedMemorySize, GEMM_SMEM);
    cudaFuncSetAttribute(prep_qkv,
                         cudaFuncAttributeMaxDynamicSharedMemorySize, PREP_SMEM);
    cudaFuncSetAttribute(flash_mma,
                         cudaFuncAttributeMaxDynamicSharedMemorySize, FLASH_SMEM);

    {
        const int n4 = (BS_ * H_) / 4;
        split_kernel<<<n4 / 256, 256>>>((const float4*)x, (uint2*)xh, (uint2*)xl, n4);
    }
    {
        dim3 grid(QKV_N / 32, H_ / 32), blk(32, 8);
        transpose_split<<<grid, blk>>>(Wqkv, wqh, wql, H_, QKV_N);
    }
    {
        dim3 grid(H_ / 32, H_ / 32), blk(32, 8);
        transpose_split<<<grid, blk>>>(Wo, woh, wol, H_, H_);
    }
    rope_tab<<<(S_ * 64) / 256, 256>>>(rc, rs);

    {
        dim3 grid(BS_ / 128, QKV_N / 256);
        gemm_bf16x3mma<<<grid, 256, GEMM_SMEM>>>(xh, xl, wqh, wql, qkv, QKV_N, H_);
    }
    {
        dim3 grid(S_ / 128, B_ * NH);
        prep_qkv<<<grid, 256, PREP_SMEM>>>(qkv, rc, rs, qh, ql, kh, kl, vth, vtl);
    }
    {
        dim3 grid(S_ / 128, B_ * NH);
        flash_mma<<<grid, 256, FLASH_SMEM>>>(qh, ql, kh, kl, vth, vtl, ch, cl);
    }
    {
        dim3 grid(BS_ / 128, H_ / 256);
        gemm_bf16x3mma<<<grid, 256, GEMM_SMEM>>>(ch, cl, woh, wol, out, H_, H_);
    }
}

// round 11
// speedup vs baseline: 1.0575x; 1.0043x over previous
#include <cuda_runtime.h>
#include <cuda_bf16.h>
#include <math.h>
#include <stdint.h>

// Problem constants
#define B_ 2
#define S_ 2048
#define H_ 4096
#define NH 32
#define HD 128
#define BS_ (B_ * S_)          // 4096 rows
#define QKV_N (3 * H_)         // 12288

// ---------------------------------------------------------------------------
// Scratch (static device globals)
// ---------------------------------------------------------------------------
__device__ float g_qkv[(size_t)BS_ * QKV_N];
__device__ __nv_bfloat16 g_xh[(size_t)BS_ * H_];
__device__ __nv_bfloat16 g_xl[(size_t)BS_ * H_];
__device__ __nv_bfloat16 g_wqh[(size_t)QKV_N * H_];
__device__ __nv_bfloat16 g_wql[(size_t)QKV_N * H_];
__device__ __nv_bfloat16 g_woh[(size_t)H_ * H_];
__device__ __nv_bfloat16 g_wol[(size_t)H_ * H_];
__device__ __nv_bfloat16 g_ch[(size_t)BS_ * H_];
__device__ __nv_bfloat16 g_cl[(size_t)BS_ * H_];
__device__ __nv_bfloat16 g_qh[(size_t)BS_ * H_];
__device__ __nv_bfloat16 g_ql[(size_t)BS_ * H_];
__device__ __nv_bfloat16 g_kh[(size_t)BS_ * H_];
__device__ __nv_bfloat16 g_kl[(size_t)BS_ * H_];
__device__ __nv_bfloat16 g_vth[(size_t)BS_ * H_];
__device__ __nv_bfloat16 g_vtl[(size_t)BS_ * H_];
__device__ float g_rcos[S_ * 64];
__device__ float g_rsin[S_ * 64];

// ---------------------------------------------------------------------------
// mma.sync + cp.async + ldmatrix helpers
// ---------------------------------------------------------------------------
__device__ __forceinline__ uint32_t smem_u32(const void* p) {
    uint32_t a;
    asm("{ .reg .u64 t; cvta.to.shared.u64 t, %1; cvt.u32.u64 %0, t; }"
        : "=r"(a) : "l"(p));
    return a;
}

#define CP_ASYNC16(dst, src) \
    asm volatile("cp.async.cg.shared.global [%0], [%1], 16;" \
                 :: "r"(dst), "l"(src) : "memory")
#define CP_COMMIT() asm volatile("cp.async.commit_group;" ::: "memory")
#define CP_WAIT1()  asm volatile("cp.async.wait_group 1;" ::: "memory")
#define CP_WAIT0()  asm volatile("cp.async.wait_group 0;" ::: "memory")

__device__ __forceinline__ void mma_bf16(float* d, const uint32_t* a,
                                         uint32_t b0, uint32_t b1) {
    asm volatile(
        "mma.sync.aligned.m16n8k16.row.col.f32.bf16.bf16.f32 "
        "{%0,%1,%2,%3}, {%4,%5,%6,%7}, {%8,%9}, {%0,%1,%2,%3};"
        : "+f"(d[0]), "+f"(d[1]), "+f"(d[2]), "+f"(d[3])
        : "r"(a[0]), "r"(a[1]), "r"(a[2]), "r"(a[3]), "r"(b0), "r"(b1));
}

#define LDSM4(r0, r1, r2, r3, addr) \
    asm volatile("ldmatrix.sync.aligned.m8n8.x4.shared.b16 {%0,%1,%2,%3}, [%4];" \
                 : "=r"(r0), "=r"(r1), "=r"(r2), "=r"(r3) : "r"(addr))

// pack two f32 -> bf16x2 in ONE instruction (lo = first arg)
#define CVTBF2(r, flo, fhi) \
    asm("cvt.rn.bf16x2.f32 %0, %1, %2;" : "=r"(r) : "f"(fhi), "f"(flo))

// ---------------------------------------------------------------------------
// bf16x3 mma.sync GEMM (unchanged from R10, ldmatrix loads)
// ---------------------------------------------------------------------------
#define SA_STRIDE 144
#define OFF_AH 0
#define OFF_AL (128 * SA_STRIDE)
#define OFF_BH (2 * 128 * SA_STRIDE)
#define OFF_BL (2 * 128 * SA_STRIDE + 256 * SA_STRIDE)
#define STAGE_BYTES (2 * 128 * SA_STRIDE + 2 * 256 * SA_STRIDE)  // 110592
#define GEMM_SMEM (2 * STAGE_BYTES)             // 221184
#define MT_STEP (16 * SA_STRIDE)                // 2304 bytes per 16 rows

__global__ __launch_bounds__(256, 1) void gemm_bf16x3mma(
    const __nv_bfloat16* __restrict__ Ah, const __nv_bfloat16* __restrict__ Al,
    const __nv_bfloat16* __restrict__ Bh, const __nv_bfloat16* __restrict__ Bl,
    float* __restrict__ C, int Nglob, int K)
{
    extern __shared__ char smem[];
    const int tid  = threadIdx.x;
    const int lane = tid & 31;
    const int wid  = tid >> 5;
    const int wm = wid & 1;
    const int wn = wid >> 1;
    const int bm = blockIdx.x * 128;
    const int bn = blockIdx.y * 256;

    const uint32_t sb = smem_u32(smem);
    const int nchunk = K >> 6;

    auto load_chunk = [&](int c, int s) {
        const int k0 = c << 6;
        const uint32_t st = sb + s * STAGE_BYTES;
        #pragma unroll
        for (int i = 0; i < 4; i++) {
            const int idx = tid + i * 256;
            const int r = idx >> 3, seg = idx & 7;
            const size_t go = (size_t)(bm + r) * K + k0 + seg * 8;
            const uint32_t so = r * SA_STRIDE + seg * 16;
            CP_ASYNC16(st + OFF_AH + so, Ah + go);
            CP_ASYNC16(st + OFF_AL + so, Al + go);
        }
        #pragma unroll
        for (int i = 0; i < 8; i++) {
            const int idx = tid + i * 256;
            const int r = idx >> 3, seg = idx & 7;
            const size_t go = (size_t)(bn + r) * K + k0 + seg * 8;
            const uint32_t so = r * SA_STRIDE + seg * 16;
            CP_ASYNC16(st + OFF_BH + so, Bh + go);
            CP_ASYNC16(st + OFF_BL + so, Bl + go);
        }
        CP_COMMIT();
    };

    float acc[4][8][4];
    #pragma unroll
    for (int mt = 0; mt < 4; mt++)
        #pragma unroll
        for (int nt = 0; nt < 8; nt++)
            #pragma unroll
            for (int j = 0; j < 4; j++) acc[mt][nt][j] = 0.f;

    load_chunk(0, 0);
    if (nchunk > 1) load_chunk(1, 1);

    const int l7 = lane & 7, sel = lane >> 3;
    const uint32_t offA = (uint32_t)(wm * 64 + (sel & 1) * 8 + l7) * SA_STRIDE
                        + (uint32_t)(sel >> 1) * 16;
    const uint32_t offB = (uint32_t)(wn * 64 + (sel >> 1) * 8 + l7) * SA_STRIDE
                        + (uint32_t)(sel & 1) * 16;

    for (int c = 0; c < nchunk; c++) {
        if (c + 1 < nchunk) { CP_WAIT1(); } else { CP_WAIT0(); }
        __syncthreads();

        const uint32_t st = sb + (c & 1) * STAGE_BYTES;
        const uint32_t aAh = st + OFF_AH + offA;
        const uint32_t aAl = st + OFF_AL + offA;
        const uint32_t aBh = st + OFF_BH + offB;
        const uint32_t aBl = st + OFF_BL + offB;

        #pragma unroll
        for (int ks = 0; ks < 4; ks++) {
            const uint32_t cb = ks * 32;
            uint32_t ah[4][4], al[4][4];
            #pragma unroll
            for (int mt = 0; mt < 4; mt++) {
                LDSM4(ah[mt][0], ah[mt][1], ah[mt][2], ah[mt][3],
                      aAh + mt * MT_STEP + cb);
                LDSM4(al[mt][0], al[mt][1], al[mt][2], al[mt][3],
                      aAl + mt * MT_STEP + cb);
            }
            uint32_t bhf[8][2];
            #pragma unroll
            for (int j = 0; j < 4; j++) {
                LDSM4(bhf[2 * j][0], bhf[2 * j][1],
                      bhf[2 * j + 1][0], bhf[2 * j + 1][1],
                      aBh + j * MT_STEP + cb);
            }
            #pragma unroll
            for (int nt = 0; nt < 8; nt++)
                #pragma unroll
                for (int mt = 0; mt < 4; mt++)
                    mma_bf16(acc[mt][nt], ah[mt], bhf[nt][0], bhf[nt][1]);
            #pragma unroll
            for (int nt = 0; nt < 8; nt++)
                #pragma unroll
                for (int mt = 0; mt < 4; mt++)
                    mma_bf16(acc[mt][nt], al[mt], bhf[nt][0], bhf[nt][1]);
            #pragma unroll
            for (int j = 0; j < 4; j++) {
                uint32_t bl00, bl01, bl10, bl11;
                LDSM4(bl00, bl01, bl10, bl11, aBl + j * MT_STEP + cb);
                #pragma unroll
                for (int mt = 0; mt < 4; mt++) {
                    mma_bf16(acc[mt][2 * j],     ah[mt], bl00, bl01);
                    mma_bf16(acc[mt][2 * j + 1], ah[mt], bl10, bl11);
                }
            }
        }
        __syncthreads();
        if (c + 2 < nchunk) load_chunk(c + 2, c & 1);
    }

    #pragma unroll
    for (int mt = 0; mt < 4; mt++) {
        const int row = bm + wm * 64 + mt * 16 + (lane >> 2);
        float* cp0 = C + (size_t)row * Nglob + bn + wn * 64 + (lane & 3) * 2;
        float* cp8 = cp0 + 8 * (size_t)Nglob;
        #pragma unroll
        for (int nt = 0; nt < 8; nt++) {
            *(float2*)(cp0 + nt * 8) = make_float2(acc[mt][nt][0], acc[mt][nt][1]);
            *(float2*)(cp8 + nt * 8) = make_float2(acc[mt][nt][2], acc[mt][nt][3]);
        }
    }
}

// ---------------------------------------------------------------------------
// Elementwise fp32 -> (bf16 hi, bf16 lo) split
// ---------------------------------------------------------------------------
__global__ void split_kernel(const float4* __restrict__ in,
                             uint2* __restrict__ h, uint2* __restrict__ l, int n4)
{
    const int i = blockIdx.x * blockDim.x + threadIdx.x;
    if (i >= n4) return;
    const float4 v = in[i];
    __nv_bfloat16 h0 = __float2bfloat16(v.x), h1 = __float2bfloat16(v.y);
    __nv_bfloat16 h2 = __float2bfloat16(v.z), h3 = __float2bfloat16(v.w);
    __nv_bfloat16 l0 = __float2bfloat16(v.x - __bfloat162float(h0));
    __nv_bfloat16 l1 = __float2bfloat16(v.y - __bfloat162float(h1));
    __nv_bfloat16 l2 = __float2bfloat16(v.z - __bfloat162float(h2));
    __nv_bfloat16 l3 = __float2bfloat16(v.w - __bfloat162float(h3));
    uint2 hh, ll;
    hh.x = (uint32_t)__bfloat16_as_ushort(h0) | ((uint32_t)__bfloat16_as_ushort(h1) << 16);
    hh.y = (uint32_t)__bfloat16_as_ushort(h2) | ((uint32_t)__bfloat16_as_ushort(h3) << 16);
    ll.x = (uint32_t)__bfloat16_as_ushort(l0) | ((uint32_t)__bfloat16_as_ushort(l1) << 16);
    ll.y = (uint32_t)__bfloat16_as_ushort(l2) | ((uint32_t)__bfloat16_as_ushort(l3) << 16);
    h[i] = hh; l[i] = ll;
}

// ---------------------------------------------------------------------------
// Transpose + split: W [K,N] fp32 -> Wt hi/lo [N,K] bf16
// ---------------------------------------------------------------------------
__global__ void transpose_split(const float* __restrict__ W,
                                __nv_bfloat16* __restrict__ Th,
                                __nv_bfloat16* __restrict__ Tl, int K, int N)
{
    __shared__ float t[32][33];
    const int tx = threadIdx.x, ty = threadIdx.y;
    const int nx = blockIdx.x * 32;
    const int ky = blockIdx.y * 32;
    #pragma unroll
    for (int j = 0; j < 32; j += 8)
        t[ty + j][tx] = W[(size_t)(ky + ty + j) * N + nx + tx];
    __syncthreads();
    #pragma unroll
    for (int j = 0; j < 32; j += 8) {
        const float v = t[tx][ty + j];
        const __nv_bfloat16 hi = __float2bfloat16(v);
        const __nv_bfloat16 lo = __float2bfloat16(v - __bfloat162float(hi));
        const size_t o = (size_t)(nx + ty + j) * K + ky + tx;
        Th[o] = hi; Tl[o] = lo;
    }
}

// ---------------------------------------------------------------------------
// RoPE cos/sin tables
// ---------------------------------------------------------------------------
__global__ void rope_tab(float* __restrict__ c, float* __restrict__ s)
{
    const int i = blockIdx.x * blockDim.x + threadIdx.x;
    const int t = i >> 6, p = i & 63;
    const float inv_freq = powf(10000.0f, -(float)p * (1.0f / 64.0f));
    float sn, cs;
    sincosf((float)t * inv_freq, &sn, &cs);
    c[i] = cs; s[i] = sn;
}

// ---------------------------------------------------------------------------
// prep_qkv: RoPE + scale + split hi/lo head-major; v transpose+split.
// ---------------------------------------------------------------------------
#define PREP_SMEM (128 * 133 * 4)

__global__ __launch_bounds__(256, 1) void prep_qkv(
    const float* __restrict__ qkv,
    const float* __restrict__ rc, const float* __restrict__ rs,
    __nv_bfloat16* __restrict__ Qh, __nv_bfloat16* __restrict__ Ql,
    __nv_bfloat16* __restrict__ Kh, __nv_bfloat16* __restrict__ Kl,
    __nv_bfloat16* __restrict__ Vh, __nv_bfloat16* __restrict__ Vl)
{
    extern __shared__ float ps[];
    const int tid = threadIdx.x;
    const int bh = blockIdx.y;
    const int b = bh >> 5, h = bh & 31;
    const int s0 = blockIdx.x * 128;
    const float scale = 0.08838834764831843f;

    #pragma unroll 4
    for (int i = 0; i < 32; i++) {
        const int idx = tid + i * 256;
        const int sr = idx >> 6, p = idx & 63;
        const int sg = s0 + sr;
        const size_t base = ((size_t)b * S_ + sg) * QKV_N + h * HD;
        const float cs = rc[sg * 64 + p], sn = rs[sg * 64 + p];
        const float q1 = qkv[base + p],        q2 = qkv[base + p + 64];
        const float k1 = qkv[base + H_ + p],   k2 = qkv[base + H_ + p + 64];
        const float qa = (q1 * cs - q2 * sn) * scale;
        const float qb = (q2 * cs + q1 * sn) * scale;
        const float ka = k1 * cs - k2 * sn;
        const float kb = k2 * cs + k1 * sn;
        const size_t ob = ((size_t)bh * S_ + sg) * HD;
        __nv_bfloat16 t;
        t = __float2bfloat16(qa); Qh[ob + p] = t;      Ql[ob + p]      = __float2bfloat16(qa - __bfloat162float(t));
        t = __float2bfloat16(qb); Qh[ob + p + 64] = t; Ql[ob + p + 64] = __float2bfloat16(qb - __bfloat162float(t));
        t = __float2bfloat16(ka); Kh[ob + p] = t;      Kl[ob + p]      = __float2bfloat16(ka - __bfloat162float(t));
        t = __float2bfloat16(kb); Kh[ob + p + 64] = t; Kl[ob + p + 64] = __float2bfloat16(kb - __bfloat162float(t));
    }

    #pragma unroll 4
    for (int i = 0; i < 64; i++) {
        const int idx = tid + i * 256;
        const int sr = idx >> 7, p = idx & 127;
        ps[sr * 133 + p] = qkv[((size_t)b * S_ + s0 + sr) * QKV_N + h * HD + 2 * H_ + p];
    }
    __syncthreads();
    #pragma unroll 4
    for (int i = 0; i < 64; i++) {
        const int idx = tid + i * 256;
        const int d = idx >> 7, sr = idx & 127;
        const float v = ps[sr * 133 + d];
        const __nv_bfloat16 hi = __float2bfloat16(v);
        const size_t o = ((size_t)bh * HD + d) * S_ + s0 + sr;
        Vh[o] = hi;
        Vl[o] = __float2bfloat16(v - __bfloat162float(hi));
    }
}

// ---------------------------------------------------------------------------
// Flash attention, mma.sync bf16x3 with ldmatrix fragment loads.
// ---------------------------------------------------------------------------
#define FQ_LD 136
#define FV_LD 72
#define SQ_ELEMS (128 * FQ_LD)
#define SK_ELEMS (64 * FQ_LD)
#define SV_ELEMS (128 * FV_LD)
#define FSTAGE (2 * SK_ELEMS + 2 * SV_ELEMS)
#define FLASH_SMEM ((2 * SQ_ELEMS + 2 * FSTAGE) * 2)
#define KROW_STEP (16 * FQ_LD * 2)   // 16 rows of K, bytes
#define VROW_STEP (16 * FV_LD * 2)   // 16 rows of V, bytes

__global__ __launch_bounds__(256, 1) void flash_mma(
    const __nv_bfloat16* __restrict__ Qh, const __nv_bfloat16* __restrict__ Ql,
    const __nv_bfloat16* __restrict__ Kh, const __nv_bfloat16* __restrict__ Kl,
    const __nv_bfloat16* __restrict__ Vh, const __nv_bfloat16* __restrict__ Vl,
    __nv_bfloat16* __restrict__ Ch, __nv_bfloat16* __restrict__ Cl)
{
    extern __shared__ __nv_bfloat16 fs[];
    const int tid = threadIdx.x;
    const int lane = tid & 31;
    const int w = tid >> 5;
    const int qblk = blockIdx.x;
    const int bh = blockIdx.y;
    const int b = bh >> 5, h = bh & 31;
    const int q0 = qblk * 128;
    const uint32_t sb = smem_u32(fs);

    const size_t hoff = (size_t)bh * S_ * HD;
    const size_t voff = (size_t)bh * HD * S_;

    #pragma unroll
    for (int i = 0; i < 8; i++) {
        const int idx = tid + i * 256;
        const int r = idx >> 4, seg = idx & 15;
        const size_t go = hoff + (size_t)(q0 + r) * HD + seg * 8;
        const uint32_t so = (r * FQ_LD + seg * 8) * 2;
        CP_ASYNC16(sb + so, Qh + go);
        CP_ASYNC16(sb + SQ_ELEMS * 2 + so, Ql + go);
    }

    auto load_kv = [&](int t, int s) {
        const int k0 = t * 64;
        const uint32_t st = sb + (2 * SQ_ELEMS + s * FSTAGE) * 2;
        #pragma unroll
        for (int i = 0; i < 4; i++) {
            const int idx = tid + i * 256;
            const int r = idx >> 4, seg = idx & 15;
            const size_t go = hoff + (size_t)(k0 + r) * HD + seg * 8;
            const uint32_t so = (r * FQ_LD + seg * 8) * 2;
            CP_ASYNC16(st + so, Kh + go);
            CP_ASYNC16(st + SK_ELEMS * 2 + so, Kl + go);
        }
        #pragma unroll
        for (int i = 0; i < 4; i++) {
            const int idx = tid + i * 256;
            const int r = idx >> 3, seg = idx & 7;
            const size_t go = voff + (size_t)r * S_ + k0 + seg * 8;
            const uint32_t so = (2 * SK_ELEMS + r * FV_LD + seg * 8) * 2;
            CP_ASYNC16(st + so, Vh + go);
            CP_ASYNC16(st + SV_ELEMS * 2 + so, Vl + go);
        }
        CP_COMMIT();
    };

    load_kv(0, 0);

    float O[16][4];
    #pragma unroll
    for (int i = 0; i < 16; i++)
        #pragma unroll
        for (int j = 0; j < 4; j++) O[i][j] = 0.f;
    float m0 = -1e30f, m1 = -1e30f, l0 = 0.f, l1 = 0.f;

    const int r0 = w * 16 + (lane >> 2);
    const int cq = (lane & 3) * 2;
    const int ntiles = 2 * qblk + 2;

    // ldmatrix per-lane offsets (A-pattern for Q, B-pattern for K/V)
    const int l7 = lane & 7, sel = lane >> 3;
    const uint32_t offQ = (uint32_t)(w * 16 + (sel & 1) * 8 + l7) * (FQ_LD * 2)
                        + (uint32_t)(sel >> 1) * 16;
    const uint32_t offK = (uint32_t)((sel >> 1) * 8 + l7) * (FQ_LD * 2)
                        + (uint32_t)(sel & 1) * 16;
    const uint32_t offV = (uint32_t)((sel >> 1) * 8 + l7) * (FV_LD * 2)
                        + (uint32_t)(sel & 1) * 16;

    const uint32_t aQh = sb + offQ;
    const uint32_t aQl = sb + SQ_ELEMS * 2 + offQ;

    for (int t = 0; t < ntiles; t++) {
        if (t + 1 < ntiles) { load_kv(t + 1, (t + 1) & 1); CP_WAIT1(); }
        else                { CP_WAIT0(); }
        __syncthreads();

        const uint32_t stg = sb + (2 * SQ_ELEMS + (t & 1) * FSTAGE) * 2;
        const uint32_t aKh = stg + offK;
        const uint32_t aKl = stg + SK_ELEMS * 2 + offK;
        const uint32_t aVh = stg + 2 * SK_ELEMS * 2 + offV;
        const uint32_t aVl = aVh + SV_ELEMS * 2;

        // ---- S = Q K^T (bf16x3, ldmatrix) ----
        float Sf[8][4];
        #pragma unroll
        for (int nt = 0; nt < 8; nt++)
            #pragma unroll
            for (int j = 0; j < 4; j++) Sf[nt][j] = 0.f;

        #pragma unroll
        for (int kk = 0; kk < 8; kk++) {
            const uint32_t cb = kk * 32;
            uint32_t ah[4], al[4];
            LDSM4(ah[0], ah[1], ah[2], ah[3], aQh + cb);
            LDSM4(al[0], al[1], al[2], al[3], aQl + cb);
            uint32_t khf[8][2];
            #pragma unroll
            for (int j = 0; j < 4; j++)
                LDSM4(khf[2 * j][0], khf[2 * j][1],
                      khf[2 * j + 1][0], khf[2 * j + 1][1],
                      aKh + j * KROW_STEP + cb);
            #pragma unroll
            for (int nt = 0; nt < 8; nt++)
                mma_bf16(Sf[nt], ah, khf[nt][0], khf[nt][1]);
            #pragma unroll
            for (int nt = 0; nt < 8; nt++)
                mma_bf16(Sf[nt], al, khf[nt][0], khf[nt][1]);
            #pragma unroll
            for (int j = 0; j < 4; j++) {
                uint32_t kl00, kl01, kl10, kl11;
                LDSM4(kl00, kl01, kl10, kl11, aKl + j * KROW_STEP + cb);
                mma_bf16(Sf[2 * j],     ah, kl00, kl01);
                mma_bf16(Sf[2 * j + 1], ah, kl10, kl11);
            }
        }

        // ---- mask + online softmax ----
        const int k0 = t * 64;
        const int qg0 = q0 + r0, qg1 = qg0 + 8;
        if (k0 + 63 > q0 + w * 16) {
            #pragma unroll
            for (int nt = 0; nt < 8; nt++) {
                const int kv = k0 + nt * 8 + cq;
                if (kv     > qg0) Sf[nt][0] = -1e30f;
                if (kv + 1 > qg0) Sf[nt][1] = -1e30f;
                if (kv     > qg1) Sf[nt][2] = -1e30f;
                if (kv + 1 > qg1) Sf[nt][3] = -1e30f;
            }
        }
        float mx0 = -1e30f, mx1 = -1e30f;
        #pragma unroll
        for (int nt = 0; nt < 8; nt++) {
            mx0 = fmaxf(mx0, fmaxf(Sf[nt][0], Sf[nt][1]));
            mx1 = fmaxf(mx1, fmaxf(Sf[nt][2], Sf[nt][3]));
        }
        mx0 = fmaxf(mx0, __shfl_xor_sync(0xffffffffu, mx0, 1));
        mx0 = fmaxf(mx0, __shfl_xor_sync(0xffffffffu, mx0, 2));
        mx1 = fmaxf(mx1, __shfl_xor_sync(0xffffffffu, mx1, 1));
        mx1 = fmaxf(mx1, __shfl_xor_sync(0xffffffffu, mx1, 2));

        const float mn0 = fmaxf(m0, mx0), mn1 = fmaxf(m1, mx1);
        const float a0 = __expf(m0 - mn0), a1 = __expf(m1 - mn1);
        m0 = mn0; m1 = mn1;

        float s0 = 0.f, s1 = 0.f;
        uint32_t Ph[8][2], Pl[8][2];
        #pragma unroll
        for (int nt = 0; nt < 8; nt++) {
            const float p00 = __expf(Sf[nt][0] - mn0);
            const float p01 = __expf(Sf[nt][1] - mn0);
            const float p10 = __expf(Sf[nt][2] - mn1);
            const float p11 = __expf(Sf[nt][3] - mn1);
            s0 += p00 + p01; s1 += p10 + p11;
            CVTBF2(Ph[nt][0], p00, p01);
            CVTBF2(Ph[nt][1], p10, p11);
            const float t00 = p00 - __uint_as_float(Ph[nt][0] << 16);
            const float t01 = p01 - __uint_as_float(Ph[nt][0] & 0xffff0000u);
            const float t10 = p10 - __uint_as_float(Ph[nt][1] << 16);
            const float t11 = p11 - __uint_as_float(Ph[nt][1] & 0xffff0000u);
            CVTBF2(Pl[nt][0], t00, t01);
            CVTBF2(Pl[nt][1], t10, t11);
        }
        s0 += __shfl_xor_sync(0xffffffffu, s0, 1);
        s0 += __shfl_xor_sync(0xffffffffu, s0, 2);
        s1 += __shfl_xor_sync(0xffffffffu, s1, 1);
        s1 += __shfl_xor_sync(0xffffffffu, s1, 2);
        l0 = l0 * a0 + s0;
        l1 = l1 * a1 + s1;

        #pragma unroll
        for (int i = 0; i < 16; i++) {
            O[i][0] *= a0; O[i][1] *= a0; O[i][2] *= a1; O[i][3] *= a1;
        }

        // ---- O += P V  (Ph*Vh, Ph*Vl, Pl*Vh; ldmatrix) ----
        #pragma unroll
        for (int ks = 0; ks < 4; ks++) {
            const uint32_t cb = ks * 32;
            const uint32_t ah[4] = {Ph[2 * ks][0], Ph[2 * ks][1],
                                    Ph[2 * ks + 1][0], Ph[2 * ks + 1][1]};
            const uint32_t al[4] = {Pl[2 * ks][0], Pl[2 * ks][1],
                                    Pl[2 * ks + 1][0], Pl[2 * ks + 1][1]};
            #pragma unroll
            for (int j = 0; j < 8; j++) {
                uint32_t v00, v01, v10, v11;
                LDSM4(v00, v01, v10, v11, aVh + j * VROW_STEP + cb);
                mma_bf16(O[2 * j],     ah, v00, v01);
                mma_bf16(O[2 * j + 1], ah, v10, v11);
            }
            #pragma unroll
            for (int j = 0; j < 8; j++) {
                uint32_t v00, v01, v10, v11;
                LDSM4(v00, v01, v10, v11, aVl + j * VROW_STEP + cb);
                mma_bf16(O[2 * j],     ah, v00, v01);
                mma_bf16(O[2 * j + 1], ah, v10, v11);
            }
            #pragma unroll
            for (int j = 0; j < 8; j++) {
                uint32_t v00, v01, v10, v11;
                LDSM4(v00, v01, v10, v11, aVh + j * VROW_STEP + cb);
                mma_bf16(O[2 * j],     al, v00, v01);
                mma_bf16(O[2 * j + 1], al, v10, v11);
            }
        }
        __syncthreads();
    }

    // ---- epilogue: normalize, split hi/lo, write ch/cl ----
    const float inv0 = 1.f / l0, inv1 = 1.f / l1;
    const int row0 = q0 + w * 16 + (lane >> 2);
    const size_t o0 = ((size_t)b * S_ + row0) * H_ + h * HD + cq;
    const size_t o1 = o0 + 8 * (size_t)H_;
    #pragma unroll
    for (int nt2 = 0; nt2 < 16; nt2++) {
        const float f0 = O[nt2][0] * inv0, f1 = O[nt2][1] * inv0;
        const float f2 = O[nt2][2] * inv1, f3 = O[nt2][3] * inv1;
        uint32_t hh0, hh1;
        CVTBF2(hh0, f0, f1);
        CVTBF2(hh1, f2, f3);
        *(uint32_t*)&Ch[o0 + nt2 * 8] = hh0;
        *(uint32_t*)&Ch[o1 + nt2 * 8] = hh1;
        const float r0f = f0 - __uint_as_float(hh0 << 16);
        const float r1f = f1 - __uint_as_float(hh0 & 0xffff0000u);
        const float r2f = f2 - __uint_as_float(hh1 << 16);
        const float r3f = f3 - __uint_as_float(hh1 & 0xffff0000u);
        uint32_t ll0, ll1;
        CVTBF2(ll0, r0f, r1f);
        CVTBF2(ll1, r2f, r3f);
        *(uint32_t*)&Cl[o0 + nt2 * 8] = ll0;
        *(uint32_t*)&Cl[o1 + nt2 * 8] = ll1;
    }
}

// ---------------------------------------------------------------------------
// Launch
// ---------------------------------------------------------------------------
extern "C" void kernel_launch(void* const* d_in, const int* in_sizes, int n_in,
                              void* d_out, int out_size)
{
    const float* x    = (const float*)d_in[0];
    const float* Wqkv = (const float*)d_in[1];
    const float* Wo   = (const float*)d_in[2];
    float* out = (float*)d_out;

    float *qkv, *rc, *rs;
    __nv_bfloat16 *xh, *xl, *wqh, *wql, *woh, *wol, *ch, *cl;
    __nv_bfloat16 *qh, *ql, *kh, *kl, *vth, *vtl;
    cudaGetSymbolAddress((void**)&qkv, g_qkv);
    cudaGetSymbolAddress((void**)&rc, g_rcos);
    cudaGetSymbolAddress((void**)&rs, g_rsin);
    cudaGetSymbolAddress((void**)&xh, g_xh);
    cudaGetSymbolAddress((void**)&xl, g_xl);
    cudaGetSymbolAddress((void**)&wqh, g_wqh);
    cudaGetSymbolAddress((void**)&wql, g_wql);
    cudaGetSymbolAddress((void**)&woh, g_woh);
    cudaGetSymbolAddress((void**)&wol, g_wol);
    cudaGetSymbolAddress((void**)&ch, g_ch);
    cudaGetSymbolAddress((void**)&cl, g_cl);
    cudaGetSymbolAddress((void**)&qh, g_qh);
    cudaGetSymbolAddress((void**)&ql, g_ql);
    cudaGetSymbolAddress((void**)&kh, g_kh);
    cudaGetSymbolAddress((void**)&kl, g_kl);
    cudaGetSymbolAddress((void**)&vth, g_vth);
    cudaGetSymbolAddress((void**)&vtl, g_vtl);

    cudaFuncSetAttribute(gemm_bf16x3mma,
                         cudaFuncAttributeMaxDynamicSharedMemorySize, GEMM_SMEM);
    cudaFuncSetAttribute(prep_qkv,
                         cudaFuncAttributeMaxDynamicSharedMemorySize, PREP_SMEM);
    cudaFuncSetAttribute(flash_mma,
                         cudaFuncAttributeMaxDynamicSharedMemorySize, FLASH_SMEM);

    {
        const int n4 = (BS_ * H_) / 4;
        split_kernel<<<n4 / 256, 256>>>((const float4*)x, (uint2*)xh, (uint2*)xl, n4);
    }
    {
        dim3 grid(QKV_N / 32, H_ / 32), blk(32, 8);
        transpose_split<<<grid, blk>>>(Wqkv, wqh, wql, H_, QKV_N);
    }
    {
        dim3 grid(H_ / 32, H_ / 32), blk(32, 8);
        transpose_split<<<grid, blk>>>(Wo, woh, wol, H_, H_);
    }
    rope_tab<<<(S_ * 64) / 256, 256>>>(rc, rs);

    {
        dim3 grid(BS_ / 128, QKV_N / 256);
        gemm_bf16x3mma<<<grid, 256, GEMM_SMEM>>>(xh, xl, wqh, wql, qkv, QKV_N, H_);
    }
    {
        dim3 grid(S_ / 128, B_ * NH);
        prep_qkv<<<grid, 256, PREP_SMEM>>>(qkv, rc, rs, qh, ql, kh, kl, vth, vtl);
    }
    {
        dim3 grid(S_ / 128, B_ * NH);
        flash_mma<<<grid, 256, FLASH_SMEM>>>(qh, ql, kh, kl, vth, vtl, ch, cl);
    }
    {
        dim3 grid(BS_ / 128, H_ / 256);
        gemm_bf16x3mma<<<grid, 256, GEMM_SMEM>>>(ch, cl, woh, wol, out, H_, H_);
    }
}

// round 12
// speedup vs baseline: 1.0594x; 1.0018x over previous
#include <cuda_runtime.h>
#include <cuda_bf16.h>
#include <math.h>
#include <stdint.h>

// Problem constants
#define B_ 2
#define S_ 2048
#define H_ 4096
#define NH 32
#define HD 128
#define BS_ (B_ * S_)          // 4096 rows
#define QKV_N (3 * H_)         // 12288

// ---------------------------------------------------------------------------
// Scratch (static device globals)
// ---------------------------------------------------------------------------
__device__ float g_qkv[(size_t)BS_ * QKV_N];
__device__ __nv_bfloat16 g_xh[(size_t)BS_ * H_];
__device__ __nv_bfloat16 g_xl[(size_t)BS_ * H_];
__device__ __nv_bfloat16 g_wqh[(size_t)QKV_N * H_];
__device__ __nv_bfloat16 g_wql[(size_t)QKV_N * H_];
__device__ __nv_bfloat16 g_woh[(size_t)H_ * H_];
__device__ __nv_bfloat16 g_wol[(size_t)H_ * H_];
__device__ __nv_bfloat16 g_ch[(size_t)BS_ * H_];
__device__ __nv_bfloat16 g_cl[(size_t)BS_ * H_];
__device__ __nv_bfloat16 g_qh[(size_t)BS_ * H_];
__device__ __nv_bfloat16 g_ql[(size_t)BS_ * H_];
__device__ __nv_bfloat16 g_kh[(size_t)BS_ * H_];
__device__ __nv_bfloat16 g_kl[(size_t)BS_ * H_];
__device__ __nv_bfloat16 g_vth[(size_t)BS_ * H_];
__device__ __nv_bfloat16 g_vtl[(size_t)BS_ * H_];
__device__ float g_rcos[S_ * 64];
__device__ float g_rsin[S_ * 64];

// ---------------------------------------------------------------------------
// mma.sync + cp.async + ldmatrix helpers
// ---------------------------------------------------------------------------
__device__ __forceinline__ uint32_t smem_u32(const void* p) {
    uint32_t a;
    asm("{ .reg .u64 t; cvta.to.shared.u64 t, %1; cvt.u32.u64 %0, t; }"
        : "=r"(a) : "l"(p));
    return a;
}

#define CP_ASYNC16(dst, src) \
    asm volatile("cp.async.cg.shared.global [%0], [%1], 16;" \
                 :: "r"(dst), "l"(src) : "memory")
#define CP_COMMIT() asm volatile("cp.async.commit_group;" ::: "memory")
#define CP_WAIT1()  asm volatile("cp.async.wait_group 1;" ::: "memory")
#define CP_WAIT0()  asm volatile("cp.async.wait_group 0;" ::: "memory")

__device__ __forceinline__ void mma_bf16(float* d, const uint32_t* a,
                                         uint32_t b0, uint32_t b1) {
    asm volatile(
        "mma.sync.aligned.m16n8k16.row.col.f32.bf16.bf16.f32 "
        "{%0,%1,%2,%3}, {%4,%5,%6,%7}, {%8,%9}, {%0,%1,%2,%3};"
        : "+f"(d[0]), "+f"(d[1]), "+f"(d[2]), "+f"(d[3])
        : "r"(a[0]), "r"(a[1]), "r"(a[2]), "r"(a[3]), "r"(b0), "r"(b1));
}

#define LDSM4(r0, r1, r2, r3, addr) \
    asm volatile("ldmatrix.sync.aligned.m8n8.x4.shared.b16 {%0,%1,%2,%3}, [%4];" \
                 : "=r"(r0), "=r"(r1), "=r"(r2), "=r"(r3) : "r"(addr))

// pack two f32 -> bf16x2 in ONE instruction (lo = first arg)
#define CVTBF2(r, flo, fhi) \
    asm("cvt.rn.bf16x2.f32 %0, %1, %2;" : "=r"(r) : "f"(fhi), "f"(flo))

// ---------------------------------------------------------------------------
// bf16x3 mma.sync GEMM (unchanged from R10/R11, ldmatrix loads)
// ---------------------------------------------------------------------------
#define SA_STRIDE 144
#define OFF_AH 0
#define OFF_AL (128 * SA_STRIDE)
#define OFF_BH (2 * 128 * SA_STRIDE)
#define OFF_BL (2 * 128 * SA_STRIDE + 256 * SA_STRIDE)
#define STAGE_BYTES (2 * 128 * SA_STRIDE + 2 * 256 * SA_STRIDE)  // 110592
#define GEMM_SMEM (2 * STAGE_BYTES)             // 221184
#define MT_STEP (16 * SA_STRIDE)                // 2304 bytes per 16 rows

__global__ __launch_bounds__(256, 1) void gemm_bf16x3mma(
    const __nv_bfloat16* __restrict__ Ah, const __nv_bfloat16* __restrict__ Al,
    const __nv_bfloat16* __restrict__ Bh, const __nv_bfloat16* __restrict__ Bl,
    float* __restrict__ C, int Nglob, int K)
{
    extern __shared__ char smem[];
    const int tid  = threadIdx.x;
    const int lane = tid & 31;
    const int wid  = tid >> 5;
    const int wm = wid & 1;
    const int wn = wid >> 1;
    const int bm = blockIdx.x * 128;
    const int bn = blockIdx.y * 256;

    const uint32_t sb = smem_u32(smem);
    const int nchunk = K >> 6;

    auto load_chunk = [&](int c, int s) {
        const int k0 = c << 6;
        const uint32_t st = sb + s * STAGE_BYTES;
        #pragma unroll
        for (int i = 0; i < 4; i++) {
            const int idx = tid + i * 256;
            const int r = idx >> 3, seg = idx & 7;
            const size_t go = (size_t)(bm + r) * K + k0 + seg * 8;
            const uint32_t so = r * SA_STRIDE + seg * 16;
            CP_ASYNC16(st + OFF_AH + so, Ah + go);
            CP_ASYNC16(st + OFF_AL + so, Al + go);
        }
        #pragma unroll
        for (int i = 0; i < 8; i++) {
            const int idx = tid + i * 256;
            const int r = idx >> 3, seg = idx & 7;
            const size_t go = (size_t)(bn + r) * K + k0 + seg * 8;
            const uint32_t so = r * SA_STRIDE + seg * 16;
            CP_ASYNC16(st + OFF_BH + so, Bh + go);
            CP_ASYNC16(st + OFF_BL + so, Bl + go);
        }
        CP_COMMIT();
    };

    float acc[4][8][4];
    #pragma unroll
    for (int mt = 0; mt < 4; mt++)
        #pragma unroll
        for (int nt = 0; nt < 8; nt++)
            #pragma unroll
            for (int j = 0; j < 4; j++) acc[mt][nt][j] = 0.f;

    load_chunk(0, 0);
    if (nchunk > 1) load_chunk(1, 1);

    const int l7 = lane & 7, sel = lane >> 3;
    const uint32_t offA = (uint32_t)(wm * 64 + (sel & 1) * 8 + l7) * SA_STRIDE
                        + (uint32_t)(sel >> 1) * 16;
    const uint32_t offB = (uint32_t)(wn * 64 + (sel >> 1) * 8 + l7) * SA_STRIDE
                        + (uint32_t)(sel & 1) * 16;

    for (int c = 0; c < nchunk; c++) {
        if (c + 1 < nchunk) { CP_WAIT1(); } else { CP_WAIT0(); }
        __syncthreads();

        const uint32_t st = sb + (c & 1) * STAGE_BYTES;
        const uint32_t aAh = st + OFF_AH + offA;
        const uint32_t aAl = st + OFF_AL + offA;
        const uint32_t aBh = st + OFF_BH + offB;
        const uint32_t aBl = st + OFF_BL + offB;

        #pragma unroll
        for (int ks = 0; ks < 4; ks++) {
            const uint32_t cb = ks * 32;
            uint32_t ah[4][4], al[4][4];
            #pragma unroll
            for (int mt = 0; mt < 4; mt++) {
                LDSM4(ah[mt][0], ah[mt][1], ah[mt][2], ah[mt][3],
                      aAh + mt * MT_STEP + cb);
                LDSM4(al[mt][0], al[mt][1], al[mt][2], al[mt][3],
                      aAl + mt * MT_STEP + cb);
            }
            uint32_t bhf[8][2];
            #pragma unroll
            for (int j = 0; j < 4; j++) {
                LDSM4(bhf[2 * j][0], bhf[2 * j][1],
                      bhf[2 * j + 1][0], bhf[2 * j + 1][1],
                      aBh + j * MT_STEP + cb);
            }
            #pragma unroll
            for (int nt = 0; nt < 8; nt++)
                #pragma unroll
                for (int mt = 0; mt < 4; mt++)
                    mma_bf16(acc[mt][nt], ah[mt], bhf[nt][0], bhf[nt][1]);
            #pragma unroll
            for (int nt = 0; nt < 8; nt++)
                #pragma unroll
                for (int mt = 0; mt < 4; mt++)
                    mma_bf16(acc[mt][nt], al[mt], bhf[nt][0], bhf[nt][1]);
            #pragma unroll
            for (int j = 0; j < 4; j++) {
                uint32_t bl00, bl01, bl10, bl11;
                LDSM4(bl00, bl01, bl10, bl11, aBl + j * MT_STEP + cb);
                #pragma unroll
                for (int mt = 0; mt < 4; mt++) {
                    mma_bf16(acc[mt][2 * j],     ah[mt], bl00, bl01);
                    mma_bf16(acc[mt][2 * j + 1], ah[mt], bl10, bl11);
                }
            }
        }
        __syncthreads();
        if (c + 2 < nchunk) load_chunk(c + 2, c & 1);
    }

    #pragma unroll
    for (int mt = 0; mt < 4; mt++) {
        const int row = bm + wm * 64 + mt * 16 + (lane >> 2);
        float* cp0 = C + (size_t)row * Nglob + bn + wn * 64 + (lane & 3) * 2;
        float* cp8 = cp0 + 8 * (size_t)Nglob;
        #pragma unroll
        for (int nt = 0; nt < 8; nt++) {
            *(float2*)(cp0 + nt * 8) = make_float2(acc[mt][nt][0], acc[mt][nt][1]);
            *(float2*)(cp8 + nt * 8) = make_float2(acc[mt][nt][2], acc[mt][nt][3]);
        }
    }
}

// ---------------------------------------------------------------------------
// Elementwise fp32 -> (bf16 hi, bf16 lo) split
// ---------------------------------------------------------------------------
__global__ void split_kernel(const float4* __restrict__ in,
                             uint2* __restrict__ h, uint2* __restrict__ l, int n4)
{
    const int i = blockIdx.x * blockDim.x + threadIdx.x;
    if (i >= n4) return;
    const float4 v = in[i];
    __nv_bfloat16 h0 = __float2bfloat16(v.x), h1 = __float2bfloat16(v.y);
    __nv_bfloat16 h2 = __float2bfloat16(v.z), h3 = __float2bfloat16(v.w);
    __nv_bfloat16 l0 = __float2bfloat16(v.x - __bfloat162float(h0));
    __nv_bfloat16 l1 = __float2bfloat16(v.y - __bfloat162float(h1));
    __nv_bfloat16 l2 = __float2bfloat16(v.z - __bfloat162float(h2));
    __nv_bfloat16 l3 = __float2bfloat16(v.w - __bfloat162float(h3));
    uint2 hh, ll;
    hh.x = (uint32_t)__bfloat16_as_ushort(h0) | ((uint32_t)__bfloat16_as_ushort(h1) << 16);
    hh.y = (uint32_t)__bfloat16_as_ushort(h2) | ((uint32_t)__bfloat16_as_ushort(h3) << 16);
    ll.x = (uint32_t)__bfloat16_as_ushort(l0) | ((uint32_t)__bfloat16_as_ushort(l1) << 16);
    ll.y = (uint32_t)__bfloat16_as_ushort(l2) | ((uint32_t)__bfloat16_as_ushort(l3) << 16);
    h[i] = hh; l[i] = ll;
}

// ---------------------------------------------------------------------------
// Transpose + split: W [K,N] fp32 -> Wt hi/lo [N,K] bf16
// ---------------------------------------------------------------------------
__global__ void transpose_split(const float* __restrict__ W,
                                __nv_bfloat16* __restrict__ Th,
                                __nv_bfloat16* __restrict__ Tl, int K, int N)
{
    __shared__ float t[32][33];
    const int tx = threadIdx.x, ty = threadIdx.y;
    const int nx = blockIdx.x * 32;
    const int ky = blockIdx.y * 32;
    #pragma unroll
    for (int j = 0; j < 32; j += 8)
        t[ty + j][tx] = W[(size_t)(ky + ty + j) * N + nx + tx];
    __syncthreads();
    #pragma unroll
    for (int j = 0; j < 32; j += 8) {
        const float v = t[tx][ty + j];
        const __nv_bfloat16 hi = __float2bfloat16(v);
        const __nv_bfloat16 lo = __float2bfloat16(v - __bfloat162float(hi));
        const size_t o = (size_t)(nx + ty + j) * K + ky + tx;
        Th[o] = hi; Tl[o] = lo;
    }
}

// ---------------------------------------------------------------------------
// RoPE cos/sin tables
// ---------------------------------------------------------------------------
__global__ void rope_tab(float* __restrict__ c, float* __restrict__ s)
{
    const int i = blockIdx.x * blockDim.x + threadIdx.x;
    const int t = i >> 6, p = i & 63;
    const float inv_freq = powf(10000.0f, -(float)p * (1.0f / 64.0f));
    float sn, cs;
    sincosf((float)t * inv_freq, &sn, &cs);
    c[i] = cs; s[i] = sn;
}

// ---------------------------------------------------------------------------
// prep_qkv: RoPE + scale + split hi/lo head-major; v transpose+split.
// ---------------------------------------------------------------------------
#define PREP_SMEM (128 * 133 * 4)

__global__ __launch_bounds__(256, 1) void prep_qkv(
    const float* __restrict__ qkv,
    const float* __restrict__ rc, const float* __restrict__ rs,
    __nv_bfloat16* __restrict__ Qh, __nv_bfloat16* __restrict__ Ql,
    __nv_bfloat16* __restrict__ Kh, __nv_bfloat16* __restrict__ Kl,
    __nv_bfloat16* __restrict__ Vh, __nv_bfloat16* __restrict__ Vl)
{
    extern __shared__ float ps[];
    const int tid = threadIdx.x;
    const int bh = blockIdx.y;
    const int b = bh >> 5, h = bh & 31;
    const int s0 = blockIdx.x * 128;
    const float scale = 0.08838834764831843f;

    #pragma unroll 4
    for (int i = 0; i < 32; i++) {
        const int idx = tid + i * 256;
        const int sr = idx >> 6, p = idx & 63;
        const int sg = s0 + sr;
        const size_t base = ((size_t)b * S_ + sg) * QKV_N + h * HD;
        const float cs = rc[sg * 64 + p], sn = rs[sg * 64 + p];
        const float q1 = qkv[base + p],        q2 = qkv[base + p + 64];
        const float k1 = qkv[base + H_ + p],   k2 = qkv[base + H_ + p + 64];
        const float qa = (q1 * cs - q2 * sn) * scale;
        const float qb = (q2 * cs + q1 * sn) * scale;
        const float ka = k1 * cs - k2 * sn;
        const float kb = k2 * cs + k1 * sn;
        const size_t ob = ((size_t)bh * S_ + sg) * HD;
        __nv_bfloat16 t;
        t = __float2bfloat16(qa); Qh[ob + p] = t;      Ql[ob + p]      = __float2bfloat16(qa - __bfloat162float(t));
        t = __float2bfloat16(qb); Qh[ob + p + 64] = t; Ql[ob + p + 64] = __float2bfloat16(qb - __bfloat162float(t));
        t = __float2bfloat16(ka); Kh[ob + p] = t;      Kl[ob + p]      = __float2bfloat16(ka - __bfloat162float(t));
        t = __float2bfloat16(kb); Kh[ob + p + 64] = t; Kl[ob + p + 64] = __float2bfloat16(kb - __bfloat162float(t));
    }

    #pragma unroll 4
    for (int i = 0; i < 64; i++) {
        const int idx = tid + i * 256;
        const int sr = idx >> 7, p = idx & 127;
        ps[sr * 133 + p] = qkv[((size_t)b * S_ + s0 + sr) * QKV_N + h * HD + 2 * H_ + p];
    }
    __syncthreads();
    #pragma unroll 4
    for (int i = 0; i < 64; i++) {
        const int idx = tid + i * 256;
        const int d = idx >> 7, sr = idx & 127;
        const float v = ps[sr * 133 + d];
        const __nv_bfloat16 hi = __float2bfloat16(v);
        const size_t o = ((size_t)bh * HD + d) * S_ + s0 + sr;
        Vh[o] = hi;
        Vl[o] = __float2bfloat16(v - __bfloat162float(hi));
    }
}

// ---------------------------------------------------------------------------
// Flash attention, mma.sync bf16x3, ldmatrix loads, heavy-first scheduling.
// ---------------------------------------------------------------------------
#define FQ_LD 136
#define FV_LD 72
#define SQ_ELEMS (128 * FQ_LD)
#define SK_ELEMS (64 * FQ_LD)
#define SV_ELEMS (128 * FV_LD)
#define FSTAGE (2 * SK_ELEMS + 2 * SV_ELEMS)
#define FLASH_SMEM ((2 * SQ_ELEMS + 2 * FSTAGE) * 2)
#define KROW_STEP (16 * FQ_LD * 2)
#define VROW_STEP (16 * FV_LD * 2)

__global__ __launch_bounds__(256, 1) void flash_mma(
    const __nv_bfloat16* __restrict__ Qh, const __nv_bfloat16* __restrict__ Ql,
    const __nv_bfloat16* __restrict__ Kh, const __nv_bfloat16* __restrict__ Kl,
    const __nv_bfloat16* __restrict__ Vh, const __nv_bfloat16* __restrict__ Vl,
    __nv_bfloat16* __restrict__ Ch, __nv_bfloat16* __restrict__ Cl)
{
    extern __shared__ __nv_bfloat16 fs[];
    const int tid = threadIdx.x;
    const int lane = tid & 31;
    const int w = tid >> 5;
    // heavy-first: high qblk (most KV tiles) launches first
    const int qblk = gridDim.x - 1 - blockIdx.x;
    const int bh = blockIdx.y;
    const int b = bh >> 5, h = bh & 31;
    const int q0 = qblk * 128;
    const uint32_t sb = smem_u32(fs);

    const size_t hoff = (size_t)bh * S_ * HD;
    const size_t voff = (size_t)bh * HD * S_;

    #pragma unroll
    for (int i = 0; i < 8; i++) {
        const int idx = tid + i * 256;
        const int r = idx >> 4, seg = idx & 15;
        const size_t go = hoff + (size_t)(q0 + r) * HD + seg * 8;
        const uint32_t so = (r * FQ_LD + seg * 8) * 2;
        CP_ASYNC16(sb + so, Qh + go);
        CP_ASYNC16(sb + SQ_ELEMS * 2 + so, Ql + go);
    }

    auto load_kv = [&](int t, int s) {
        const int k0 = t * 64;
        const uint32_t st = sb + (2 * SQ_ELEMS + s * FSTAGE) * 2;
        #pragma unroll
        for (int i = 0; i < 4; i++) {
            const int idx = tid + i * 256;
            const int r = idx >> 4, seg = idx & 15;
            const size_t go = hoff + (size_t)(k0 + r) * HD + seg * 8;
            const uint32_t so = (r * FQ_LD + seg * 8) * 2;
            CP_ASYNC16(st + so, Kh + go);
            CP_ASYNC16(st + SK_ELEMS * 2 + so, Kl + go);
        }
        #pragma unroll
        for (int i = 0; i < 4; i++) {
            const int idx = tid + i * 256;
            const int r = idx >> 3, seg = idx & 7;
            const size_t go = voff + (size_t)r * S_ + k0 + seg * 8;
            const uint32_t so = (2 * SK_ELEMS + r * FV_LD + seg * 8) * 2;
            CP_ASYNC16(st + so, Vh + go);
            CP_ASYNC16(st + SV_ELEMS * 2 + so, Vl + go);
        }
        CP_COMMIT();
    };

    load_kv(0, 0);

    float O[16][4];
    #pragma unroll
    for (int i = 0; i < 16; i++)
        #pragma unroll
        for (int j = 0; j < 4; j++) O[i][j] = 0.f;
    float m0 = -1e30f, m1 = -1e30f, l0 = 0.f, l1 = 0.f;

    const int r0 = w * 16 + (lane >> 2);
    const int cq = (lane & 3) * 2;
    const int ntiles = 2 * qblk + 2;

    const int l7 = lane & 7, sel = lane >> 3;
    const uint32_t offQ = (uint32_t)(w * 16 + (sel & 1) * 8 + l7) * (FQ_LD * 2)
                        + (uint32_t)(sel >> 1) * 16;
    const uint32_t offK = (uint32_t)((sel >> 1) * 8 + l7) * (FQ_LD * 2)
                        + (uint32_t)(sel & 1) * 16;
    const uint32_t offV = (uint32_t)((sel >> 1) * 8 + l7) * (FV_LD * 2)
                        + (uint32_t)(sel & 1) * 16;

    const uint32_t aQh = sb + offQ;
    const uint32_t aQl = sb + SQ_ELEMS * 2 + offQ;

    for (int t = 0; t < ntiles; t++) {
        if (t + 1 < ntiles) { load_kv(t + 1, (t + 1) & 1); CP_WAIT1(); }
        else                { CP_WAIT0(); }
        __syncthreads();

        const uint32_t stg = sb + (2 * SQ_ELEMS + (t & 1) * FSTAGE) * 2;
        const uint32_t aKh = stg + offK;
        const uint32_t aKl = stg + SK_ELEMS * 2 + offK;
        const uint32_t aVh = stg + 2 * SK_ELEMS * 2 + offV;
        const uint32_t aVl = aVh + SV_ELEMS * 2;

        // ---- S = Q K^T (bf16x3, ldmatrix) ----
        float Sf[8][4];
        #pragma unroll
        for (int nt = 0; nt < 8; nt++)
            #pragma unroll
            for (int j = 0; j < 4; j++) Sf[nt][j] = 0.f;

        #pragma unroll
        for (int kk = 0; kk < 8; kk++) {
            const uint32_t cb = kk * 32;
            uint32_t ah[4], al[4];
            LDSM4(ah[0], ah[1], ah[2], ah[3], aQh + cb);
            LDSM4(al[0], al[1], al[2], al[3], aQl + cb);
            uint32_t khf[8][2];
            #pragma unroll
            for (int j = 0; j < 4; j++)
                LDSM4(khf[2 * j][0], khf[2 * j][1],
                      khf[2 * j + 1][0], khf[2 * j + 1][1],
                      aKh + j * KROW_STEP + cb);
            #pragma unroll
            for (int nt = 0; nt < 8; nt++)
                mma_bf16(Sf[nt], ah, khf[nt][0], khf[nt][1]);
            #pragma unroll
            for (int nt = 0; nt < 8; nt++)
                mma_bf16(Sf[nt], al, khf[nt][0], khf[nt][1]);
            #pragma unroll
            for (int j = 0; j < 4; j++) {
                uint32_t kl00, kl01, kl10, kl11;
                LDSM4(kl00, kl01, kl10, kl11, aKl + j * KROW_STEP + cb);
                mma_bf16(Sf[2 * j],     ah, kl00, kl01);
                mma_bf16(Sf[2 * j + 1], ah, kl10, kl11);
            }
        }

        // ---- mask + online softmax ----
        const int k0 = t * 64;
        const int qg0 = q0 + r0, qg1 = qg0 + 8;
        if (k0 + 63 > q0 + w * 16) {
            #pragma unroll
            for (int nt = 0; nt < 8; nt++) {
                const int kv = k0 + nt * 8 + cq;
                if (kv     > qg0) Sf[nt][0] = -1e30f;
                if (kv + 1 > qg0) Sf[nt][1] = -1e30f;
                if (kv     > qg1) Sf[nt][2] = -1e30f;
                if (kv + 1 > qg1) Sf[nt][3] = -1e30f;
            }
        }
        float mx0 = -1e30f, mx1 = -1e30f;
        #pragma unroll
        for (int nt = 0; nt < 8; nt++) {
            mx0 = fmaxf(mx0, fmaxf(Sf[nt][0], Sf[nt][1]));
            mx1 = fmaxf(mx1, fmaxf(Sf[nt][2], Sf[nt][3]));
        }
        mx0 = fmaxf(mx0, __shfl_xor_sync(0xffffffffu, mx0, 1));
        mx0 = fmaxf(mx0, __shfl_xor_sync(0xffffffffu, mx0, 2));
        mx1 = fmaxf(mx1, __shfl_xor_sync(0xffffffffu, mx1, 1));
        mx1 = fmaxf(mx1, __shfl_xor_sync(0xffffffffu, mx1, 2));

        const float mn0 = fmaxf(m0, mx0), mn1 = fmaxf(m1, mx1);
        const float a0 = __expf(m0 - mn0), a1 = __expf(m1 - mn1);
        m0 = mn0; m1 = mn1;

        float s0 = 0.f, s1 = 0.f;
        uint32_t Ph[8][2], Pl[8][2];
        #pragma unroll
        for (int nt = 0; nt < 8; nt++) {
            const float p00 = __expf(Sf[nt][0] - mn0);
            const float p01 = __expf(Sf[nt][1] - mn0);
            const float p10 = __expf(Sf[nt][2] - mn1);
            const float p11 = __expf(Sf[nt][3] - mn1);
            s0 += p00 + p01; s1 += p10 + p11;
            CVTBF2(Ph[nt][0], p00, p01);
            CVTBF2(Ph[nt][1], p10, p11);
            const float t00 = p00 - __uint_as_float(Ph[nt][0] << 16);
            const float t01 = p01 - __uint_as_float(Ph[nt][0] & 0xffff0000u);
            const float t10 = p10 - __uint_as_float(Ph[nt][1] << 16);
            const float t11 = p11 - __uint_as_float(Ph[nt][1] & 0xffff0000u);
            CVTBF2(Pl[nt][0], t00, t01);
            CVTBF2(Pl[nt][1], t10, t11);
        }
        s0 += __shfl_xor_sync(0xffffffffu, s0, 1);
        s0 += __shfl_xor_sync(0xffffffffu, s0, 2);
        s1 += __shfl_xor_sync(0xffffffffu, s1, 1);
        s1 += __shfl_xor_sync(0xffffffffu, s1, 2);
        l0 = l0 * a0 + s0;
        l1 = l1 * a1 + s1;

        #pragma unroll
        for (int i = 0; i < 16; i++) {
            O[i][0] *= a0; O[i][1] *= a0; O[i][2] *= a1; O[i][3] *= a1;
        }

        // ---- O += P V  (Ph*Vh, Ph*Vl, Pl*Vh; ldmatrix) ----
        #pragma unroll
        for (int ks = 0; ks < 4; ks++) {
            const uint32_t cb = ks * 32;
            const uint32_t ah[4] = {Ph[2 * ks][0], Ph[2 * ks][1],
                                    Ph[2 * ks + 1][0], Ph[2 * ks + 1][1]};
            const uint32_t al[4] = {Pl[2 * ks][0], Pl[2 * ks][1],
                                    Pl[2 * ks + 1][0], Pl[2 * ks + 1][1]};
            #pragma unroll
            for (int j = 0; j < 8; j++) {
                uint32_t v00, v01, v10, v11;
                LDSM4(v00, v01, v10, v11, aVh + j * VROW_STEP + cb);
                mma_bf16(O[2 * j],     ah, v00, v01);
                mma_bf16(O[2 * j + 1], ah, v10, v11);
            }
            #pragma unroll
            for (int j = 0; j < 8; j++) {
                uint32_t v00, v01, v10, v11;
                LDSM4(v00, v01, v10, v11, aVl + j * VROW_STEP + cb);
                mma_bf16(O[2 * j],     ah, v00, v01);
                mma_bf16(O[2 * j + 1], ah, v10, v11);
            }
            #pragma unroll
            for (int j = 0; j < 8; j++) {
                uint32_t v00, v01, v10, v11;
                LDSM4(v00, v01, v10, v11, aVh + j * VROW_STEP + cb);
                mma_bf16(O[2 * j],     al, v00, v01);
                mma_bf16(O[2 * j + 1], al, v10, v11);
            }
        }
        __syncthreads();
    }

    // ---- epilogue: normalize, split hi/lo, write ch/cl ----
    const float inv0 = 1.f / l0, inv1 = 1.f / l1;
    const int row0 = q0 + w * 16 + (lane >> 2);
    const size_t o0 = ((size_t)b * S_ + row0) * H_ + h * HD + cq;
    const size_t o1 = o0 + 8 * (size_t)H_;
    #pragma unroll
    for (int nt2 = 0; nt2 < 16; nt2++) {
        const float f0 = O[nt2][0] * inv0, f1 = O[nt2][1] * inv0;
        const float f2 = O[nt2][2] * inv1, f3 = O[nt2][3] * inv1;
        uint32_t hh0, hh1;
        CVTBF2(hh0, f0, f1);
        CVTBF2(hh1, f2, f3);
        *(uint32_t*)&Ch[o0 + nt2 * 8] = hh0;
        *(uint32_t*)&Ch[o1 + nt2 * 8] = hh1;
        const float r0f = f0 - __uint_as_float(hh0 << 16);
        const float r1f = f1 - __uint_as_float(hh0 & 0xffff0000u);
        const float r2f = f2 - __uint_as_float(hh1 << 16);
        const float r3f = f3 - __uint_as_float(hh1 & 0xffff0000u);
        uint32_t ll0, ll1;
        CVTBF2(ll0, r0f, r1f);
        CVTBF2(ll1, r2f, r3f);
        *(uint32_t*)&Cl[o0 + nt2 * 8] = ll0;
        *(uint32_t*)&Cl[o1 + nt2 * 8] = ll1;
    }
}

// ---------------------------------------------------------------------------
// Launch (Wo transpose forked onto a side stream, joined before final GEMM)
// ---------------------------------------------------------------------------
extern "C" void kernel_launch(void* const* d_in, const int* in_sizes, int n_in,
                              void* d_out, int out_size)
{
    const float* x    = (const float*)d_in[0];
    const float* Wqkv = (const float*)d_in[1];
    const float* Wo   = (const float*)d_in[2];
    float* out = (float*)d_out;

    float *qkv, *rc, *rs;
    __nv_bfloat16 *xh, *xl, *wqh, *wql, *woh, *wol, *ch, *cl;
    __nv_bfloat16 *qh, *ql, *kh, *kl, *vth, *vtl;
    cudaGetSymbolAddress((void**)&qkv, g_qkv);
    cudaGetSymbolAddress((void**)&rc, g_rcos);
    cudaGetSymbolAddress((void**)&rs, g_rsin);
    cudaGetSymbolAddress((void**)&xh, g_xh);
    cudaGetSymbolAddress((void**)&xl, g_xl);
    cudaGetSymbolAddress((void**)&wqh, g_wqh);
    cudaGetSymbolAddress((void**)&wql, g_wql);
    cudaGetSymbolAddress((void**)&woh, g_woh);
    cudaGetSymbolAddress((void**)&wol, g_wol);
    cudaGetSymbolAddress((void**)&ch, g_ch);
    cudaGetSymbolAddress((void**)&cl, g_cl);
    cudaGetSymbolAddress((void**)&qh, g_qh);
    cudaGetSymbolAddress((void**)&ql, g_ql);
    cudaGetSymbolAddress((void**)&kh, g_kh);
    cudaGetSymbolAddress((void**)&kl, g_kl);
    cudaGetSymbolAddress((void**)&vth, g_vth);
    cudaGetSymbolAddress((void**)&vtl, g_vtl);

    cudaFuncSetAttribute(gemm_bf16x3mma,
                         cudaFuncAttributeMaxDynamicSharedMemorySize, GEMM_SMEM);
    cudaFuncSetAttribute(prep_qkv,
                         cudaFuncAttributeMaxDynamicSharedMemorySize, PREP_SMEM);
    cudaFuncSetAttribute(flash_mma,
                         cudaFuncAttributeMaxDynamicSharedMemorySize, FLASH_SMEM);

    // side stream + fork/join events (created once; no device allocations)
    static cudaStream_t s2 = nullptr;
    static cudaEvent_t e_fork = nullptr, e_join = nullptr;
    if (s2 == nullptr) {
        cudaStreamCreateWithFlags(&s2, cudaStreamNonBlocking);
        cudaEventCreateWithFlags(&e_fork, cudaEventDisableTiming);
        cudaEventCreateWithFlags(&e_join, cudaEventDisableTiming);
    }

    // fork: Wo transpose runs on s2, overlapped with the main pipeline
    cudaEventRecord(e_fork, 0);
    cudaStreamWaitEvent(s2, e_fork, 0);
    {
        dim3 grid(H_ / 32, H_ / 32), blk(32, 8);
        transpose_split<<<grid, blk, 0, s2>>>(Wo, woh, wol, H_, H_);
    }
    cudaEventRecord(e_join, s2);

    // main pipeline
    {
        const int n4 = (BS_ * H_) / 4;
        split_kernel<<<n4 / 256, 256>>>((const float4*)x, (uint2*)xh, (uint2*)xl, n4);
    }
    {
        dim3 grid(QKV_N / 32, H_ / 32), blk(32, 8);
        transpose_split<<<grid, blk>>>(Wqkv, wqh, wql, H_, QKV_N);
    }
    rope_tab<<<(S_ * 64) / 256, 256>>>(rc, rs);

    {
        dim3 grid(BS_ / 128, QKV_N / 256);
        gemm_bf16x3mma<<<grid, 256, GEMM_SMEM>>>(xh, xl, wqh, wql, qkv, QKV_N, H_);
    }
    {
        dim3 grid(S_ / 128, B_ * NH);
        prep_qkv<<<grid, 256, PREP_SMEM>>>(qkv, rc, rs, qh, ql, kh, kl, vth, vtl);
    }
    {
        dim3 grid(S_ / 128, B_ * NH);
        flash_mma<<<grid, 256, FLASH_SMEM>>>(qh, ql, kh, kl, vth, vtl, ch, cl);
    }

    // join: final GEMM needs woh/wol
    cudaStreamWaitEvent(0, e_join, 0);
    {
        dim3 grid(BS_ / 128, H_ / 256);
        gemm_bf16x3mma<<<grid, 256, GEMM_SMEM>>>(ch, cl, woh, wol, out, H_, H_);
    }
}

// round 13
// speedup vs baseline: 1.4078x; 1.3289x over previous
#include <cuda_runtime.h>
#include <cuda_fp16.h>
#include <math.h>
#include <stdint.h>

// Problem constants
#define B_ 2
#define S_ 2048
#define H_ 4096
#define NH 32
#define HD 128
#define BS_ (B_ * S_)          // 4096 rows
#define QKV_N (3 * H_)         // 12288

// ---------------------------------------------------------------------------
// Scratch (static device globals)
// ---------------------------------------------------------------------------
__device__ float g_qkv[(size_t)BS_ * QKV_N];
__device__ __half g_x16[(size_t)BS_ * H_];          // x fp16 (A single)
__device__ __half g_wqh[(size_t)QKV_N * H_];        // Wqkv^T hi
__device__ __half g_wql[(size_t)QKV_N * H_];        // Wqkv^T lo
__device__ __half g_woh[(size_t)H_ * H_];
__device__ __half g_wol[(size_t)H_ * H_];
__device__ __half g_c16[(size_t)BS_ * H_];          // ctx fp16 (A single)
__device__ __half g_q16[(size_t)BS_ * H_];          // Q single
__device__ __half g_kh[(size_t)BS_ * H_];
__device__ __half g_kl[(size_t)BS_ * H_];
__device__ __half g_vth[(size_t)BS_ * H_];          // V^T hi [BH,128,S]
__device__ __half g_vtl[(size_t)BS_ * H_];
__device__ float g_rcos[S_ * 64];
__device__ float g_rsin[S_ * 64];

// ---------------------------------------------------------------------------
// mma.sync + cp.async + ldmatrix helpers
// ---------------------------------------------------------------------------
__device__ __forceinline__ uint32_t smem_u32(const void* p) {
    uint32_t a;
    asm("{ .reg .u64 t; cvta.to.shared.u64 t, %1; cvt.u32.u64 %0, t; }"
        : "=r"(a) : "l"(p));
    return a;
}

#define CP_ASYNC16(dst, src) \
    asm volatile("cp.async.cg.shared.global [%0], [%1], 16;" \
                 :: "r"(dst), "l"(src) : "memory")
#define CP_COMMIT() asm volatile("cp.async.commit_group;" ::: "memory")
#define CP_WAIT1()  asm volatile("cp.async.wait_group 1;" ::: "memory")
#define CP_WAIT0()  asm volatile("cp.async.wait_group 0;" ::: "memory")

__device__ __forceinline__ void mma_f16(float* d, const uint32_t* a,
                                        uint32_t b0, uint32_t b1) {
    asm volatile(
        "mma.sync.aligned.m16n8k16.row.col.f32.f16.f16.f32 "
        "{%0,%1,%2,%3}, {%4,%5,%6,%7}, {%8,%9}, {%0,%1,%2,%3};"
        : "+f"(d[0]), "+f"(d[1]), "+f"(d[2]), "+f"(d[3])
        : "r"(a[0]), "r"(a[1]), "r"(a[2]), "r"(a[3]), "r"(b0), "r"(b1));
}

#define LDSM4(r0, r1, r2, r3, addr) \
    asm volatile("ldmatrix.sync.aligned.m8n8.x4.shared.b16 {%0,%1,%2,%3}, [%4];" \
                 : "=r"(r0), "=r"(r1), "=r"(r2), "=r"(r3) : "r"(addr))

// pack two f32 -> f16x2 (lo half = flo)
#define CVTH2(r, flo, fhi) \
    asm("cvt.rn.f16x2.f32 %0, %1, %2;" : "=r"(r) : "f"(fhi), "f"(flo))

// ---------------------------------------------------------------------------
// fp16x2 mma.sync GEMM:  C[M,N] = A * B^T  (A [M,K] single fp16, B [N,K] hi/lo)
// Tile 128x256, BK=64, 256 threads (8 warps; warp tile 64x64), 2-stage,
// ldmatrix loads.  C = A*Bh + A*Bl.
// ---------------------------------------------------------------------------
#define SA_STRIDE 144
#define OFF_A  0
#define OFF_BH (128 * SA_STRIDE)
#define OFF_BL (128 * SA_STRIDE + 256 * SA_STRIDE)
#define STAGE_BYTES (128 * SA_STRIDE + 2 * 256 * SA_STRIDE)   // 92160
#define GEMM_SMEM (2 * STAGE_BYTES)                           // 184320
#define MT_STEP (16 * SA_STRIDE)

__global__ __launch_bounds__(256, 1) void gemm_f16x2mma(
    const __half* __restrict__ A,
    const __half* __restrict__ Bh, const __half* __restrict__ Bl,
    float* __restrict__ C, int Nglob, int K)
{
    extern __shared__ char smem[];
    const int tid  = threadIdx.x;
    const int lane = tid & 31;
    const int wid  = tid >> 5;
    const int wm = wid & 1;
    const int wn = wid >> 1;
    const int bm = blockIdx.x * 128;
    const int bn = blockIdx.y * 256;

    const uint32_t sb = smem_u32(smem);
    const int nchunk = K >> 6;

    auto load_chunk = [&](int c, int s) {
        const int k0 = c << 6;
        const uint32_t st = sb + s * STAGE_BYTES;
        #pragma unroll
        for (int i = 0; i < 4; i++) {
            const int idx = tid + i * 256;          // 0..1023
            const int r = idx >> 3, seg = idx & 7;
            const size_t go = (size_t)(bm + r) * K + k0 + seg * 8;
            const uint32_t so = r * SA_STRIDE + seg * 16;
            CP_ASYNC16(st + OFF_A + so, A + go);
        }
        #pragma unroll
        for (int i = 0; i < 8; i++) {
            const int idx = tid + i * 256;          // 0..2047
            const int r = idx >> 3, seg = idx & 7;
            const size_t go = (size_t)(bn + r) * K + k0 + seg * 8;
            const uint32_t so = r * SA_STRIDE + seg * 16;
            CP_ASYNC16(st + OFF_BH + so, Bh + go);
            CP_ASYNC16(st + OFF_BL + so, Bl + go);
        }
        CP_COMMIT();
    };

    float acc[4][8][4];
    #pragma unroll
    for (int mt = 0; mt < 4; mt++)
        #pragma unroll
        for (int nt = 0; nt < 8; nt++)
            #pragma unroll
            for (int j = 0; j < 4; j++) acc[mt][nt][j] = 0.f;

    load_chunk(0, 0);
    if (nchunk > 1) load_chunk(1, 1);

    const int l7 = lane & 7, sel = lane >> 3;
    const uint32_t offA = (uint32_t)(wm * 64 + (sel & 1) * 8 + l7) * SA_STRIDE
                        + (uint32_t)(sel >> 1) * 16;
    const uint32_t offB = (uint32_t)(wn * 64 + (sel >> 1) * 8 + l7) * SA_STRIDE
                        + (uint32_t)(sel & 1) * 16;

    for (int c = 0; c < nchunk; c++) {
        if (c + 1 < nchunk) { CP_WAIT1(); } else { CP_WAIT0(); }
        __syncthreads();

        const uint32_t st = sb + (c & 1) * STAGE_BYTES;
        const uint32_t aA  = st + OFF_A  + offA;
        const uint32_t aBh = st + OFF_BH + offB;
        const uint32_t aBl = st + OFF_BL + offB;

        #pragma unroll
        for (int ks = 0; ks < 4; ks++) {
            const uint32_t cb = ks * 32;
            uint32_t ah[4][4];
            #pragma unroll
            for (int mt = 0; mt < 4; mt++)
                LDSM4(ah[mt][0], ah[mt][1], ah[mt][2], ah[mt][3],
                      aA + mt * MT_STEP + cb);
            uint32_t bhf[8][2];
            #pragma unroll
            for (int j = 0; j < 4; j++)
                LDSM4(bhf[2 * j][0], bhf[2 * j][1],
                      bhf[2 * j + 1][0], bhf[2 * j + 1][1],
                      aBh + j * MT_STEP + cb);
            #pragma unroll
            for (int nt = 0; nt < 8; nt++)
                #pragma unroll
                for (int mt = 0; mt < 4; mt++)
                    mma_f16(acc[mt][nt], ah[mt], bhf[nt][0], bhf[nt][1]);
            #pragma unroll
            for (int j = 0; j < 4; j++) {
                uint32_t bl00, bl01, bl10, bl11;
                LDSM4(bl00, bl01, bl10, bl11, aBl + j * MT_STEP + cb);
                #pragma unroll
                for (int mt = 0; mt < 4; mt++) {
                    mma_f16(acc[mt][2 * j],     ah[mt], bl00, bl01);
                    mma_f16(acc[mt][2 * j + 1], ah[mt], bl10, bl11);
                }
            }
        }
        __syncthreads();
        if (c + 2 < nchunk) load_chunk(c + 2, c & 1);
    }

    #pragma unroll
    for (int mt = 0; mt < 4; mt++) {
        const int row = bm + wm * 64 + mt * 16 + (lane >> 2);
        float* cp0 = C + (size_t)row * Nglob + bn + wn * 64 + (lane & 3) * 2;
        float* cp8 = cp0 + 8 * (size_t)Nglob;
        #pragma unroll
        for (int nt = 0; nt < 8; nt++) {
            *(float2*)(cp0 + nt * 8) = make_float2(acc[mt][nt][0], acc[mt][nt][1]);
            *(float2*)(cp8 + nt * 8) = make_float2(acc[mt][nt][2], acc[mt][nt][3]);
        }
    }
}

// ---------------------------------------------------------------------------
// Elementwise fp32 -> fp16 (single) conversion
// ---------------------------------------------------------------------------
__global__ void conv16_kernel(const float4* __restrict__ in,
                              uint2* __restrict__ o, int n4)
{
    const int i = blockIdx.x * blockDim.x + threadIdx.x;
    if (i >= n4) return;
    const float4 v = in[i];
    uint32_t a, b;
    CVTH2(a, v.x, v.y);
    CVTH2(b, v.z, v.w);
    uint2 r; r.x = a; r.y = b;
    o[i] = r;
}

// ---------------------------------------------------------------------------
// Transpose + split: W [K,N] fp32 -> Wt hi/lo [N,K] fp16
// ---------------------------------------------------------------------------
__global__ void transpose_split(const float* __restrict__ W,
                                __half* __restrict__ Th,
                                __half* __restrict__ Tl, int K, int N)
{
    __shared__ float t[32][33];
    const int tx = threadIdx.x, ty = threadIdx.y;
    const int nx = blockIdx.x * 32;
    const int ky = blockIdx.y * 32;
    #pragma unroll
    for (int j = 0; j < 32; j += 8)
        t[ty + j][tx] = W[(size_t)(ky + ty + j) * N + nx + tx];
    __syncthreads();
    #pragma unroll
    for (int j = 0; j < 32; j += 8) {
        const float v = t[tx][ty + j];
        const __half hi = __float2half(v);
        const __half lo = __float2half(v - __half2float(hi));
        const size_t o = (size_t)(nx + ty + j) * K + ky + tx;
        Th[o] = hi; Tl[o] = lo;
    }
}

// ---------------------------------------------------------------------------
// RoPE cos/sin tables
// ---------------------------------------------------------------------------
__global__ void rope_tab(float* __restrict__ c, float* __restrict__ s)
{
    const int i = blockIdx.x * blockDim.x + threadIdx.x;
    const int t = i >> 6, p = i & 63;
    const float inv_freq = powf(10000.0f, -(float)p * (1.0f / 64.0f));
    float sn, cs;
    sincosf((float)t * inv_freq, &sn, &cs);
    c[i] = cs; s[i] = sn;
}

// ---------------------------------------------------------------------------
// prep_qkv: RoPE + scale; Q single fp16, K hi/lo, V^T hi/lo.
// ---------------------------------------------------------------------------
#define PREP_SMEM (128 * 133 * 4)

__global__ __launch_bounds__(256, 1) void prep_qkv(
    const float* __restrict__ qkv,
    const float* __restrict__ rc, const float* __restrict__ rs,
    __half* __restrict__ Q16,
    __half* __restrict__ Kh, __half* __restrict__ Kl,
    __half* __restrict__ Vh, __half* __restrict__ Vl)
{
    extern __shared__ float ps[];
    const int tid = threadIdx.x;
    const int bh = blockIdx.y;
    const int b = bh >> 5, h = bh & 31;
    const int s0 = blockIdx.x * 128;
    const float scale = 0.08838834764831843f;

    #pragma unroll 4
    for (int i = 0; i < 32; i++) {
        const int idx = tid + i * 256;
        const int sr = idx >> 6, p = idx & 63;
        const int sg = s0 + sr;
        const size_t base = ((size_t)b * S_ + sg) * QKV_N + h * HD;
        const float cs = rc[sg * 64 + p], sn = rs[sg * 64 + p];
        const float q1 = qkv[base + p],        q2 = qkv[base + p + 64];
        const float k1 = qkv[base + H_ + p],   k2 = qkv[base + H_ + p + 64];
        const float qa = (q1 * cs - q2 * sn) * scale;
        const float qb = (q2 * cs + q1 * sn) * scale;
        const float ka = k1 * cs - k2 * sn;
        const float kb = k2 * cs + k1 * sn;
        const size_t ob = ((size_t)bh * S_ + sg) * HD;
        Q16[ob + p]      = __float2half(qa);
        Q16[ob + p + 64] = __float2half(qb);
        __half t;
        t = __float2half(ka); Kh[ob + p] = t;      Kl[ob + p]      = __float2half(ka - __half2float(t));
        t = __float2half(kb); Kh[ob + p + 64] = t; Kl[ob + p + 64] = __float2half(kb - __half2float(t));
    }

    #pragma unroll 4
    for (int i = 0; i < 64; i++) {
        const int idx = tid + i * 256;
        const int sr = idx >> 7, p = idx & 127;
        ps[sr * 133 + p] = qkv[((size_t)b * S_ + s0 + sr) * QKV_N + h * HD + 2 * H_ + p];
    }
    __syncthreads();
    #pragma unroll 4
    for (int i = 0; i < 64; i++) {
        const int idx = tid + i * 256;
        const int d = idx >> 7, sr = idx & 127;
        const float v = ps[sr * 133 + d];
        const __half hi = __float2half(v);
        const size_t o = ((size_t)bh * HD + d) * S_ + s0 + sr;
        Vh[o] = hi;
        Vl[o] = __float2half(v - __half2float(hi));
    }
}

// ---------------------------------------------------------------------------
// Flash attention, fp16x2: QK = Q*(Kh+Kl), PV = P*(Vh+Vl), P fp16-quantized.
// ---------------------------------------------------------------------------
#define FQ_LD 136
#define FV_LD 72
#define SQ_ELEMS (128 * FQ_LD)
#define SK_ELEMS (64 * FQ_LD)
#define SV_ELEMS (128 * FV_LD)
#define FSTAGE (2 * SK_ELEMS + 2 * SV_ELEMS)
#define FLASH_SMEM ((SQ_ELEMS + 2 * FSTAGE) * 2)   // 178176
#define KROW_STEP (16 * FQ_LD * 2)
#define VROW_STEP (16 * FV_LD * 2)

__global__ __launch_bounds__(256, 1) void flash_mma(
    const __half* __restrict__ Q16,
    const __half* __restrict__ Kh, const __half* __restrict__ Kl,
    const __half* __restrict__ Vh, const __half* __restrict__ Vl,
    __half* __restrict__ C16)
{
    extern __shared__ __half fs[];
    const int tid = threadIdx.x;
    const int lane = tid & 31;
    const int w = tid >> 5;
    const int qblk = gridDim.x - 1 - blockIdx.x;   // heavy-first
    const int bh = blockIdx.y;
    const int b = bh >> 5, h = bh & 31;
    const int q0 = qblk * 128;
    const uint32_t sb = smem_u32(fs);

    const size_t hoff = (size_t)bh * S_ * HD;
    const size_t voff = (size_t)bh * HD * S_;

    #pragma unroll
    for (int i = 0; i < 8; i++) {
        const int idx = tid + i * 256;
        const int r = idx >> 4, seg = idx & 15;
        const size_t go = hoff + (size_t)(q0 + r) * HD + seg * 8;
        const uint32_t so = (r * FQ_LD + seg * 8) * 2;
        CP_ASYNC16(sb + so, Q16 + go);
    }

    auto load_kv = [&](int t, int s) {
        const int k0 = t * 64;
        const uint32_t st = sb + (SQ_ELEMS + s * FSTAGE) * 2;
        #pragma unroll
        for (int i = 0; i < 4; i++) {
            const int idx = tid + i * 256;
            const int r = idx >> 4, seg = idx & 15;
            const size_t go = hoff + (size_t)(k0 + r) * HD + seg * 8;
            const uint32_t so = (r * FQ_LD + seg * 8) * 2;
            CP_ASYNC16(st + so, Kh + go);
            CP_ASYNC16(st + SK_ELEMS * 2 + so, Kl + go);
        }
        #pragma unroll
        for (int i = 0; i < 4; i++) {
            const int idx = tid + i * 256;
            const int r = idx >> 3, seg = idx & 7;
            const size_t go = voff + (size_t)r * S_ + k0 + seg * 8;
            const uint32_t so = (2 * SK_ELEMS + r * FV_LD + seg * 8) * 2;
            CP_ASYNC16(st + so, Vh + go);
            CP_ASYNC16(st + SV_ELEMS * 2 + so, Vl + go);
        }
        CP_COMMIT();
    };

    load_kv(0, 0);

    float O[16][4];
    #pragma unroll
    for (int i = 0; i < 16; i++)
        #pragma unroll
        for (int j = 0; j < 4; j++) O[i][j] = 0.f;
    float m0 = -1e30f, m1 = -1e30f, l0 = 0.f, l1 = 0.f;

    const int r0 = w * 16 + (lane >> 2);
    const int cq = (lane & 3) * 2;
    const int ntiles = 2 * qblk + 2;

    const int l7 = lane & 7, sel = lane >> 3;
    const uint32_t offQ = (uint32_t)(w * 16 + (sel & 1) * 8 + l7) * (FQ_LD * 2)
                        + (uint32_t)(sel >> 1) * 16;
    const uint32_t offK = (uint32_t)((sel >> 1) * 8 + l7) * (FQ_LD * 2)
                        + (uint32_t)(sel & 1) * 16;
    const uint32_t offV = (uint32_t)((sel >> 1) * 8 + l7) * (FV_LD * 2)
                        + (uint32_t)(sel & 1) * 16;

    const uint32_t aQ = sb + offQ;

    for (int t = 0; t < ntiles; t++) {
        if (t + 1 < ntiles) { load_kv(t + 1, (t + 1) & 1); CP_WAIT1(); }
        else                { CP_WAIT0(); }
        __syncthreads();

        const uint32_t stg = sb + (SQ_ELEMS + (t & 1) * FSTAGE) * 2;
        const uint32_t aKh = stg + offK;
        const uint32_t aKl = stg + SK_ELEMS * 2 + offK;
        const uint32_t aVh = stg + 2 * SK_ELEMS * 2 + offV;
        const uint32_t aVl = aVh + SV_ELEMS * 2;

        // ---- S = Q K^T (Q single, K hi+lo) ----
        float Sf[8][4];
        #pragma unroll
        for (int nt = 0; nt < 8; nt++)
            #pragma unroll
            for (int j = 0; j < 4; j++) Sf[nt][j] = 0.f;

        #pragma unroll
        for (int kk = 0; kk < 8; kk++) {
            const uint32_t cb = kk * 32;
            uint32_t ah[4];
            LDSM4(ah[0], ah[1], ah[2], ah[3], aQ + cb);
            uint32_t khf[8][2];
            #pragma unroll
            for (int j = 0; j < 4; j++)
                LDSM4(khf[2 * j][0], khf[2 * j][1],
                      khf[2 * j + 1][0], khf[2 * j + 1][1],
                      aKh + j * KROW_STEP + cb);
            #pragma unroll
            for (int nt = 0; nt < 8; nt++)
                mma_f16(Sf[nt], ah, khf[nt][0], khf[nt][1]);
            #pragma unroll
            for (int j = 0; j < 4; j++) {
                uint32_t kl00, kl01, kl10, kl11;
                LDSM4(kl00, kl01, kl10, kl11, aKl + j * KROW_STEP + cb);
                mma_f16(Sf[2 * j],     ah, kl00, kl01);
                mma_f16(Sf[2 * j + 1], ah, kl10, kl11);
            }
        }

        // ---- mask + online softmax ----
        const int k0 = t * 64;
        const int qg0 = q0 + r0, qg1 = qg0 + 8;
        if (k0 + 63 > q0 + w * 16) {
            #pragma unroll
            for (int nt = 0; nt < 8; nt++) {
                const int kv = k0 + nt * 8 + cq;
                if (kv     > qg0) Sf[nt][0] = -1e30f;
                if (kv + 1 > qg0) Sf[nt][1] = -1e30f;
                if (kv     > qg1) Sf[nt][2] = -1e30f;
                if (kv + 1 > qg1) Sf[nt][3] = -1e30f;
            }
        }
        float mx0 = -1e30f, mx1 = -1e30f;
        #pragma unroll
        for (int nt = 0; nt < 8; nt++) {
            mx0 = fmaxf(mx0, fmaxf(Sf[nt][0], Sf[nt][1]));
            mx1 = fmaxf(mx1, fmaxf(Sf[nt][2], Sf[nt][3]));
        }
        mx0 = fmaxf(mx0, __shfl_xor_sync(0xffffffffu, mx0, 1));
        mx0 = fmaxf(mx0, __shfl_xor_sync(0xffffffffu, mx0, 2));
        mx1 = fmaxf(mx1, __shfl_xor_sync(0xffffffffu, mx1, 1));
        mx1 = fmaxf(mx1, __shfl_xor_sync(0xffffffffu, mx1, 2));

        const float mn0 = fmaxf(m0, mx0), mn1 = fmaxf(m1, mx1);
        const float a0 = __expf(m0 - mn0), a1 = __expf(m1 - mn1);
        m0 = mn0; m1 = mn1;

        float s0 = 0.f, s1 = 0.f;
        uint32_t Ph[8][2];
        #pragma unroll
        for (int nt = 0; nt < 8; nt++) {
            const float p00 = __expf(Sf[nt][0] - mn0);
            const float p01 = __expf(Sf[nt][1] - mn0);
            const float p10 = __expf(Sf[nt][2] - mn1);
            const float p11 = __expf(Sf[nt][3] - mn1);
            s0 += p00 + p01; s1 += p10 + p11;
            CVTH2(Ph[nt][0], p00, p01);
            CVTH2(Ph[nt][1], p10, p11);
        }
        s0 += __shfl_xor_sync(0xffffffffu, s0, 1);
        s0 += __shfl_xor_sync(0xffffffffu, s0, 2);
        s1 += __shfl_xor_sync(0xffffffffu, s1, 1);
        s1 += __shfl_xor_sync(0xffffffffu, s1, 2);
        l0 = l0 * a0 + s0;
        l1 = l1 * a1 + s1;

        #pragma unroll
        for (int i = 0; i < 16; i++) {
            O[i][0] *= a0; O[i][1] *= a0; O[i][2] *= a1; O[i][3] *= a1;
        }

        // ---- O += P V (P single, V hi+lo) ----
        #pragma unroll
        for (int ks = 0; ks < 4; ks++) {
            const uint32_t cb = ks * 32;
            const uint32_t ah[4] = {Ph[2 * ks][0], Ph[2 * ks][1],
                                    Ph[2 * ks + 1][0], Ph[2 * ks + 1][1]};
            #pragma unroll
            for (int j = 0; j < 8; j++) {
                uint32_t v00, v01, v10, v11;
                LDSM4(v00, v01, v10, v11, aVh + j * VROW_STEP + cb);
                mma_f16(O[2 * j],     ah, v00, v01);
                mma_f16(O[2 * j + 1], ah, v10, v11);
            }
            #pragma unroll
            for (int j = 0; j < 8; j++) {
                uint32_t v00, v01, v10, v11;
                LDSM4(v00, v01, v10, v11, aVl + j * VROW_STEP + cb);
                mma_f16(O[2 * j],     ah, v00, v01);
                mma_f16(O[2 * j + 1], ah, v10, v11);
            }
        }
        __syncthreads();
    }

    // ---- epilogue: normalize, write single fp16 ctx ----
    const float inv0 = 1.f / l0, inv1 = 1.f / l1;
    const int row0 = q0 + w * 16 + (lane >> 2);
    const size_t o0 = ((size_t)b * S_ + row0) * H_ + h * HD + cq;
    const size_t o1 = o0 + 8 * (size_t)H_;
    #pragma unroll
    for (int nt2 = 0; nt2 < 16; nt2++) {
        uint32_t hh0, hh1;
        CVTH2(hh0, O[nt2][0] * inv0, O[nt2][1] * inv0);
        CVTH2(hh1, O[nt2][2] * inv1, O[nt2][3] * inv1);
        *(uint32_t*)&C16[o0 + nt2 * 8] = hh0;
        *(uint32_t*)&C16[o1 + nt2 * 8] = hh1;
    }
}

// ---------------------------------------------------------------------------
// Launch
// ---------------------------------------------------------------------------
extern "C" void kernel_launch(void* const* d_in, const int* in_sizes, int n_in,
                              void* d_out, int out_size)
{
    const float* x    = (const float*)d_in[0];
    const float* Wqkv = (const float*)d_in[1];
    const float* Wo   = (const float*)d_in[2];
    float* out = (float*)d_out;

    float *qkv, *rc, *rs;
    __half *x16, *wqh, *wql, *woh, *wol, *c16;
    __half *q16, *kh, *kl, *vth, *vtl;
    cudaGetSymbolAddress((void**)&qkv, g_qkv);
    cudaGetSymbolAddress((void**)&rc, g_rcos);
    cudaGetSymbolAddress((void**)&rs, g_rsin);
    cudaGetSymbolAddress((void**)&x16, g_x16);
    cudaGetSymbolAddress((void**)&wqh, g_wqh);
    cudaGetSymbolAddress((void**)&wql, g_wql);
    cudaGetSymbolAddress((void**)&woh, g_woh);
    cudaGetSymbolAddress((void**)&wol, g_wol);
    cudaGetSymbolAddress((void**)&c16, g_c16);
    cudaGetSymbolAddress((void**)&q16, g_q16);
    cudaGetSymbolAddress((void**)&kh, g_kh);
    cudaGetSymbolAddress((void**)&kl, g_kl);
    cudaGetSymbolAddress((void**)&vth, g_vth);
    cudaGetSymbolAddress((void**)&vtl, g_vtl);

    cudaFuncSetAttribute(gemm_f16x2mma,
                         cudaFuncAttributeMaxDynamicSharedMemorySize, GEMM_SMEM);
    cudaFuncSetAttribute(prep_qkv,
                         cudaFuncAttributeMaxDynamicSharedMemorySize, PREP_SMEM);
    cudaFuncSetAttribute(flash_mma,
                         cudaFuncAttributeMaxDynamicSharedMemorySize, FLASH_SMEM);

    // side stream + fork/join for Wo transpose overlap
    static cudaStream_t s2 = nullptr;
    static cudaEvent_t e_fork = nullptr, e_join = nullptr;
    if (s2 == nullptr) {
        cudaStreamCreateWithFlags(&s2, cudaStreamNonBlocking);
        cudaEventCreateWithFlags(&e_fork, cudaEventDisableTiming);
        cudaEventCreateWithFlags(&e_join, cudaEventDisableTiming);
    }

    cudaEventRecord(e_fork, 0);
    cudaStreamWaitEvent(s2, e_fork, 0);
    {
        dim3 grid(H_ / 32, H_ / 32), blk(32, 8);
        transpose_split<<<grid, blk, 0, s2>>>(Wo, woh, wol, H_, H_);
    }
    cudaEventRecord(e_join, s2);

    {
        const int n4 = (BS_ * H_) / 4;
        conv16_kernel<<<n4 / 256, 256>>>((const float4*)x, (uint2*)x16, n4);
    }
    {
        dim3 grid(QKV_N / 32, H_ / 32), blk(32, 8);
        transpose_split<<<grid, blk>>>(Wqkv, wqh, wql, H_, QKV_N);
    }
    rope_tab<<<(S_ * 64) / 256, 256>>>(rc, rs);

    {
        dim3 grid(BS_ / 128, QKV_N / 256);
        gemm_f16x2mma<<<grid, 256, GEMM_SMEM>>>(x16, wqh, wql, qkv, QKV_N, H_);
    }
    {
        dim3 grid(S_ / 128, B_ * NH);
        prep_qkv<<<grid, 256, PREP_SMEM>>>(qkv, rc, rs, q16, kh, kl, vth, vtl);
    }
    {
        dim3 grid(S_ / 128, B_ * NH);
        flash_mma<<<grid, 256, FLASH_SMEM>>>(q16, kh, kl, vth, vtl, c16);
    }

    cudaStreamWaitEvent(0, e_join, 0);
    {
        dim3 grid(BS_ / 128, H_ / 256);
        gemm_f16x2mma<<<grid, 256, GEMM_SMEM>>>(c16, woh, wol, out, H_, H_);
    }
}

// round 14
// speedup vs baseline: 1.4461x; 1.0271x over previous
#include <cuda_runtime.h>
#include <cuda_fp16.h>
#include <math.h>
#include <stdint.h>

// Problem constants
#define B_ 2
#define S_ 2048
#define H_ 4096
#define NH 32
#define HD 128
#define BS_ (B_ * S_)          // 4096 rows
#define QKV_N (3 * H_)         // 12288

// ---------------------------------------------------------------------------
// Scratch (static device globals)
// ---------------------------------------------------------------------------
__device__ float g_qkv[(size_t)BS_ * QKV_N];
__device__ __half g_x16[(size_t)BS_ * H_];          // x fp16 (A single)
__device__ __half g_wqh[(size_t)QKV_N * H_];        // Wqkv^T hi
__device__ __half g_wql[(size_t)QKV_N * H_];        // Wqkv^T lo
__device__ __half g_woh[(size_t)H_ * H_];
__device__ __half g_wol[(size_t)H_ * H_];
__device__ __half g_c16[(size_t)BS_ * H_];          // ctx fp16 (A single)
__device__ __half g_q16[(size_t)BS_ * H_];          // Q single
__device__ __half g_kh[(size_t)BS_ * H_];
__device__ __half g_kl[(size_t)BS_ * H_];
__device__ __half g_vt16[(size_t)BS_ * H_];         // V^T single [BH,128,S]
__device__ float g_rcos[S_ * 64];
__device__ float g_rsin[S_ * 64];

// ---------------------------------------------------------------------------
// mma.sync + cp.async + ldmatrix helpers
// ---------------------------------------------------------------------------
__device__ __forceinline__ uint32_t smem_u32(const void* p) {
    uint32_t a;
    asm("{ .reg .u64 t; cvta.to.shared.u64 t, %1; cvt.u32.u64 %0, t; }"
        : "=r"(a) : "l"(p));
    return a;
}

#define CP_ASYNC16(dst, src) \
    asm volatile("cp.async.cg.shared.global [%0], [%1], 16;" \
                 :: "r"(dst), "l"(src) : "memory")
#define CP_COMMIT() asm volatile("cp.async.commit_group;" ::: "memory")
#define CP_WAIT1()  asm volatile("cp.async.wait_group 1;" ::: "memory")
#define CP_WAIT0()  asm volatile("cp.async.wait_group 0;" ::: "memory")

__device__ __forceinline__ void mma_f16(float* d, const uint32_t* a,
                                        uint32_t b0, uint32_t b1) {
    asm volatile(
        "mma.sync.aligned.m16n8k16.row.col.f32.f16.f16.f32 "
        "{%0,%1,%2,%3}, {%4,%5,%6,%7}, {%8,%9}, {%0,%1,%2,%3};"
        : "+f"(d[0]), "+f"(d[1]), "+f"(d[2]), "+f"(d[3])
        : "r"(a[0]), "r"(a[1]), "r"(a[2]), "r"(a[3]), "r"(b0), "r"(b1));
}

#define LDSM4(r0, r1, r2, r3, addr) \
    asm volatile("ldmatrix.sync.aligned.m8n8.x4.shared.b16 {%0,%1,%2,%3}, [%4];" \
                 : "=r"(r0), "=r"(r1), "=r"(r2), "=r"(r3) : "r"(addr))

// pack two f32 -> f16x2 (lo half = flo)
#define CVTH2(r, flo, fhi) \
    asm("cvt.rn.f16x2.f32 %0, %1, %2;" : "=r"(r) : "f"(fhi), "f"(flo))

// ---------------------------------------------------------------------------
// fp16x2 mma.sync GEMM (unchanged from R13)
// ---------------------------------------------------------------------------
#define SA_STRIDE 144
#define OFF_A  0
#define OFF_BH (128 * SA_STRIDE)
#define OFF_BL (128 * SA_STRIDE + 256 * SA_STRIDE)
#define STAGE_BYTES (128 * SA_STRIDE + 2 * 256 * SA_STRIDE)   // 92160
#define GEMM_SMEM (2 * STAGE_BYTES)                           // 184320
#define MT_STEP (16 * SA_STRIDE)

__global__ __launch_bounds__(256, 1) void gemm_f16x2mma(
    const __half* __restrict__ A,
    const __half* __restrict__ Bh, const __half* __restrict__ Bl,
    float* __restrict__ C, int Nglob, int K)
{
    extern __shared__ char smem[];
    const int tid  = threadIdx.x;
    const int lane = tid & 31;
    const int wid  = tid >> 5;
    const int wm = wid & 1;
    const int wn = wid >> 1;
    const int bm = blockIdx.x * 128;
    const int bn = blockIdx.y * 256;

    const uint32_t sb = smem_u32(smem);
    const int nchunk = K >> 6;

    auto load_chunk = [&](int c, int s) {
        const int k0 = c << 6;
        const uint32_t st = sb + s * STAGE_BYTES;
        #pragma unroll
        for (int i = 0; i < 4; i++) {
            const int idx = tid + i * 256;
            const int r = idx >> 3, seg = idx & 7;
            const size_t go = (size_t)(bm + r) * K + k0 + seg * 8;
            const uint32_t so = r * SA_STRIDE + seg * 16;
            CP_ASYNC16(st + OFF_A + so, A + go);
        }
        #pragma unroll
        for (int i = 0; i < 8; i++) {
            const int idx = tid + i * 256;
            const int r = idx >> 3, seg = idx & 7;
            const size_t go = (size_t)(bn + r) * K + k0 + seg * 8;
            const uint32_t so = r * SA_STRIDE + seg * 16;
            CP_ASYNC16(st + OFF_BH + so, Bh + go);
            CP_ASYNC16(st + OFF_BL + so, Bl + go);
        }
        CP_COMMIT();
    };

    float acc[4][8][4];
    #pragma unroll
    for (int mt = 0; mt < 4; mt++)
        #pragma unroll
        for (int nt = 0; nt < 8; nt++)
            #pragma unroll
            for (int j = 0; j < 4; j++) acc[mt][nt][j] = 0.f;

    load_chunk(0, 0);
    if (nchunk > 1) load_chunk(1, 1);

    const int l7 = lane & 7, sel = lane >> 3;
    const uint32_t offA = (uint32_t)(wm * 64 + (sel & 1) * 8 + l7) * SA_STRIDE
                        + (uint32_t)(sel >> 1) * 16;
    const uint32_t offB = (uint32_t)(wn * 64 + (sel >> 1) * 8 + l7) * SA_STRIDE
                        + (uint32_t)(sel & 1) * 16;

    for (int c = 0; c < nchunk; c++) {
        if (c + 1 < nchunk) { CP_WAIT1(); } else { CP_WAIT0(); }
        __syncthreads();

        const uint32_t st = sb + (c & 1) * STAGE_BYTES;
        const uint32_t aA  = st + OFF_A  + offA;
        const uint32_t aBh = st + OFF_BH + offB;
        const uint32_t aBl = st + OFF_BL + offB;

        #pragma unroll
        for (int ks = 0; ks < 4; ks++) {
            const uint32_t cb = ks * 32;
            uint32_t ah[4][4];
            #pragma unroll
            for (int mt = 0; mt < 4; mt++)
                LDSM4(ah[mt][0], ah[mt][1], ah[mt][2], ah[mt][3],
                      aA + mt * MT_STEP + cb);
            uint32_t bhf[8][2];
            #pragma unroll
            for (int j = 0; j < 4; j++)
                LDSM4(bhf[2 * j][0], bhf[2 * j][1],
                      bhf[2 * j + 1][0], bhf[2 * j + 1][1],
                      aBh + j * MT_STEP + cb);
            #pragma unroll
            for (int nt = 0; nt < 8; nt++)
                #pragma unroll
                for (int mt = 0; mt < 4; mt++)
                    mma_f16(acc[mt][nt], ah[mt], bhf[nt][0], bhf[nt][1]);
            #pragma unroll
            for (int j = 0; j < 4; j++) {
                uint32_t bl00, bl01, bl10, bl11;
                LDSM4(bl00, bl01, bl10, bl11, aBl + j * MT_STEP + cb);
                #pragma unroll
                for (int mt = 0; mt < 4; mt++) {
                    mma_f16(acc[mt][2 * j],     ah[mt], bl00, bl01);
                    mma_f16(acc[mt][2 * j + 1], ah[mt], bl10, bl11);
                }
            }
        }
        __syncthreads();
        if (c + 2 < nchunk) load_chunk(c + 2, c & 1);
    }

    #pragma unroll
    for (int mt = 0; mt < 4; mt++) {
        const int row = bm + wm * 64 + mt * 16 + (lane >> 2);
        float* cp0 = C + (size_t)row * Nglob + bn + wn * 64 + (lane & 3) * 2;
        float* cp8 = cp0 + 8 * (size_t)Nglob;
        #pragma unroll
        for (int nt = 0; nt < 8; nt++) {
            *(float2*)(cp0 + nt * 8) = make_float2(acc[mt][nt][0], acc[mt][nt][1]);
            *(float2*)(cp8 + nt * 8) = make_float2(acc[mt][nt][2], acc[mt][nt][3]);
        }
    }
}

// ---------------------------------------------------------------------------
// Elementwise fp32 -> fp16 (single) conversion
// ---------------------------------------------------------------------------
__global__ void conv16_kernel(const float4* __restrict__ in,
                              uint2* __restrict__ o, int n4)
{
    const int i = blockIdx.x * blockDim.x + threadIdx.x;
    if (i >= n4) return;
    const float4 v = in[i];
    uint32_t a, b;
    CVTH2(a, v.x, v.y);
    CVTH2(b, v.z, v.w);
    uint2 r; r.x = a; r.y = b;
    o[i] = r;
}

// ---------------------------------------------------------------------------
// Transpose + split: W [K,N] fp32 -> Wt hi/lo [N,K] fp16
// ---------------------------------------------------------------------------
__global__ void transpose_split(const float* __restrict__ W,
                                __half* __restrict__ Th,
                                __half* __restrict__ Tl, int K, int N)
{
    __shared__ float t[32][33];
    const int tx = threadIdx.x, ty = threadIdx.y;
    const int nx = blockIdx.x * 32;
    const int ky = blockIdx.y * 32;
    #pragma unroll
    for (int j = 0; j < 32; j += 8)
        t[ty + j][tx] = W[(size_t)(ky + ty + j) * N + nx + tx];
    __syncthreads();
    #pragma unroll
    for (int j = 0; j < 32; j += 8) {
        const float v = t[tx][ty + j];
        const __half hi = __float2half(v);
        const __half lo = __float2half(v - __half2float(hi));
        const size_t o = (size_t)(nx + ty + j) * K + ky + tx;
        Th[o] = hi; Tl[o] = lo;
    }
}

// ---------------------------------------------------------------------------
// RoPE cos/sin tables
// ---------------------------------------------------------------------------
__global__ void rope_tab(float* __restrict__ c, float* __restrict__ s)
{
    const int i = blockIdx.x * blockDim.x + threadIdx.x;
    const int t = i >> 6, p = i & 63;
    const float inv_freq = powf(10000.0f, -(float)p * (1.0f / 64.0f));
    float sn, cs;
    sincosf((float)t * inv_freq, &sn, &cs);
    c[i] = cs; s[i] = sn;
}

// ---------------------------------------------------------------------------
// prep_qkv: RoPE + scale; Q single fp16, K hi/lo, V^T single.
// ---------------------------------------------------------------------------
#define PREP_SMEM (128 * 133 * 4)

__global__ __launch_bounds__(256, 1) void prep_qkv(
    const float* __restrict__ qkv,
    const float* __restrict__ rc, const float* __restrict__ rs,
    __half* __restrict__ Q16,
    __half* __restrict__ Kh, __half* __restrict__ Kl,
    __half* __restrict__ Vt)
{
    extern __shared__ float ps[];
    const int tid = threadIdx.x;
    const int bh = blockIdx.y;
    const int b = bh >> 5, h = bh & 31;
    const int s0 = blockIdx.x * 128;
    const float scale = 0.08838834764831843f;

    #pragma unroll 4
    for (int i = 0; i < 32; i++) {
        const int idx = tid + i * 256;
        const int sr = idx >> 6, p = idx & 63;
        const int sg = s0 + sr;
        const size_t base = ((size_t)b * S_ + sg) * QKV_N + h * HD;
        const float cs = rc[sg * 64 + p], sn = rs[sg * 64 + p];
        const float q1 = qkv[base + p],        q2 = qkv[base + p + 64];
        const float k1 = qkv[base + H_ + p],   k2 = qkv[base + H_ + p + 64];
        const float qa = (q1 * cs - q2 * sn) * scale;
        const float qb = (q2 * cs + q1 * sn) * scale;
        const float ka = k1 * cs - k2 * sn;
        const float kb = k2 * cs + k1 * sn;
        const size_t ob = ((size_t)bh * S_ + sg) * HD;
        Q16[ob + p]      = __float2half(qa);
        Q16[ob + p + 64] = __float2half(qb);
        __half t;
        t = __float2half(ka); Kh[ob + p] = t;      Kl[ob + p]      = __float2half(ka - __half2float(t));
        t = __float2half(kb); Kh[ob + p + 64] = t; Kl[ob + p + 64] = __float2half(kb - __half2float(t));
    }

    #pragma unroll 4
    for (int i = 0; i < 64; i++) {
        const int idx = tid + i * 256;
        const int sr = idx >> 7, p = idx & 127;
        ps[sr * 133 + p] = qkv[((size_t)b * S_ + s0 + sr) * QKV_N + h * HD + 2 * H_ + p];
    }
    __syncthreads();
    #pragma unroll 4
    for (int i = 0; i < 64; i++) {
        const int idx = tid + i * 256;
        const int d = idx >> 7, sr = idx & 127;
        Vt[((size_t)bh * HD + d) * S_ + s0 + sr] = __float2half(ps[sr * 133 + d]);
    }
}

// ---------------------------------------------------------------------------
// Flash attention, fp16: QK = Q*(Kh+Kl) (2 passes), PV = P*V (1 pass).
// ---------------------------------------------------------------------------
#define FQ_LD 136
#define FV_LD 72
#define SQ_ELEMS (128 * FQ_LD)
#define SK_ELEMS (64 * FQ_LD)
#define SV_ELEMS (128 * FV_LD)
#define FSTAGE (2 * SK_ELEMS + SV_ELEMS)
#define FLASH_SMEM ((SQ_ELEMS + 2 * FSTAGE) * 2)   // 141312
#define KROW_STEP (16 * FQ_LD * 2)
#define VROW_STEP (16 * FV_LD * 2)

__global__ __launch_bounds__(256, 1) void flash_mma(
    const __half* __restrict__ Q16,
    const __half* __restrict__ Kh, const __half* __restrict__ Kl,
    const __half* __restrict__ Vt,
    __half* __restrict__ C16)
{
    extern __shared__ __half fs[];
    const int tid = threadIdx.x;
    const int lane = tid & 31;
    const int w = tid >> 5;
    const int qblk = gridDim.x - 1 - blockIdx.x;   // heavy-first
    const int bh = blockIdx.y;
    const int b = bh >> 5, h = bh & 31;
    const int q0 = qblk * 128;
    const uint32_t sb = smem_u32(fs);

    const size_t hoff = (size_t)bh * S_ * HD;
    const size_t voff = (size_t)bh * HD * S_;

    #pragma unroll
    for (int i = 0; i < 8; i++) {
        const int idx = tid + i * 256;
        const int r = idx >> 4, seg = idx & 15;
        const size_t go = hoff + (size_t)(q0 + r) * HD + seg * 8;
        const uint32_t so = (r * FQ_LD + seg * 8) * 2;
        CP_ASYNC16(sb + so, Q16 + go);
    }

    auto load_kv = [&](int t, int s) {
        const int k0 = t * 64;
        const uint32_t st = sb + (SQ_ELEMS + s * FSTAGE) * 2;
        #pragma unroll
        for (int i = 0; i < 4; i++) {
            const int idx = tid + i * 256;
            const int r = idx >> 4, seg = idx & 15;
            const size_t go = hoff + (size_t)(k0 + r) * HD + seg * 8;
            const uint32_t so = (r * FQ_LD + seg * 8) * 2;
            CP_ASYNC16(st + so, Kh + go);
            CP_ASYNC16(st + SK_ELEMS * 2 + so, Kl + go);
        }
        #pragma unroll
        for (int i = 0; i < 4; i++) {
            const int idx = tid + i * 256;
            const int r = idx >> 3, seg = idx & 7;
            const size_t go = voff + (size_t)r * S_ + k0 + seg * 8;
            const uint32_t so = (2 * SK_ELEMS + r * FV_LD + seg * 8) * 2;
            CP_ASYNC16(st + so, Vt + go);
        }
        CP_COMMIT();
    };

    load_kv(0, 0);

    float O[16][4];
    #pragma unroll
    for (int i = 0; i < 16; i++)
        #pragma unroll
        for (int j = 0; j < 4; j++) O[i][j] = 0.f;
    float m0 = -1e30f, m1 = -1e30f, l0 = 0.f, l1 = 0.f;

    const int r0 = w * 16 + (lane >> 2);
    const int cq = (lane & 3) * 2;
    const int ntiles = 2 * qblk + 2;

    const int l7 = lane & 7, sel = lane >> 3;
    const uint32_t offQ = (uint32_t)(w * 16 + (sel & 1) * 8 + l7) * (FQ_LD * 2)
                        + (uint32_t)(sel >> 1) * 16;
    const uint32_t offK = (uint32_t)((sel >> 1) * 8 + l7) * (FQ_LD * 2)
                        + (uint32_t)(sel & 1) * 16;
    const uint32_t offV = (uint32_t)((sel >> 1) * 8 + l7) * (FV_LD * 2)
                        + (uint32_t)(sel & 1) * 16;

    const uint32_t aQ = sb + offQ;

    for (int t = 0; t < ntiles; t++) {
        if (t + 1 < ntiles) { load_kv(t + 1, (t + 1) & 1); CP_WAIT1(); }
        else                { CP_WAIT0(); }
        __syncthreads();

        const uint32_t stg = sb + (SQ_ELEMS + (t & 1) * FSTAGE) * 2;
        const uint32_t aKh = stg + offK;
        const uint32_t aKl = stg + SK_ELEMS * 2 + offK;
        const uint32_t aVh = stg + 2 * SK_ELEMS * 2 + offV;

        // ---- S = Q K^T (Q single, K hi+lo) ----
        float Sf[8][4];
        #pragma unroll
        for (int nt = 0; nt < 8; nt++)
            #pragma unroll
            for (int j = 0; j < 4; j++) Sf[nt][j] = 0.f;

        #pragma unroll
        for (int kk = 0; kk < 8; kk++) {
            const uint32_t cb = kk * 32;
            uint32_t ah[4];
            LDSM4(ah[0], ah[1], ah[2], ah[3], aQ + cb);
            uint32_t khf[8][2];
            #pragma unroll
            for (int j = 0; j < 4; j++)
                LDSM4(khf[2 * j][0], khf[2 * j][1],
                      khf[2 * j + 1][0], khf[2 * j + 1][1],
                      aKh + j * KROW_STEP + cb);
            #pragma unroll
            for (int nt = 0; nt < 8; nt++)
                mma_f16(Sf[nt], ah, khf[nt][0], khf[nt][1]);
            #pragma unroll
            for (int j = 0; j < 4; j++) {
                uint32_t kl00, kl01, kl10, kl11;
                LDSM4(kl00, kl01, kl10, kl11, aKl + j * KROW_STEP + cb);
                mma_f16(Sf[2 * j],     ah, kl00, kl01);
                mma_f16(Sf[2 * j + 1], ah, kl10, kl11);
            }
        }

        // ---- mask + online softmax ----
        const int k0 = t * 64;
        const int qg0 = q0 + r0, qg1 = qg0 + 8;
        if (k0 + 63 > q0 + w * 16) {
            #pragma unroll
            for (int nt = 0; nt < 8; nt++) {
                const int kv = k0 + nt * 8 + cq;
                if (kv     > qg0) Sf[nt][0] = -1e30f;
                if (kv + 1 > qg0) Sf[nt][1] = -1e30f;
                if (kv     > qg1) Sf[nt][2] = -1e30f;
                if (kv + 1 > qg1) Sf[nt][3] = -1e30f;
            }
        }
        float mx0 = -1e30f, mx1 = -1e30f;
        #pragma unroll
        for (int nt = 0; nt < 8; nt++) {
            mx0 = fmaxf(mx0, fmaxf(Sf[nt][0], Sf[nt][1]));
            mx1 = fmaxf(mx1, fmaxf(Sf[nt][2], Sf[nt][3]));
        }
        mx0 = fmaxf(mx0, __shfl_xor_sync(0xffffffffu, mx0, 1));
        mx0 = fmaxf(mx0, __shfl_xor_sync(0xffffffffu, mx0, 2));
        mx1 = fmaxf(mx1, __shfl_xor_sync(0xffffffffu, mx1, 1));
        mx1 = fmaxf(mx1, __shfl_xor_sync(0xffffffffu, mx1, 2));

        const float mn0 = fmaxf(m0, mx0), mn1 = fmaxf(m1, mx1);
        const float a0 = __expf(m0 - mn0), a1 = __expf(m1 - mn1);
        m0 = mn0; m1 = mn1;

        float s0 = 0.f, s1 = 0.f;
        uint32_t Ph[8][2];
        #pragma unroll
        for (int nt = 0; nt < 8; nt++) {
            const float p00 = __expf(Sf[nt][0] - mn0);
            const float p01 = __expf(Sf[nt][1] - mn0);
            const float p10 = __expf(Sf[nt][2] - mn1);
            const float p11 = __expf(Sf[nt][3] - mn1);
            s0 += p00 + p01; s1 += p10 + p11;
            CVTH2(Ph[nt][0], p00, p01);
            CVTH2(Ph[nt][1], p10, p11);
        }
        s0 += __shfl_xor_sync(0xffffffffu, s0, 1);
        s0 += __shfl_xor_sync(0xffffffffu, s0, 2);
        s1 += __shfl_xor_sync(0xffffffffu, s1, 1);
        s1 += __shfl_xor_sync(0xffffffffu, s1, 2);
        l0 = l0 * a0 + s0;
        l1 = l1 * a1 + s1;

        #pragma unroll
        for (int i = 0; i < 16; i++) {
            O[i][0] *= a0; O[i][1] *= a0; O[i][2] *= a1; O[i][3] *= a1;
        }

        // ---- O += P V (single pass) ----
        #pragma unroll
        for (int ks = 0; ks < 4; ks++) {
            const uint32_t cb = ks * 32;
            const uint32_t ah[4] = {Ph[2 * ks][0], Ph[2 * ks][1],
                                    Ph[2 * ks + 1][0], Ph[2 * ks + 1][1]};
            #pragma unroll
            for (int j = 0; j < 8; j++) {
                uint32_t v00, v01, v10, v11;
                LDSM4(v00, v01, v10, v11, aVh + j * VROW_STEP + cb);
                mma_f16(O[2 * j],     ah, v00, v01);
                mma_f16(O[2 * j + 1], ah, v10, v11);
            }
        }
        __syncthreads();
    }

    // ---- epilogue: normalize, write single fp16 ctx ----
    const float inv0 = 1.f / l0, inv1 = 1.f / l1;
    const int row0 = q0 + w * 16 + (lane >> 2);
    const size_t o0 = ((size_t)b * S_ + row0) * H_ + h * HD + cq;
    const size_t o1 = o0 + 8 * (size_t)H_;
    #pragma unroll
    for (int nt2 = 0; nt2 < 16; nt2++) {
        uint32_t hh0, hh1;
        CVTH2(hh0, O[nt2][0] * inv0, O[nt2][1] * inv0);
        CVTH2(hh1, O[nt2][2] * inv1, O[nt2][3] * inv1);
        *(uint32_t*)&C16[o0 + nt2 * 8] = hh0;
        *(uint32_t*)&C16[o1 + nt2 * 8] = hh1;
    }
}

// ---------------------------------------------------------------------------
// Launch
// ---------------------------------------------------------------------------
extern "C" void kernel_launch(void* const* d_in, const int* in_sizes, int n_in,
                              void* d_out, int out_size)
{
    const float* x    = (const float*)d_in[0];
    const float* Wqkv = (const float*)d_in[1];
    const float* Wo   = (const float*)d_in[2];
    float* out = (float*)d_out;

    float *qkv, *rc, *rs;
    __half *x16, *wqh, *wql, *woh, *wol, *c16;
    __half *q16, *kh, *kl, *vt16;
    cudaGetSymbolAddress((void**)&qkv, g_qkv);
    cudaGetSymbolAddress((void**)&rc, g_rcos);
    cudaGetSymbolAddress((void**)&rs, g_rsin);
    cudaGetSymbolAddress((void**)&x16, g_x16);
    cudaGetSymbolAddress((void**)&wqh, g_wqh);
    cudaGetSymbolAddress((void**)&wql, g_wql);
    cudaGetSymbolAddress((void**)&woh, g_woh);
    cudaGetSymbolAddress((void**)&wol, g_wol);
    cudaGetSymbolAddress((void**)&c16, g_c16);
    cudaGetSymbolAddress((void**)&q16, g_q16);
    cudaGetSymbolAddress((void**)&kh, g_kh);
    cudaGetSymbolAddress((void**)&kl, g_kl);
    cudaGetSymbolAddress((void**)&vt16, g_vt16);

    cudaFuncSetAttribute(gemm_f16x2mma,
                         cudaFuncAttributeMaxDynamicSharedMemorySize, GEMM_SMEM);
    cudaFuncSetAttribute(prep_qkv,
                         cudaFuncAttributeMaxDynamicSharedMemorySize, PREP_SMEM);
    cudaFuncSetAttribute(flash_mma,
                         cudaFuncAttributeMaxDynamicSharedMemorySize, FLASH_SMEM);

    // side stream + fork/join for Wo transpose overlap
    static cudaStream_t s2 = nullptr;
    static cudaEvent_t e_fork = nullptr, e_join = nullptr;
    if (s2 == nullptr) {
        cudaStreamCreateWithFlags(&s2, cudaStreamNonBlocking);
        cudaEventCreateWithFlags(&e_fork, cudaEventDisableTiming);
        cudaEventCreateWithFlags(&e_join, cudaEventDisableTiming);
    }

    cudaEventRecord(e_fork, 0);
    cudaStreamWaitEvent(s2, e_fork, 0);
    {
        dim3 grid(H_ / 32, H_ / 32), blk(32, 8);
        transpose_split<<<grid, blk, 0, s2>>>(Wo, woh, wol, H_, H_);
    }
    cudaEventRecord(e_join, s2);

    {
        const int n4 = (BS_ * H_) / 4;
        conv16_kernel<<<n4 / 256, 256>>>((const float4*)x, (uint2*)x16, n4);
    }
    {
        dim3 grid(QKV_N / 32, H_ / 32), blk(32, 8);
        transpose_split<<<grid, blk>>>(Wqkv, wqh, wql, H_, QKV_N);
    }
    rope_tab<<<(S_ * 64) / 256, 256>>>(rc, rs);

    {
        dim3 grid(BS_ / 128, QKV_N / 256);
        gemm_f16x2mma<<<grid, 256, GEMM_SMEM>>>(x16, wqh, wql, qkv, QKV_N, H_);
    }
    {
        dim3 grid(S_ / 128, B_ * NH);
        prep_qkv<<<grid, 256, PREP_SMEM>>>(qkv, rc, rs, q16, kh, kl, vt16);
    }
    {
        dim3 grid(S_ / 128, B_ * NH);
        flash_mma<<<grid, 256, FLASH_SMEM>>>(q16, kh, kl, vt16, c16);
    }

    cudaStreamWaitEvent(0, e_join, 0);
    {
        dim3 grid(BS_ / 128, H_ / 256);
        gemm_f16x2mma<<<grid, 256, GEMM_SMEM>>>(c16, woh, wol, out, H_, H_);
    }
}

// round 15
// speedup vs baseline: 2.3287x; 1.6104x over previous
#include <cuda_runtime.h>
#include <cuda_fp16.h>
#include <math.h>
#include <stdint.h>

// Problem constants
#define B_ 2
#define S_ 2048
#define H_ 4096
#define NH 32
#define HD 128
#define BS_ (B_ * S_)          // 4096 rows
#define QKV_N (3 * H_)         // 12288

// ---------------------------------------------------------------------------
// Scratch (static device globals)
// ---------------------------------------------------------------------------
__device__ float g_qkv[(size_t)BS_ * QKV_N];
__device__ __half g_x16[(size_t)BS_ * H_];          // x fp16
__device__ __half g_wq16[(size_t)QKV_N * H_];       // Wqkv^T fp16
__device__ __half g_wo16[(size_t)H_ * H_];          // Wo^T fp16
__device__ __half g_c16[(size_t)BS_ * H_];          // ctx fp16
__device__ __half g_q16[(size_t)BS_ * H_];          // Q single
__device__ __half g_kh[(size_t)BS_ * H_];
__device__ __half g_kl[(size_t)BS_ * H_];
__device__ __half g_vt16[(size_t)BS_ * H_];         // V^T single [BH,128,S]
__device__ float g_rcos[S_ * 64];
__device__ float g_rsin[S_ * 64];

// ---------------------------------------------------------------------------
// mma.sync + cp.async + ldmatrix helpers
// ---------------------------------------------------------------------------
__device__ __forceinline__ uint32_t smem_u32(const void* p) {
    uint32_t a;
    asm("{ .reg .u64 t; cvta.to.shared.u64 t, %1; cvt.u32.u64 %0, t; }"
        : "=r"(a) : "l"(p));
    return a;
}

#define CP_ASYNC16(dst, src) \
    asm volatile("cp.async.cg.shared.global [%0], [%1], 16;" \
                 :: "r"(dst), "l"(src) : "memory")
#define CP_COMMIT() asm volatile("cp.async.commit_group;" ::: "memory")
#define CP_WAIT1()  asm volatile("cp.async.wait_group 1;" ::: "memory")
#define CP_WAIT0()  asm volatile("cp.async.wait_group 0;" ::: "memory")

__device__ __forceinline__ void mma_f16(float* d, const uint32_t* a,
                                        uint32_t b0, uint32_t b1) {
    asm volatile(
        "mma.sync.aligned.m16n8k16.row.col.f32.f16.f16.f32 "
        "{%0,%1,%2,%3}, {%4,%5,%6,%7}, {%8,%9}, {%0,%1,%2,%3};"
        : "+f"(d[0]), "+f"(d[1]), "+f"(d[2]), "+f"(d[3])
        : "r"(a[0]), "r"(a[1]), "r"(a[2]), "r"(a[3]), "r"(b0), "r"(b1));
}

#define LDSM4(r0, r1, r2, r3, addr) \
    asm volatile("ldmatrix.sync.aligned.m8n8.x4.shared.b16 {%0,%1,%2,%3}, [%4];" \
                 : "=r"(r0), "=r"(r1), "=r"(r2), "=r"(r3) : "r"(addr))

// pack two f32 -> f16x2 (lo half = flo)
#define CVTH2(r, flo, fhi) \
    asm("cvt.rn.f16x2.f32 %0, %1, %2;" : "=r"(r) : "f"(fhi), "f"(flo))

// ---------------------------------------------------------------------------
// fp16 single x single mma.sync GEMM:  C[M,N] = A * B^T
// Tile 128x256, BK=64, 256 threads (8 warps; warp tile 64x64), 2-stage,
// ldmatrix loads.
// ---------------------------------------------------------------------------
#define SA_STRIDE 144
#define OFF_A  0
#define OFF_B  (128 * SA_STRIDE)
#define STAGE_BYTES (128 * SA_STRIDE + 256 * SA_STRIDE)   // 55296
#define GEMM_SMEM (2 * STAGE_BYTES)                       // 110592
#define MT_STEP (16 * SA_STRIDE)

__global__ __launch_bounds__(256, 1) void gemm_f16mma(
    const __half* __restrict__ A, const __half* __restrict__ B,
    float* __restrict__ C, int Nglob, int K)
{
    extern __shared__ char smem[];
    const int tid  = threadIdx.x;
    const int lane = tid & 31;
    const int wid  = tid >> 5;
    const int wm = wid & 1;
    const int wn = wid >> 1;
    const int bm = blockIdx.x * 128;
    const int bn = blockIdx.y * 256;

    const uint32_t sb = smem_u32(smem);
    const int nchunk = K >> 6;

    auto load_chunk = [&](int c, int s) {
        const int k0 = c << 6;
        const uint32_t st = sb + s * STAGE_BYTES;
        #pragma unroll
        for (int i = 0; i < 4; i++) {
            const int idx = tid + i * 256;          // 0..1023
            const int r = idx >> 3, seg = idx & 7;
            const size_t go = (size_t)(bm + r) * K + k0 + seg * 8;
            const uint32_t so = r * SA_STRIDE + seg * 16;
            CP_ASYNC16(st + OFF_A + so, A + go);
        }
        #pragma unroll
        for (int i = 0; i < 8; i++) {
            const int idx = tid + i * 256;          // 0..2047
            const int r = idx >> 3, seg = idx & 7;
            const size_t go = (size_t)(bn + r) * K + k0 + seg * 8;
            const uint32_t so = r * SA_STRIDE + seg * 16;
            CP_ASYNC16(st + OFF_B + so, B + go);
        }
        CP_COMMIT();
    };

    float acc[4][8][4];
    #pragma unroll
    for (int mt = 0; mt < 4; mt++)
        #pragma unroll
        for (int nt = 0; nt < 8; nt++)
            #pragma unroll
            for (int j = 0; j < 4; j++) acc[mt][nt][j] = 0.f;

    load_chunk(0, 0);
    if (nchunk > 1) load_chunk(1, 1);

    const int l7 = lane & 7, sel = lane >> 3;
    const uint32_t offA = (uint32_t)(wm * 64 + (sel & 1) * 8 + l7) * SA_STRIDE
                        + (uint32_t)(sel >> 1) * 16;
    const uint32_t offB = (uint32_t)(wn * 64 + (sel >> 1) * 8 + l7) * SA_STRIDE
                        + (uint32_t)(sel & 1) * 16;

    for (int c = 0; c < nchunk; c++) {
        if (c + 1 < nchunk) { CP_WAIT1(); } else { CP_WAIT0(); }
        __syncthreads();

        const uint32_t st = sb + (c & 1) * STAGE_BYTES;
        const uint32_t aA = st + OFF_A + offA;
        const uint32_t aB = st + OFF_B + offB;

        #pragma unroll
        for (int ks = 0; ks < 4; ks++) {
            const uint32_t cb = ks * 32;
            uint32_t ah[4][4];
            #pragma unroll
            for (int mt = 0; mt < 4; mt++)
                LDSM4(ah[mt][0], ah[mt][1], ah[mt][2], ah[mt][3],
                      aA + mt * MT_STEP + cb);
            uint32_t bf[8][2];
            #pragma unroll
            for (int j = 0; j < 4; j++)
                LDSM4(bf[2 * j][0], bf[2 * j][1],
                      bf[2 * j + 1][0], bf[2 * j + 1][1],
                      aB + j * MT_STEP + cb);
            #pragma unroll
            for (int nt = 0; nt < 8; nt++)
                #pragma unroll
                for (int mt = 0; mt < 4; mt++)
                    mma_f16(acc[mt][nt], ah[mt], bf[nt][0], bf[nt][1]);
        }
        __syncthreads();
        if (c + 2 < nchunk) load_chunk(c + 2, c & 1);
    }

    #pragma unroll
    for (int mt = 0; mt < 4; mt++) {
        const int row = bm + wm * 64 + mt * 16 + (lane >> 2);
        float* cp0 = C + (size_t)row * Nglob + bn + wn * 64 + (lane & 3) * 2;
        float* cp8 = cp0 + 8 * (size_t)Nglob;
        #pragma unroll
        for (int nt = 0; nt < 8; nt++) {
            *(float2*)(cp0 + nt * 8) = make_float2(acc[mt][nt][0], acc[mt][nt][1]);
            *(float2*)(cp8 + nt * 8) = make_float2(acc[mt][nt][2], acc[mt][nt][3]);
        }
    }
}

// ---------------------------------------------------------------------------
// Elementwise fp32 -> fp16 conversion
// ---------------------------------------------------------------------------
__global__ void conv16_kernel(const float4* __restrict__ in,
                              uint2* __restrict__ o, int n4)
{
    const int i = blockIdx.x * blockDim.x + threadIdx.x;
    if (i >= n4) return;
    const float4 v = in[i];
    uint32_t a, b;
    CVTH2(a, v.x, v.y);
    CVTH2(b, v.z, v.w);
    uint2 r; r.x = a; r.y = b;
    o[i] = r;
}

// ---------------------------------------------------------------------------
// Transpose: W [K,N] fp32 -> Wt [N,K] fp16 single
// ---------------------------------------------------------------------------
__global__ void transpose16(const float* __restrict__ W,
                            __half* __restrict__ T, int K, int N)
{
    __shared__ float t[32][33];
    const int tx = threadIdx.x, ty = threadIdx.y;
    const int nx = blockIdx.x * 32;
    const int ky = blockIdx.y * 32;
    #pragma unroll
    for (int j = 0; j < 32; j += 8)
        t[ty + j][tx] = W[(size_t)(ky + ty + j) * N + nx + tx];
    __syncthreads();
    #pragma unroll
    for (int j = 0; j < 32; j += 8)
        T[(size_t)(nx + ty + j) * K + ky + tx] = __float2half(t[tx][ty + j]);
}

// ---------------------------------------------------------------------------
// RoPE cos/sin tables
// ---------------------------------------------------------------------------
__global__ void rope_tab(float* __restrict__ c, float* __restrict__ s)
{
    const int i = blockIdx.x * blockDim.x + threadIdx.x;
    const int t = i >> 6, p = i & 63;
    const float inv_freq = powf(10000.0f, -(float)p * (1.0f / 64.0f));
    float sn, cs;
    sincosf((float)t * inv_freq, &sn, &cs);
    c[i] = cs; s[i] = sn;
}

// ---------------------------------------------------------------------------
// prep_qkv: RoPE + scale; Q single fp16, K hi/lo, V^T single.
// ---------------------------------------------------------------------------
#define PREP_SMEM (128 * 133 * 4)

__global__ __launch_bounds__(256, 1) void prep_qkv(
    const float* __restrict__ qkv,
    const float* __restrict__ rc, const float* __restrict__ rs,
    __half* __restrict__ Q16,
    __half* __restrict__ Kh, __half* __restrict__ Kl,
    __half* __restrict__ Vt)
{
    extern __shared__ float ps[];
    const int tid = threadIdx.x;
    const int bh = blockIdx.y;
    const int b = bh >> 5, h = bh & 31;
    const int s0 = blockIdx.x * 128;
    const float scale = 0.08838834764831843f;

    #pragma unroll 4
    for (int i = 0; i < 32; i++) {
        const int idx = tid + i * 256;
        const int sr = idx >> 6, p = idx & 63;
        const int sg = s0 + sr;
        const size_t base = ((size_t)b * S_ + sg) * QKV_N + h * HD;
        const float cs = rc[sg * 64 + p], sn = rs[sg * 64 + p];
        const float q1 = qkv[base + p],        q2 = qkv[base + p + 64];
        const float k1 = qkv[base + H_ + p],   k2 = qkv[base + H_ + p + 64];
        const float qa = (q1 * cs - q2 * sn) * scale;
        const float qb = (q2 * cs + q1 * sn) * scale;
        const float ka = k1 * cs - k2 * sn;
        const float kb = k2 * cs + k1 * sn;
        const size_t ob = ((size_t)bh * S_ + sg) * HD;
        Q16[ob + p]      = __float2half(qa);
        Q16[ob + p + 64] = __float2half(qb);
        __half t;
        t = __float2half(ka); Kh[ob + p] = t;      Kl[ob + p]      = __float2half(ka - __half2float(t));
        t = __float2half(kb); Kh[ob + p + 64] = t; Kl[ob + p + 64] = __float2half(kb - __half2float(t));
    }

    #pragma unroll 4
    for (int i = 0; i < 64; i++) {
        const int idx = tid + i * 256;
        const int sr = idx >> 7, p = idx & 127;
        ps[sr * 133 + p] = qkv[((size_t)b * S_ + s0 + sr) * QKV_N + h * HD + 2 * H_ + p];
    }
    __syncthreads();
    #pragma unroll 4
    for (int i = 0; i < 64; i++) {
        const int idx = tid + i * 256;
        const int d = idx >> 7, sr = idx & 127;
        Vt[((size_t)bh * HD + d) * S_ + s0 + sr] = __float2half(ps[sr * 133 + d]);
    }
}

// ---------------------------------------------------------------------------
// Flash attention (unchanged from R14): QK = Q*(Kh+Kl), PV = P*V.
// ---------------------------------------------------------------------------
#define FQ_LD 136
#define FV_LD 72
#define SQ_ELEMS (128 * FQ_LD)
#define SK_ELEMS (64 * FQ_LD)
#define SV_ELEMS (128 * FV_LD)
#define FSTAGE (2 * SK_ELEMS + SV_ELEMS)
#define FLASH_SMEM ((SQ_ELEMS + 2 * FSTAGE) * 2)
#define KROW_STEP (16 * FQ_LD * 2)
#define VROW_STEP (16 * FV_LD * 2)

__global__ __launch_bounds__(256, 1) void flash_mma(
    const __half* __restrict__ Q16,
    const __half* __restrict__ Kh, const __half* __restrict__ Kl,
    const __half* __restrict__ Vt,
    __half* __restrict__ C16)
{
    extern __shared__ __half fs[];
    const int tid = threadIdx.x;
    const int lane = tid & 31;
    const int w = tid >> 5;
    const int qblk = gridDim.x - 1 - blockIdx.x;
    const int bh = blockIdx.y;
    const int b = bh >> 5, h = bh & 31;
    const int q0 = qblk * 128;
    const uint32_t sb = smem_u32(fs);

    const size_t hoff = (size_t)bh * S_ * HD;
    const size_t voff = (size_t)bh * HD * S_;

    #pragma unroll
    for (int i = 0; i < 8; i++) {
        const int idx = tid + i * 256;
        const int r = idx >> 4, seg = idx & 15;
        const size_t go = hoff + (size_t)(q0 + r) * HD + seg * 8;
        const uint32_t so = (r * FQ_LD + seg * 8) * 2;
        CP_ASYNC16(sb + so, Q16 + go);
    }

    auto load_kv = [&](int t, int s) {
        const int k0 = t * 64;
        const uint32_t st = sb + (SQ_ELEMS + s * FSTAGE) * 2;
        #pragma unroll
        for (int i = 0; i < 4; i++) {
            const int idx = tid + i * 256;
            const int r = idx >> 4, seg = idx & 15;
            const size_t go = hoff + (size_t)(k0 + r) * HD + seg * 8;
            const uint32_t so = (r * FQ_LD + seg * 8) * 2;
            CP_ASYNC16(st + so, Kh + go);
            CP_ASYNC16(st + SK_ELEMS * 2 + so, Kl + go);
        }
        #pragma unroll
        for (int i = 0; i < 4; i++) {
            const int idx = tid + i * 256;
            const int r = idx >> 3, seg = idx & 7;
            const size_t go = voff + (size_t)r * S_ + k0 + seg * 8;
            const uint32_t so = (2 * SK_ELEMS + r * FV_LD + seg * 8) * 2;
            CP_ASYNC16(st + so, Vt + go);
        }
        CP_COMMIT();
    };

    load_kv(0, 0);

    float O[16][4];
    #pragma unroll
    for (int i = 0; i < 16; i++)
        #pragma unroll
        for (int j = 0; j < 4; j++) O[i][j] = 0.f;
    float m0 = -1e30f, m1 = -1e30f, l0 = 0.f, l1 = 0.f;

    const int r0 = w * 16 + (lane >> 2);
    const int cq = (lane & 3) * 2;
    const int ntiles = 2 * qblk + 2;

    const int l7 = lane & 7, sel = lane >> 3;
    const uint32_t offQ = (uint32_t)(w * 16 + (sel & 1) * 8 + l7) * (FQ_LD * 2)
                        + (uint32_t)(sel >> 1) * 16;
    const uint32_t offK = (uint32_t)((sel >> 1) * 8 + l7) * (FQ_LD * 2)
                        + (uint32_t)(sel & 1) * 16;
    const uint32_t offV = (uint32_t)((sel >> 1) * 8 + l7) * (FV_LD * 2)
                        + (uint32_t)(sel & 1) * 16;

    const uint32_t aQ = sb + offQ;

    for (int t = 0; t < ntiles; t++) {
        if (t + 1 < ntiles) { load_kv(t + 1, (t + 1) & 1); CP_WAIT1(); }
        else                { CP_WAIT0(); }
        __syncthreads();

        const uint32_t stg = sb + (SQ_ELEMS + (t & 1) * FSTAGE) * 2;
        const uint32_t aKh = stg + offK;
        const uint32_t aKl = stg + SK_ELEMS * 2 + offK;
        const uint32_t aVh = stg + 2 * SK_ELEMS * 2 + offV;

        float Sf[8][4];
        #pragma unroll
        for (int nt = 0; nt < 8; nt++)
            #pragma unroll
            for (int j = 0; j < 4; j++) Sf[nt][j] = 0.f;

        #pragma unroll
        for (int kk = 0; kk < 8; kk++) {
            const uint32_t cb = kk * 32;
            uint32_t ah[4];
            LDSM4(ah[0], ah[1], ah[2], ah[3], aQ + cb);
            uint32_t khf[8][2];
            #pragma unroll
            for (int j = 0; j < 4; j++)
                LDSM4(khf[2 * j][0], khf[2 * j][1],
                      khf[2 * j + 1][0], khf[2 * j + 1][1],
                      aKh + j * KROW_STEP + cb);
            #pragma unroll
            for (int nt = 0; nt < 8; nt++)
                mma_f16(Sf[nt], ah, khf[nt][0], khf[nt][1]);
            #pragma unroll
            for (int j = 0; j < 4; j++) {
                uint32_t kl00, kl01, kl10, kl11;
                LDSM4(kl00, kl01, kl10, kl11, aKl + j * KROW_STEP + cb);
                mma_f16(Sf[2 * j],     ah, kl00, kl01);
                mma_f16(Sf[2 * j + 1], ah, kl10, kl11);
            }
        }

        const int k0 = t * 64;
        const int qg0 = q0 + r0, qg1 = qg0 + 8;
        if (k0 + 63 > q0 + w * 16) {
            #pragma unroll
            for (int nt = 0; nt < 8; nt++) {
                const int kv = k0 + nt * 8 + cq;
                if (kv     > qg0) Sf[nt][0] = -1e30f;
                if (kv + 1 > qg0) Sf[nt][1] = -1e30f;
                if (kv     > qg1) Sf[nt][2] = -1e30f;
                if (kv + 1 > qg1) Sf[nt][3] = -1e30f;
            }
        }
        float mx0 = -1e30f, mx1 = -1e30f;
        #pragma unroll
        for (int nt = 0; nt < 8; nt++) {
            mx0 = fmaxf(mx0, fmaxf(Sf[nt][0], Sf[nt][1]));
            mx1 = fmaxf(mx1, fmaxf(Sf[nt][2], Sf[nt][3]));
        }
        mx0 = fmaxf(mx0, __shfl_xor_sync(0xffffffffu, mx0, 1));
        mx0 = fmaxf(mx0, __shfl_xor_sync(0xffffffffu, mx0, 2));
        mx1 = fmaxf(mx1, __shfl_xor_sync(0xffffffffu, mx1, 1));
        mx1 = fmaxf(mx1, __shfl_xor_sync(0xffffffffu, mx1, 2));

        const float mn0 = fmaxf(m0, mx0), mn1 = fmaxf(m1, mx1);
        const float a0 = __expf(m0 - mn0), a1 = __expf(m1 - mn1);
        m0 = mn0; m1 = mn1;

        float s0 = 0.f, s1 = 0.f;
        uint32_t Ph[8][2];
        #pragma unroll
        for (int nt = 0; nt < 8; nt++) {
            const float p00 = __expf(Sf[nt][0] - mn0);
            const float p01 = __expf(Sf[nt][1] - mn0);
            const float p10 = __expf(Sf[nt][2] - mn1);
            const float p11 = __expf(Sf[nt][3] - mn1);
            s0 += p00 + p01; s1 += p10 + p11;
            CVTH2(Ph[nt][0], p00, p01);
            CVTH2(Ph[nt][1], p10, p11);
        }
        s0 += __shfl_xor_sync(0xffffffffu, s0, 1);
        s0 += __shfl_xor_sync(0xffffffffu, s0, 2);
        s1 += __shfl_xor_sync(0xffffffffu, s1, 1);
        s1 += __shfl_xor_sync(0xffffffffu, s1, 2);
        l0 = l0 * a0 + s0;
        l1 = l1 * a1 + s1;

        #pragma unroll
        for (int i = 0; i < 16; i++) {
            O[i][0] *= a0; O[i][1] *= a0; O[i][2] *= a1; O[i][3] *= a1;
        }

        #pragma unroll
        for (int ks = 0; ks < 4; ks++) {
            const uint32_t cb = ks * 32;
            const uint32_t ah[4] = {Ph[2 * ks][0], Ph[2 * ks][1],
                                    Ph[2 * ks + 1][0], Ph[2 * ks + 1][1]};
            #pragma unroll
            for (int j = 0; j < 8; j++) {
                uint32_t v00, v01, v10, v11;
                LDSM4(v00, v01, v10, v11, aVh + j * VROW_STEP + cb);
                mma_f16(O[2 * j],     ah, v00, v01);
                mma_f16(O[2 * j + 1], ah, v10, v11);
            }
        }
        __syncthreads();
    }

    const float inv0 = 1.f / l0, inv1 = 1.f / l1;
    const int row0 = q0 + w * 16 + (lane >> 2);
    const size_t o0 = ((size_t)b * S_ + row0) * H_ + h * HD + cq;
    const size_t o1 = o0 + 8 * (size_t)H_;
    #pragma unroll
    for (int nt2 = 0; nt2 < 16; nt2++) {
        uint32_t hh0, hh1;
        CVTH2(hh0, O[nt2][0] * inv0, O[nt2][1] * inv0);
        CVTH2(hh1, O[nt2][2] * inv1, O[nt2][3] * inv1);
        *(uint32_t*)&C16[o0 + nt2 * 8] = hh0;
        *(uint32_t*)&C16[o1 + nt2 * 8] = hh1;
    }
}

// ---------------------------------------------------------------------------
// Launch
// ---------------------------------------------------------------------------
extern "C" void kernel_launch(void* const* d_in, const int* in_sizes, int n_in,
                              void* d_out, int out_size)
{
    const float* x    = (const float*)d_in[0];
    const float* Wqkv = (const float*)d_in[1];
    const float* Wo   = (const float*)d_in[2];
    float* out = (float*)d_out;

    float *qkv, *rc, *rs;
    __half *x16, *wq16, *wo16, *c16;
    __half *q16, *kh, *kl, *vt16;
    cudaGetSymbolAddress((void**)&qkv, g_qkv);
    cudaGetSymbolAddress((void**)&rc, g_rcos);
    cudaGetSymbolAddress((void**)&rs, g_rsin);
    cudaGetSymbolAddress((void**)&x16, g_x16);
    cudaGetSymbolAddress((void**)&wq16, g_wq16);
    cudaGetSymbolAddress((void**)&wo16, g_wo16);
    cudaGetSymbolAddress((void**)&c16, g_c16);
    cudaGetSymbolAddress((void**)&q16, g_q16);
    cudaGetSymbolAddress((void**)&kh, g_kh);
    cudaGetSymbolAddress((void**)&kl, g_kl);
    cudaGetSymbolAddress((void**)&vt16, g_vt16);

    cudaFuncSetAttribute(gemm_f16mma,
                         cudaFuncAttributeMaxDynamicSharedMemorySize, GEMM_SMEM);
    cudaFuncSetAttribute(prep_qkv,
                         cudaFuncAttributeMaxDynamicSharedMemorySize, PREP_SMEM);
    cudaFuncSetAttribute(flash_mma,
                         cudaFuncAttributeMaxDynamicSharedMemorySize, FLASH_SMEM);

    // side stream + fork/join for Wo transpose overlap
    static cudaStream_t s2 = nullptr;
    static cudaEvent_t e_fork = nullptr, e_join = nullptr;
    if (s2 == nullptr) {
        cudaStreamCreateWithFlags(&s2, cudaStreamNonBlocking);
        cudaEventCreateWithFlags(&e_fork, cudaEventDisableTiming);
        cudaEventCreateWithFlags(&e_join, cudaEventDisableTiming);
    }

    cudaEventRecord(e_fork, 0);
    cudaStreamWaitEvent(s2, e_fork, 0);
    {
        dim3 grid(H_ / 32, H_ / 32), blk(32, 8);
        transpose16<<<grid, blk, 0, s2>>>(Wo, wo16, H_, H_);
    }
    cudaEventRecord(e_join, s2);

    {
        const int n4 = (BS_ * H_) / 4;
        conv16_kernel<<<n4 / 256, 256>>>((const float4*)x, (uint2*)x16, n4);
    }
    {
        dim3 grid(QKV_N / 32, H_ / 32), blk(32, 8);
        transpose16<<<grid, blk>>>(Wqkv, wq16, H_, QKV_N);
    }
    rope_tab<<<(S_ * 64) / 256, 256>>>(rc, rs);

    {
        dim3 grid(BS_ / 128, QKV_N / 256);
        gemm_f16mma<<<grid, 256, GEMM_SMEM>>>(x16, wq16, qkv, QKV_N, H_);
    }
    {
        dim3 grid(S_ / 128, B_ * NH);
        prep_qkv<<<grid, 256, PREP_SMEM>>>(qkv, rc, rs, q16, kh, kl, vt16);
    }
    {
        dim3 grid(S_ / 128, B_ * NH);
        flash_mma<<<grid, 256, FLASH_SMEM>>>(q16, kh, kl, vt16, c16);
    }

    cudaStreamWaitEvent(0, e_join, 0);
    {
        dim3 grid(BS_ / 128, H_ / 256);
        gemm_f16mma<<<grid, 256, GEMM_SMEM>>>(c16, wo16, out, H_, H_);
    }
}

// round 16
// speedup vs baseline: 2.4496x; 1.0519x over previous
#include <cuda_runtime.h>
#include <cuda_fp16.h>
#include <math.h>
#include <stdint.h>

// Problem constants
#define B_ 2
#define S_ 2048
#define H_ 4096
#define NH 32
#define HD 128
#define BS_ (B_ * S_)          // 4096 rows
#define QKV_N (3 * H_)         // 12288

// ---------------------------------------------------------------------------
// Scratch (static device globals)
// ---------------------------------------------------------------------------
__device__ float g_qkv[(size_t)BS_ * QKV_N];
__device__ __half g_x16[(size_t)BS_ * H_];          // x fp16
__device__ __half g_wq16[(size_t)QKV_N * H_];       // Wqkv^T fp16
__device__ __half g_wo16[(size_t)H_ * H_];          // Wo^T fp16
__device__ __half g_c16[(size_t)BS_ * H_];          // ctx fp16
__device__ __half g_q16[(size_t)BS_ * H_];          // Q fp16
__device__ __half g_k16[(size_t)BS_ * H_];          // K fp16 (single)
__device__ __half g_vt16[(size_t)BS_ * H_];         // V^T fp16 [BH,128,S]
__device__ float g_rcos[S_ * 64];
__device__ float g_rsin[S_ * 64];

// ---------------------------------------------------------------------------
// mma.sync + cp.async + ldmatrix helpers
// ---------------------------------------------------------------------------
__device__ __forceinline__ uint32_t smem_u32(const void* p) {
    uint32_t a;
    asm("{ .reg .u64 t; cvta.to.shared.u64 t, %1; cvt.u32.u64 %0, t; }"
        : "=r"(a) : "l"(p));
    return a;
}

#define CP_ASYNC16(dst, src) \
    asm volatile("cp.async.cg.shared.global [%0], [%1], 16;" \
                 :: "r"(dst), "l"(src) : "memory")
#define CP_COMMIT() asm volatile("cp.async.commit_group;" ::: "memory")
#define CP_WAIT2()  asm volatile("cp.async.wait_group 2;" ::: "memory")
#define CP_WAIT1()  asm volatile("cp.async.wait_group 1;" ::: "memory")
#define CP_WAIT0()  asm volatile("cp.async.wait_group 0;" ::: "memory")

__device__ __forceinline__ void mma_f16(float* d, const uint32_t* a,
                                        uint32_t b0, uint32_t b1) {
    asm volatile(
        "mma.sync.aligned.m16n8k16.row.col.f32.f16.f16.f32 "
        "{%0,%1,%2,%3}, {%4,%5,%6,%7}, {%8,%9}, {%0,%1,%2,%3};"
        : "+f"(d[0]), "+f"(d[1]), "+f"(d[2]), "+f"(d[3])
        : "r"(a[0]), "r"(a[1]), "r"(a[2]), "r"(a[3]), "r"(b0), "r"(b1));
}

#define LDSM4(r0, r1, r2, r3, addr) \
    asm volatile("ldmatrix.sync.aligned.m8n8.x4.shared.b16 {%0,%1,%2,%3}, [%4];" \
                 : "=r"(r0), "=r"(r1), "=r"(r2), "=r"(r3) : "r"(addr))

// pack two f32 -> f16x2 (lo half = flo)
#define CVTH2(r, flo, fhi) \
    asm("cvt.rn.f16x2.f32 %0, %1, %2;" : "=r"(r) : "f"(fhi), "f"(flo))

// ---------------------------------------------------------------------------
// fp16 mma.sync GEMM:  C[M,N] = A * B^T
// Tile 128x256, BK=64, 256 threads (8 warps; warp tile 64x64),
// 3-stage cp.async pipeline, ldmatrix loads.
// ---------------------------------------------------------------------------
#define SA_STRIDE 144
#define OFF_A  0
#define OFF_B  (128 * SA_STRIDE)
#define STAGE_BYTES (128 * SA_STRIDE + 256 * SA_STRIDE)   // 55296
#define GEMM_SMEM (3 * STAGE_BYTES)                       // 165888
#define MT_STEP (16 * SA_STRIDE)

__global__ __launch_bounds__(256, 1) void gemm_f16mma(
    const __half* __restrict__ A, const __half* __restrict__ B,
    float* __restrict__ C, int Nglob, int K)
{
    extern __shared__ char smem[];
    const int tid  = threadIdx.x;
    const int lane = tid & 31;
    const int wid  = tid >> 5;
    const int wm = wid & 1;
    const int wn = wid >> 1;
    const int bm = blockIdx.x * 128;
    const int bn = blockIdx.y * 256;

    const uint32_t sb = smem_u32(smem);
    const int nchunk = K >> 6;

    auto load_chunk = [&](int c, int s) {
        const int k0 = c << 6;
        const uint32_t st = sb + s * STAGE_BYTES;
        #pragma unroll
        for (int i = 0; i < 4; i++) {
            const int idx = tid + i * 256;
            const int r = idx >> 3, seg = idx & 7;
            const size_t go = (size_t)(bm + r) * K + k0 + seg * 8;
            const uint32_t so = r * SA_STRIDE + seg * 16;
            CP_ASYNC16(st + OFF_A + so, A + go);
        }
        #pragma unroll
        for (int i = 0; i < 8; i++) {
            const int idx = tid + i * 256;
            const int r = idx >> 3, seg = idx & 7;
            const size_t go = (size_t)(bn + r) * K + k0 + seg * 8;
            const uint32_t so = r * SA_STRIDE + seg * 16;
            CP_ASYNC16(st + OFF_B + so, B + go);
        }
        CP_COMMIT();
    };

    float acc[4][8][4];
    #pragma unroll
    for (int mt = 0; mt < 4; mt++)
        #pragma unroll
        for (int nt = 0; nt < 8; nt++)
            #pragma unroll
            for (int j = 0; j < 4; j++) acc[mt][nt][j] = 0.f;

    load_chunk(0, 0);
    if (nchunk > 1) load_chunk(1, 1);
    if (nchunk > 2) load_chunk(2, 2);

    const int l7 = lane & 7, sel = lane >> 3;
    const uint32_t offA = (uint32_t)(wm * 64 + (sel & 1) * 8 + l7) * SA_STRIDE
                        + (uint32_t)(sel >> 1) * 16;
    const uint32_t offB = (uint32_t)(wn * 64 + (sel >> 1) * 8 + l7) * SA_STRIDE
                        + (uint32_t)(sel & 1) * 16;

    for (int c = 0; c < nchunk; c++) {
        if (c + 2 < nchunk)      { CP_WAIT2(); }
        else if (c + 1 < nchunk) { CP_WAIT1(); }
        else                     { CP_WAIT0(); }
        __syncthreads();

        const uint32_t st = sb + (c % 3) * STAGE_BYTES;
        const uint32_t aA = st + OFF_A + offA;
        const uint32_t aB = st + OFF_B + offB;

        #pragma unroll
        for (int ks = 0; ks < 4; ks++) {
            const uint32_t cb = ks * 32;
            uint32_t ah[4][4];
            #pragma unroll
            for (int mt = 0; mt < 4; mt++)
                LDSM4(ah[mt][0], ah[mt][1], ah[mt][2], ah[mt][3],
                      aA + mt * MT_STEP + cb);
            uint32_t bf[8][2];
            #pragma unroll
            for (int j = 0; j < 4; j++)
                LDSM4(bf[2 * j][0], bf[2 * j][1],
                      bf[2 * j + 1][0], bf[2 * j + 1][1],
                      aB + j * MT_STEP + cb);
            #pragma unroll
            for (int nt = 0; nt < 8; nt++)
                #pragma unroll
                for (int mt = 0; mt < 4; mt++)
                    mma_f16(acc[mt][nt], ah[mt], bf[nt][0], bf[nt][1]);
        }
        __syncthreads();
        if (c + 3 < nchunk) load_chunk(c + 3, c % 3);
    }

    #pragma unroll
    for (int mt = 0; mt < 4; mt++) {
        const int row = bm + wm * 64 + mt * 16 + (lane >> 2);
        float* cp0 = C + (size_t)row * Nglob + bn + wn * 64 + (lane & 3) * 2;
        float* cp8 = cp0 + 8 * (size_t)Nglob;
        #pragma unroll
        for (int nt = 0; nt < 8; nt++) {
            *(float2*)(cp0 + nt * 8) = make_float2(acc[mt][nt][0], acc[mt][nt][1]);
            *(float2*)(cp8 + nt * 8) = make_float2(acc[mt][nt][2], acc[mt][nt][3]);
        }
    }
}

// ---------------------------------------------------------------------------
// Elementwise fp32 -> fp16 conversion
// ---------------------------------------------------------------------------
__global__ void conv16_kernel(const float4* __restrict__ in,
                              uint2* __restrict__ o, int n4)
{
    const int i = blockIdx.x * blockDim.x + threadIdx.x;
    if (i >= n4) return;
    const float4 v = in[i];
    uint32_t a, b;
    CVTH2(a, v.x, v.y);
    CVTH2(b, v.z, v.w);
    uint2 r; r.x = a; r.y = b;
    o[i] = r;
}

// ---------------------------------------------------------------------------
// Transpose: W [K,N] fp32 -> Wt [N,K] fp16
// ---------------------------------------------------------------------------
__global__ void transpose16(const float* __restrict__ W,
                            __half* __restrict__ T, int K, int N)
{
    __shared__ float t[32][33];
    const int tx = threadIdx.x, ty = threadIdx.y;
    const int nx = blockIdx.x * 32;
    const int ky = blockIdx.y * 32;
    #pragma unroll
    for (int j = 0; j < 32; j += 8)
        t[ty + j][tx] = W[(size_t)(ky + ty + j) * N + nx + tx];
    __syncthreads();
    #pragma unroll
    for (int j = 0; j < 32; j += 8)
        T[(size_t)(nx + ty + j) * K + ky + tx] = __float2half(t[tx][ty + j]);
}

// ---------------------------------------------------------------------------
// RoPE cos/sin tables
// ---------------------------------------------------------------------------
__global__ void rope_tab(float* __restrict__ c, float* __restrict__ s)
{
    const int i = blockIdx.x * blockDim.x + threadIdx.x;
    const int t = i >> 6, p = i & 63;
    const float inv_freq = powf(10000.0f, -(float)p * (1.0f / 64.0f));
    float sn, cs;
    sincosf((float)t * inv_freq, &sn, &cs);
    c[i] = cs; s[i] = sn;
}

// ---------------------------------------------------------------------------
// prep_qkv: RoPE + scale; Q, K, V^T all single fp16.
// ---------------------------------------------------------------------------
#define PREP_SMEM (128 * 133 * 4)

__global__ __launch_bounds__(256, 1) void prep_qkv(
    const float* __restrict__ qkv,
    const float* __restrict__ rc, const float* __restrict__ rs,
    __half* __restrict__ Q16, __half* __restrict__ K16,
    __half* __restrict__ Vt)
{
    extern __shared__ float ps[];
    const int tid = threadIdx.x;
    const int bh = blockIdx.y;
    const int b = bh >> 5, h = bh & 31;
    const int s0 = blockIdx.x * 128;
    const float scale = 0.08838834764831843f;

    #pragma unroll 4
    for (int i = 0; i < 32; i++) {
        const int idx = tid + i * 256;
        const int sr = idx >> 6, p = idx & 63;
        const int sg = s0 + sr;
        const size_t base = ((size_t)b * S_ + sg) * QKV_N + h * HD;
        const float cs = rc[sg * 64 + p], sn = rs[sg * 64 + p];
        const float q1 = qkv[base + p],        q2 = qkv[base + p + 64];
        const float k1 = qkv[base + H_ + p],   k2 = qkv[base + H_ + p + 64];
        const size_t ob = ((size_t)bh * S_ + sg) * HD;
        Q16[ob + p]      = __float2half((q1 * cs - q2 * sn) * scale);
        Q16[ob + p + 64] = __float2half((q2 * cs + q1 * sn) * scale);
        K16[ob + p]      = __float2half(k1 * cs - k2 * sn);
        K16[ob + p + 64] = __float2half(k2 * cs + k1 * sn);
    }

    #pragma unroll 4
    for (int i = 0; i < 64; i++) {
        const int idx = tid + i * 256;
        const int sr = idx >> 7, p = idx & 127;
        ps[sr * 133 + p] = qkv[((size_t)b * S_ + s0 + sr) * QKV_N + h * HD + 2 * H_ + p];
    }
    __syncthreads();
    #pragma unroll 4
    for (int i = 0; i < 64; i++) {
        const int idx = tid + i * 256;
        const int d = idx >> 7, sr = idx & 127;
        Vt[((size_t)bh * HD + d) * S_ + s0 + sr] = __float2half(ps[sr * 133 + d]);
    }
}

// ---------------------------------------------------------------------------
// Flash attention, single-precision fp16 operands: QK 1 pass, PV 1 pass.
// ---------------------------------------------------------------------------
#define FQ_LD 136
#define FV_LD 72
#define SQ_ELEMS (128 * FQ_LD)
#define SK_ELEMS (64 * FQ_LD)
#define SV_ELEMS (128 * FV_LD)
#define FSTAGE (SK_ELEMS + SV_ELEMS)
#define FLASH_SMEM ((SQ_ELEMS + 2 * FSTAGE) * 2)   // 106496
#define KROW_STEP (16 * FQ_LD * 2)
#define VROW_STEP (16 * FV_LD * 2)

__global__ __launch_bounds__(256, 1) void flash_mma(
    const __half* __restrict__ Q16, const __half* __restrict__ K16,
    const __half* __restrict__ Vt,
    __half* __restrict__ C16)
{
    extern __shared__ __half fs[];
    const int tid = threadIdx.x;
    const int lane = tid & 31;
    const int w = tid >> 5;
    const int qblk = gridDim.x - 1 - blockIdx.x;
    const int bh = blockIdx.y;
    const int b = bh >> 5, h = bh & 31;
    const int q0 = qblk * 128;
    const uint32_t sb = smem_u32(fs);

    const size_t hoff = (size_t)bh * S_ * HD;
    const size_t voff = (size_t)bh * HD * S_;

    #pragma unroll
    for (int i = 0; i < 8; i++) {
        const int idx = tid + i * 256;
        const int r = idx >> 4, seg = idx & 15;
        const size_t go = hoff + (size_t)(q0 + r) * HD + seg * 8;
        const uint32_t so = (r * FQ_LD + seg * 8) * 2;
        CP_ASYNC16(sb + so, Q16 + go);
    }

    auto load_kv = [&](int t, int s) {
        const int k0 = t * 64;
        const uint32_t st = sb + (SQ_ELEMS + s * FSTAGE) * 2;
        #pragma unroll
        for (int i = 0; i < 4; i++) {
            const int idx = tid + i * 256;
            const int r = idx >> 4, seg = idx & 15;
            const size_t go = hoff + (size_t)(k0 + r) * HD + seg * 8;
            const uint32_t so = (r * FQ_LD + seg * 8) * 2;
            CP_ASYNC16(st + so, K16 + go);
        }
        #pragma unroll
        for (int i = 0; i < 4; i++) {
            const int idx = tid + i * 256;
            const int r = idx >> 3, seg = idx & 7;
            const size_t go = voff + (size_t)r * S_ + k0 + seg * 8;
            const uint32_t so = (SK_ELEMS + r * FV_LD + seg * 8) * 2;
            CP_ASYNC16(st + so, Vt + go);
        }
        CP_COMMIT();
    };

    load_kv(0, 0);

    float O[16][4];
    #pragma unroll
    for (int i = 0; i < 16; i++)
        #pragma unroll
        for (int j = 0; j < 4; j++) O[i][j] = 0.f;
    float m0 = -1e30f, m1 = -1e30f, l0 = 0.f, l1 = 0.f;

    const int r0 = w * 16 + (lane >> 2);
    const int cq = (lane & 3) * 2;
    const int ntiles = 2 * qblk + 2;

    const int l7 = lane & 7, sel = lane >> 3;
    const uint32_t offQ = (uint32_t)(w * 16 + (sel & 1) * 8 + l7) * (FQ_LD * 2)
                        + (uint32_t)(sel >> 1) * 16;
    const uint32_t offK = (uint32_t)((sel >> 1) * 8 + l7) * (FQ_LD * 2)
                        + (uint32_t)(sel & 1) * 16;
    const uint32_t offV = (uint32_t)((sel >> 1) * 8 + l7) * (FV_LD * 2)
                        + (uint32_t)(sel & 1) * 16;

    const uint32_t aQ = sb + offQ;

    for (int t = 0; t < ntiles; t++) {
        if (t + 1 < ntiles) { load_kv(t + 1, (t + 1) & 1); CP_WAIT1(); }
        else                { CP_WAIT0(); }
        __syncthreads();

        const uint32_t stg = sb + (SQ_ELEMS + (t & 1) * FSTAGE) * 2;
        const uint32_t aK = stg + offK;
        const uint32_t aV = stg + SK_ELEMS * 2 + offV;

        // ---- S = Q K^T (single pass) ----
        float Sf[8][4];
        #pragma unroll
        for (int nt = 0; nt < 8; nt++)
            #pragma unroll
            for (int j = 0; j < 4; j++) Sf[nt][j] = 0.f;

        #pragma unroll
        for (int kk = 0; kk < 8; kk++) {
            const uint32_t cb = kk * 32;
            uint32_t ah[4];
            LDSM4(ah[0], ah[1], ah[2], ah[3], aQ + cb);
            uint32_t khf[8][2];
            #pragma unroll
            for (int j = 0; j < 4; j++)
                LDSM4(khf[2 * j][0], khf[2 * j][1],
                      khf[2 * j + 1][0], khf[2 * j + 1][1],
                      aK + j * KROW_STEP + cb);
            #pragma unroll
            for (int nt = 0; nt < 8; nt++)
                mma_f16(Sf[nt], ah, khf[nt][0], khf[nt][1]);
        }

        // ---- mask + online softmax ----
        const int k0 = t * 64;
        const int qg0 = q0 + r0, qg1 = qg0 + 8;
        if (k0 + 63 > q0 + w * 16) {
            #pragma unroll
            for (int nt = 0; nt < 8; nt++) {
                const int kv = k0 + nt * 8 + cq;
                if (kv     > qg0) Sf[nt][0] = -1e30f;
                if (kv + 1 > qg0) Sf[nt][1] = -1e30f;
                if (kv     > qg1) Sf[nt][2] = -1e30f;
                if (kv + 1 > qg1) Sf[nt][3] = -1e30f;
            }
        }
        float mx0 = -1e30f, mx1 = -1e30f;
        #pragma unroll
        for (int nt = 0; nt < 8; nt++) {
            mx0 = fmaxf(mx0, fmaxf(Sf[nt][0], Sf[nt][1]));
            mx1 = fmaxf(mx1, fmaxf(Sf[nt][2], Sf[nt][3]));
        }
        mx0 = fmaxf(mx0, __shfl_xor_sync(0xffffffffu, mx0, 1));
        mx0 = fmaxf(mx0, __shfl_xor_sync(0xffffffffu, mx0, 2));
        mx1 = fmaxf(mx1, __shfl_xor_sync(0xffffffffu, mx1, 1));
        mx1 = fmaxf(mx1, __shfl_xor_sync(0xffffffffu, mx1, 2));

        const float mn0 = fmaxf(m0, mx0), mn1 = fmaxf(m1, mx1);
        const float a0 = __expf(m0 - mn0), a1 = __expf(m1 - mn1);
        m0 = mn0; m1 = mn1;

        float s0 = 0.f, s1 = 0.f;
        uint32_t Ph[8][2];
        #pragma unroll
        for (int nt = 0; nt < 8; nt++) {
            const float p00 = __expf(Sf[nt][0] - mn0);
            const float p01 = __expf(Sf[nt][1] - mn0);
            const float p10 = __expf(Sf[nt][2] - mn1);
            const float p11 = __expf(Sf[nt][3] - mn1);
            s0 += p00 + p01; s1 += p10 + p11;
            CVTH2(Ph[nt][0], p00, p01);
            CVTH2(Ph[nt][1], p10, p11);
        }
        s0 += __shfl_xor_sync(0xffffffffu, s0, 1);
        s0 += __shfl_xor_sync(0xffffffffu, s0, 2);
        s1 += __shfl_xor_sync(0xffffffffu, s1, 1);
        s1 += __shfl_xor_sync(0xffffffffu, s1, 2);
        l0 = l0 * a0 + s0;
        l1 = l1 * a1 + s1;

        #pragma unroll
        for (int i = 0; i < 16; i++) {
            O[i][0] *= a0; O[i][1] *= a0; O[i][2] *= a1; O[i][3] *= a1;
        }

        // ---- O += P V (single pass) ----
        #pragma unroll
        for (int ks = 0; ks < 4; ks++) {
            const uint32_t cb = ks * 32;
            const uint32_t ah[4] = {Ph[2 * ks][0], Ph[2 * ks][1],
                                    Ph[2 * ks + 1][0], Ph[2 * ks + 1][1]};
            #pragma unroll
            for (int j = 0; j < 8; j++) {
                uint32_t v00, v01, v10, v11;
                LDSM4(v00, v01, v10, v11, aV + j * VROW_STEP + cb);
                mma_f16(O[2 * j],     ah, v00, v01);
                mma_f16(O[2 * j + 1], ah, v10, v11);
            }
        }
        __syncthreads();
    }

    const float inv0 = 1.f / l0, inv1 = 1.f / l1;
    const int row0 = q0 + w * 16 + (lane >> 2);
    const size_t o0 = ((size_t)b * S_ + row0) * H_ + h * HD + cq;
    const size_t o1 = o0 + 8 * (size_t)H_;
    #pragma unroll
    for (int nt2 = 0; nt2 < 16; nt2++) {
        uint32_t hh0, hh1;
        CVTH2(hh0, O[nt2][0] * inv0, O[nt2][1] * inv0);
        CVTH2(hh1, O[nt2][2] * inv1, O[nt2][3] * inv1);
        *(uint32_t*)&C16[o0 + nt2 * 8] = hh0;
        *(uint32_t*)&C16[o1 + nt2 * 8] = hh1;
    }
}

// ---------------------------------------------------------------------------
// Launch
// ---------------------------------------------------------------------------
extern "C" void kernel_launch(void* const* d_in, const int* in_sizes, int n_in,
                              void* d_out, int out_size)
{
    const float* x    = (const float*)d_in[0];
    const float* Wqkv = (const float*)d_in[1];
    const float* Wo   = (const float*)d_in[2];
    float* out = (float*)d_out;

    float *qkv, *rc, *rs;
    __half *x16, *wq16, *wo16, *c16;
    __half *q16, *k16, *vt16;
    cudaGetSymbolAddress((void**)&qkv, g_qkv);
    cudaGetSymbolAddress((void**)&rc, g_rcos);
    cudaGetSymbolAddress((void**)&rs, g_rsin);
    cudaGetSymbolAddress((void**)&x16, g_x16);
    cudaGetSymbolAddress((void**)&wq16, g_wq16);
    cudaGetSymbolAddress((void**)&wo16, g_wo16);
    cudaGetSymbolAddress((void**)&c16, g_c16);
    cudaGetSymbolAddress((void**)&q16, g_q16);
    cudaGetSymbolAddress((void**)&k16, g_k16);
    cudaGetSymbolAddress((void**)&vt16, g_vt16);

    cudaFuncSetAttribute(gemm_f16mma,
                         cudaFuncAttributeMaxDynamicSharedMemorySize, GEMM_SMEM);
    cudaFuncSetAttribute(prep_qkv,
                         cudaFuncAttributeMaxDynamicSharedMemorySize, PREP_SMEM);
    cudaFuncSetAttribute(flash_mma,
                         cudaFuncAttributeMaxDynamicSharedMemorySize, FLASH_SMEM);

    // side stream + fork/join for Wo transpose overlap
    static cudaStream_t s2 = nullptr;
    static cudaEvent_t e_fork = nullptr, e_join = nullptr;
    if (s2 == nullptr) {
        cudaStreamCreateWithFlags(&s2, cudaStreamNonBlocking);
        cudaEventCreateWithFlags(&e_fork, cudaEventDisableTiming);
        cudaEventCreateWithFlags(&e_join, cudaEventDisableTiming);
    }

    cudaEventRecord(e_fork, 0);
    cudaStreamWaitEvent(s2, e_fork, 0);
    {
        dim3 grid(H_ / 32, H_ / 32), blk(32, 8);
        transpose16<<<grid, blk, 0, s2>>>(Wo, wo16, H_, H_);
    }
    cudaEventRecord(e_join, s2);

    {
        const int n4 = (BS_ * H_) / 4;
        conv16_kernel<<<n4 / 256, 256>>>((const float4*)x, (uint2*)x16, n4);
    }
    {
        dim3 grid(QKV_N / 32, H_ / 32), blk(32, 8);
        transpose16<<<grid, blk>>>(Wqkv, wq16, H_, QKV_N);
    }
    rope_tab<<<(S_ * 64) / 256, 256>>>(rc, rs);

    {
        dim3 grid(BS_ / 128, QKV_N / 256);
        gemm_f16mma<<<grid, 256, GEMM_SMEM>>>(x16, wq16, qkv, QKV_N, H_);
    }
    {
        dim3 grid(S_ / 128, B_ * NH);
        prep_qkv<<<grid, 256, PREP_SMEM>>>(qkv, rc, rs, q16, k16, vt16);
    }
    {
        dim3 grid(S_ / 128, B_ * NH);
        flash_mma<<<grid, 256, FLASH_SMEM>>>(q16, k16, vt16, c16);
    }

    cudaStreamWaitEvent(0, e_join, 0);
    {
        dim3 grid(BS_ / 128, H_ / 256);
        gemm_f16mma<<<grid, 256, GEMM_SMEM>>>(c16, wo16, out, H_, H_);
    }
}

// round 17
// speedup vs baseline: 2.5530x; 1.0422x over previous
#include <cuda_runtime.h>
#include <cuda_fp16.h>
#include <math.h>
#include <stdint.h>

// Problem constants
#define B_ 2
#define S_ 2048
#define H_ 4096
#define NH 32
#define HD 128
#define BS_ (B_ * S_)          // 4096 rows
#define QKV_N (3 * H_)         // 12288

// ---------------------------------------------------------------------------
// Scratch (static device globals)
// ---------------------------------------------------------------------------
__device__ float g_qkv[(size_t)BS_ * QKV_N];
__device__ __half g_x16[(size_t)BS_ * H_];
__device__ __half g_wq16[(size_t)QKV_N * H_];
__device__ __half g_wo16[(size_t)H_ * H_];
__device__ __half g_c16[(size_t)BS_ * H_];
__device__ __half g_q16[(size_t)BS_ * H_];
__device__ __half g_k16[(size_t)BS_ * H_];
__device__ __half g_vt16[(size_t)BS_ * H_];
__device__ float g_rcos[S_ * 64];
__device__ float g_rsin[S_ * 64];

// ---------------------------------------------------------------------------
// mma.sync + cp.async + ldmatrix helpers
// ---------------------------------------------------------------------------
__device__ __forceinline__ uint32_t smem_u32(const void* p) {
    uint32_t a;
    asm("{ .reg .u64 t; cvta.to.shared.u64 t, %1; cvt.u32.u64 %0, t; }"
        : "=r"(a) : "l"(p));
    return a;
}

#define CP_ASYNC16(dst, src) \
    asm volatile("cp.async.cg.shared.global [%0], [%1], 16;" \
                 :: "r"(dst), "l"(src) : "memory")
#define CP_COMMIT() asm volatile("cp.async.commit_group;" ::: "memory")
#define CP_WAIT1()  asm volatile("cp.async.wait_group 1;" ::: "memory")
#define CP_WAIT0()  asm volatile("cp.async.wait_group 0;" ::: "memory")

__device__ __forceinline__ void mma_f16(float* d, const uint32_t* a,
                                        uint32_t b0, uint32_t b1) {
    asm volatile(
        "mma.sync.aligned.m16n8k16.row.col.f32.f16.f16.f32 "
        "{%0,%1,%2,%3}, {%4,%5,%6,%7}, {%8,%9}, {%0,%1,%2,%3};"
        : "+f"(d[0]), "+f"(d[1]), "+f"(d[2]), "+f"(d[3])
        : "r"(a[0]), "r"(a[1]), "r"(a[2]), "r"(a[3]), "r"(b0), "r"(b1));
}

#define LDSM4(r0, r1, r2, r3, addr) \
    asm volatile("ldmatrix.sync.aligned.m8n8.x4.shared.b16 {%0,%1,%2,%3}, [%4];" \
                 : "=r"(r0), "=r"(r1), "=r"(r2), "=r"(r3) : "r"(addr))

#define CVTH2(r, flo, fhi) \
    asm("cvt.rn.f16x2.f32 %0, %1, %2;" : "=r"(r) : "f"(fhi), "f"(flo))

// ---------------------------------------------------------------------------
// fp16 mma.sync GEMM:  C[M,N] = A * B^T
// Tile 128x256, BK=128, 256 threads (8 warps; warp tile 64x64),
// 2-stage cp.async pipeline, ldmatrix loads.
// ---------------------------------------------------------------------------
#define SA_STRIDE 272          // 128 fp16 = 256B + 16B pad
#define OFF_A  0
#define OFF_B  (128 * SA_STRIDE)
#define STAGE_BYTES (128 * SA_STRIDE + 256 * SA_STRIDE)   // 104448
#define GEMM_SMEM (2 * STAGE_BYTES)                       // 208896
#define MT_STEP (16 * SA_STRIDE)

__global__ __launch_bounds__(256, 1) void gemm_f16mma(
    const __half* __restrict__ A, const __half* __restrict__ B,
    float* __restrict__ C, int Nglob, int K)
{
    extern __shared__ char smem[];
    const int tid  = threadIdx.x;
    const int lane = tid & 31;
    const int wid  = tid >> 5;
    const int wm = wid & 1;
    const int wn = wid >> 1;
    const int bm = blockIdx.x * 128;
    const int bn = blockIdx.y * 256;

    const uint32_t sb = smem_u32(smem);
    const int nchunk = K >> 7;       // BK=128

    auto load_chunk = [&](int c, int s) {
        const int k0 = c << 7;
        const uint32_t st = sb + s * STAGE_BYTES;
        // A: 128 rows x 16 segs of 16B
        #pragma unroll
        for (int i = 0; i < 8; i++) {
            const int idx = tid + i * 256;          // 0..2047
            const int r = idx >> 4, seg = idx & 15;
            const size_t go = (size_t)(bm + r) * K + k0 + seg * 8;
            const uint32_t so = r * SA_STRIDE + seg * 16;
            CP_ASYNC16(st + OFF_A + so, A + go);
        }
        // B: 256 rows x 16 segs
        #pragma unroll
        for (int i = 0; i < 16; i++) {
            const int idx = tid + i * 256;          // 0..4095
            const int r = idx >> 4, seg = idx & 15;
            const size_t go = (size_t)(bn + r) * K + k0 + seg * 8;
            const uint32_t so = r * SA_STRIDE + seg * 16;
            CP_ASYNC16(st + OFF_B + so, B + go);
        }
        CP_COMMIT();
    };

    float acc[4][8][4];
    #pragma unroll
    for (int mt = 0; mt < 4; mt++)
        #pragma unroll
        for (int nt = 0; nt < 8; nt++)
            #pragma unroll
            for (int j = 0; j < 4; j++) acc[mt][nt][j] = 0.f;

    load_chunk(0, 0);
    if (nchunk > 1) load_chunk(1, 1);

    const int l7 = lane & 7, sel = lane >> 3;
    const uint32_t offA = (uint32_t)(wm * 64 + (sel & 1) * 8 + l7) * SA_STRIDE
                        + (uint32_t)(sel >> 1) * 16;
    const uint32_t offB = (uint32_t)(wn * 64 + (sel >> 1) * 8 + l7) * SA_STRIDE
                        + (uint32_t)(sel & 1) * 16;

    for (int c = 0; c < nchunk; c++) {
        if (c + 1 < nchunk) { CP_WAIT1(); } else { CP_WAIT0(); }
        __syncthreads();

        const uint32_t st = sb + (c & 1) * STAGE_BYTES;
        const uint32_t aA = st + OFF_A + offA;
        const uint32_t aB = st + OFF_B + offB;

        #pragma unroll
        for (int ks = 0; ks < 8; ks++) {
            const uint32_t cb = ks * 32;
            uint32_t ah[4][4];
            #pragma unroll
            for (int mt = 0; mt < 4; mt++)
                LDSM4(ah[mt][0], ah[mt][1], ah[mt][2], ah[mt][3],
                      aA + mt * MT_STEP + cb);
            uint32_t bf[8][2];
            #pragma unroll
            for (int j = 0; j < 4; j++)
                LDSM4(bf[2 * j][0], bf[2 * j][1],
                      bf[2 * j + 1][0], bf[2 * j + 1][1],
                      aB + j * MT_STEP + cb);
            #pragma unroll
            for (int nt = 0; nt < 8; nt++)
                #pragma unroll
                for (int mt = 0; mt < 4; mt++)
                    mma_f16(acc[mt][nt], ah[mt], bf[nt][0], bf[nt][1]);
        }
        __syncthreads();
        if (c + 2 < nchunk) load_chunk(c + 2, c & 1);
    }

    #pragma unroll
    for (int mt = 0; mt < 4; mt++) {
        const int row = bm + wm * 64 + mt * 16 + (lane >> 2);
        float* cp0 = C + (size_t)row * Nglob + bn + wn * 64 + (lane & 3) * 2;
        float* cp8 = cp0 + 8 * (size_t)Nglob;
        #pragma unroll
        for (int nt = 0; nt < 8; nt++) {
            *(float2*)(cp0 + nt * 8) = make_float2(acc[mt][nt][0], acc[mt][nt][1]);
            *(float2*)(cp8 + nt * 8) = make_float2(acc[mt][nt][2], acc[mt][nt][3]);
        }
    }
}

// ---------------------------------------------------------------------------
// Elementwise fp32 -> fp16 conversion
// ---------------------------------------------------------------------------
__global__ void conv16_kernel(const float4* __restrict__ in,
                              uint2* __restrict__ o, int n4)
{
    const int i = blockIdx.x * blockDim.x + threadIdx.x;
    if (i >= n4) return;
    const float4 v = in[i];
    uint32_t a, b;
    CVTH2(a, v.x, v.y);
    CVTH2(b, v.z, v.w);
    uint2 r; r.x = a; r.y = b;
    o[i] = r;
}

// ---------------------------------------------------------------------------
// Transpose: W [K,N] fp32 -> Wt [N,K] fp16
// ---------------------------------------------------------------------------
__global__ void transpose16(const float* __restrict__ W,
                            __half* __restrict__ T, int K, int N)
{
    __shared__ float t[32][33];
    const int tx = threadIdx.x, ty = threadIdx.y;
    const int nx = blockIdx.x * 32;
    const int ky = blockIdx.y * 32;
    #pragma unroll
    for (int j = 0; j < 32; j += 8)
        t[ty + j][tx] = W[(size_t)(ky + ty + j) * N + nx + tx];
    __syncthreads();
    #pragma unroll
    for (int j = 0; j < 32; j += 8)
        T[(size_t)(nx + ty + j) * K + ky + tx] = __float2half(t[tx][ty + j]);
}

// ---------------------------------------------------------------------------
// RoPE cos/sin tables
// ---------------------------------------------------------------------------
__global__ void rope_tab(float* __restrict__ c, float* __restrict__ s)
{
    const int i = blockIdx.x * blockDim.x + threadIdx.x;
    const int t = i >> 6, p = i & 63;
    const float inv_freq = powf(10000.0f, -(float)p * (1.0f / 64.0f));
    float sn, cs;
    sincosf((float)t * inv_freq, &sn, &cs);
    c[i] = cs; s[i] = sn;
}

// ---------------------------------------------------------------------------
// prep_qkv: RoPE + scale; Q, K, V^T single fp16.
// ---------------------------------------------------------------------------
#define PREP_SMEM (128 * 133 * 4)

__global__ __launch_bounds__(256, 1) void prep_qkv(
    const float* __restrict__ qkv,
    const float* __restrict__ rc, const float* __restrict__ rs,
    __half* __restrict__ Q16, __half* __restrict__ K16,
    __half* __restrict__ Vt)
{
    extern __shared__ float ps[];
    const int tid = threadIdx.x;
    const int bh = blockIdx.y;
    const int b = bh >> 5, h = bh & 31;
    const int s0 = blockIdx.x * 128;
    const float scale = 0.08838834764831843f;

    #pragma unroll 4
    for (int i = 0; i < 32; i++) {
        const int idx = tid + i * 256;
        const int sr = idx >> 6, p = idx & 63;
        const int sg = s0 + sr;
        const size_t base = ((size_t)b * S_ + sg) * QKV_N + h * HD;
        const float cs = rc[sg * 64 + p], sn = rs[sg * 64 + p];
        const float q1 = qkv[base + p],        q2 = qkv[base + p + 64];
        const float k1 = qkv[base + H_ + p],   k2 = qkv[base + H_ + p + 64];
        const size_t ob = ((size_t)bh * S_ + sg) * HD;
        Q16[ob + p]      = __float2half((q1 * cs - q2 * sn) * scale);
        Q16[ob + p + 64] = __float2half((q2 * cs + q1 * sn) * scale);
        K16[ob + p]      = __float2half(k1 * cs - k2 * sn);
        K16[ob + p + 64] = __float2half(k2 * cs + k1 * sn);
    }

    #pragma unroll 4
    for (int i = 0; i < 64; i++) {
        const int idx = tid + i * 256;
        const int sr = idx >> 7, p = idx & 127;
        ps[sr * 133 + p] = qkv[((size_t)b * S_ + s0 + sr) * QKV_N + h * HD + 2 * H_ + p];
    }
    __syncthreads();
    #pragma unroll 4
    for (int i = 0; i < 64; i++) {
        const int idx = tid + i * 256;
        const int d = idx >> 7, sr = idx & 127;
        Vt[((size_t)bh * HD + d) * S_ + s0 + sr] = __float2half(ps[sr * 133 + d]);
    }
}

// ---------------------------------------------------------------------------
// Flash attention (unchanged from R16): QK 1 pass, PV 1 pass.
// ---------------------------------------------------------------------------
#define FQ_LD 136
#define FV_LD 72
#define SQ_ELEMS (128 * FQ_LD)
#define SK_ELEMS (64 * FQ_LD)
#define SV_ELEMS (128 * FV_LD)
#define FSTAGE (SK_ELEMS + SV_ELEMS)
#define FLASH_SMEM ((SQ_ELEMS + 2 * FSTAGE) * 2)
#define KROW_STEP (16 * FQ_LD * 2)
#define VROW_STEP (16 * FV_LD * 2)

__global__ __launch_bounds__(256, 1) void flash_mma(
    const __half* __restrict__ Q16, const __half* __restrict__ K16,
    const __half* __restrict__ Vt,
    __half* __restrict__ C16)
{
    extern __shared__ __half fs[];
    const int tid = threadIdx.x;
    const int lane = tid & 31;
    const int w = tid >> 5;
    const int qblk = gridDim.x - 1 - blockIdx.x;
    const int bh = blockIdx.y;
    const int b = bh >> 5, h = bh & 31;
    const int q0 = qblk * 128;
    const uint32_t sb = smem_u32(fs);

    const size_t hoff = (size_t)bh * S_ * HD;
    const size_t voff = (size_t)bh * HD * S_;

    #pragma unroll
    for (int i = 0; i < 8; i++) {
        const int idx = tid + i * 256;
        const int r = idx >> 4, seg = idx & 15;
        const size_t go = hoff + (size_t)(q0 + r) * HD + seg * 8;
        const uint32_t so = (r * FQ_LD + seg * 8) * 2;
        CP_ASYNC16(sb + so, Q16 + go);
    }

    auto load_kv = [&](int t, int s) {
        const int k0 = t * 64;
        const uint32_t st = sb + (SQ_ELEMS + s * FSTAGE) * 2;
        #pragma unroll
        for (int i = 0; i < 4; i++) {
            const int idx = tid + i * 256;
            const int r = idx >> 4, seg = idx & 15;
            const size_t go = hoff + (size_t)(k0 + r) * HD + seg * 8;
            const uint32_t so = (r * FQ_LD + seg * 8) * 2;
            CP_ASYNC16(st + so, K16 + go);
        }
        #pragma unroll
        for (int i = 0; i < 4; i++) {
            const int idx = tid + i * 256;
            const int r = idx >> 3, seg = idx & 7;
            const size_t go = voff + (size_t)r * S_ + k0 + seg * 8;
            const uint32_t so = (SK_ELEMS + r * FV_LD + seg * 8) * 2;
            CP_ASYNC16(st + so, Vt + go);
        }
        CP_COMMIT();
    };

    load_kv(0, 0);

    float O[16][4];
    #pragma unroll
    for (int i = 0; i < 16; i++)
        #pragma unroll
        for (int j = 0; j < 4; j++) O[i][j] = 0.f;
    float m0 = -1e30f, m1 = -1e30f, l0 = 0.f, l1 = 0.f;

    const int r0 = w * 16 + (lane >> 2);
    const int cq = (lane & 3) * 2;
    const int ntiles = 2 * qblk + 2;

    const int l7 = lane & 7, sel = lane >> 3;
    const uint32_t offQ = (uint32_t)(w * 16 + (sel & 1) * 8 + l7) * (FQ_LD * 2)
                        + (uint32_t)(sel >> 1) * 16;
    const uint32_t offK = (uint32_t)((sel >> 1) * 8 + l7) * (FQ_LD * 2)
                        + (uint32_t)(sel & 1) * 16;
    const uint32_t offV = (uint32_t)((sel >> 1) * 8 + l7) * (FV_LD * 2)
                        + (uint32_t)(sel & 1) * 16;

    const uint32_t aQ = sb + offQ;

    for (int t = 0; t < ntiles; t++) {
        if (t + 1 < ntiles) { load_kv(t + 1, (t + 1) & 1); CP_WAIT1(); }
        else                { CP_WAIT0(); }
        __syncthreads();

        const uint32_t stg = sb + (SQ_ELEMS + (t & 1) * FSTAGE) * 2;
        const uint32_t aK = stg + offK;
        const uint32_t aV = stg + SK_ELEMS * 2 + offV;

        float Sf[8][4];
        #pragma unroll
        for (int nt = 0; nt < 8; nt++)
            #pragma unroll
            for (int j = 0; j < 4; j++) Sf[nt][j] = 0.f;

        #pragma unroll
        for (int kk = 0; kk < 8; kk++) {
            const uint32_t cb = kk * 32;
            uint32_t ah[4];
            LDSM4(ah[0], ah[1], ah[2], ah[3], aQ + cb);
            uint32_t khf[8][2];
            #pragma unroll
            for (int j = 0; j < 4; j++)
                LDSM4(khf[2 * j][0], khf[2 * j][1],
                      khf[2 * j + 1][0], khf[2 * j + 1][1],
                      aK + j * KROW_STEP + cb);
            #pragma unroll
            for (int nt = 0; nt < 8; nt++)
                mma_f16(Sf[nt], ah, khf[nt][0], khf[nt][1]);
        }

        const int k0 = t * 64;
        const int qg0 = q0 + r0, qg1 = qg0 + 8;
        if (k0 + 63 > q0 + w * 16) {
            #pragma unroll
            for (int nt = 0; nt < 8; nt++) {
                const int kv = k0 + nt * 8 + cq;
                if (kv     > qg0) Sf[nt][0] = -1e30f;
                if (kv + 1 > qg0) Sf[nt][1] = -1e30f;
                if (kv     > qg1) Sf[nt][2] = -1e30f;
                if (kv + 1 > qg1) Sf[nt][3] = -1e30f;
            }
        }
        float mx0 = -1e30f, mx1 = -1e30f;
        #pragma unroll
        for (int nt = 0; nt < 8; nt++) {
            mx0 = fmaxf(mx0, fmaxf(Sf[nt][0], Sf[nt][1]));
            mx1 = fmaxf(mx1, fmaxf(Sf[nt][2], Sf[nt][3]));
        }
        mx0 = fmaxf(mx0, __shfl_xor_sync(0xffffffffu, mx0, 1));
        mx0 = fmaxf(mx0, __shfl_xor_sync(0xffffffffu, mx0, 2));
        mx1 = fmaxf(mx1, __shfl_xor_sync(0xffffffffu, mx1, 1));
        mx1 = fmaxf(mx1, __shfl_xor_sync(0xffffffffu, mx1, 2));

        const float mn0 = fmaxf(m0, mx0), mn1 = fmaxf(m1, mx1);
        const float a0 = __expf(m0 - mn0), a1 = __expf(m1 - mn1);
        m0 = mn0; m1 = mn1;

        float s0 = 0.f, s1 = 0.f;
        uint32_t Ph[8][2];
        #pragma unroll
        for (int nt = 0; nt < 8; nt++) {
            const float p00 = __expf(Sf[nt][0] - mn0);
            const float p01 = __expf(Sf[nt][1] - mn0);
            const float p10 = __expf(Sf[nt][2] - mn1);
            const float p11 = __expf(Sf[nt][3] - mn1);
            s0 += p00 + p01; s1 += p10 + p11;
            CVTH2(Ph[nt][0], p00, p01);
            CVTH2(Ph[nt][1], p10, p11);
        }
        s0 += __shfl_xor_sync(0xffffffffu, s0, 1);
        s0 += __shfl_xor_sync(0xffffffffu, s0, 2);
        s1 += __shfl_xor_sync(0xffffffffu, s1, 1);
        s1 += __shfl_xor_sync(0xffffffffu, s1, 2);
        l0 = l0 * a0 + s0;
        l1 = l1 * a1 + s1;

        #pragma unroll
        for (int i = 0; i < 16; i++) {
            O[i][0] *= a0; O[i][1] *= a0; O[i][2] *= a1; O[i][3] *= a1;
        }

        #pragma unroll
        for (int ks = 0; ks < 4; ks++) {
            const uint32_t cb = ks * 32;
            const uint32_t ah[4] = {Ph[2 * ks][0], Ph[2 * ks][1],
                                    Ph[2 * ks + 1][0], Ph[2 * ks + 1][1]};
            #pragma unroll
            for (int j = 0; j < 8; j++) {
                uint32_t v00, v01, v10, v11;
                LDSM4(v00, v01, v10, v11, aV + j * VROW_STEP + cb);
                mma_f16(O[2 * j],     ah, v00, v01);
                mma_f16(O[2 * j + 1], ah, v10, v11);
            }
        }
        __syncthreads();
    }

    const float inv0 = 1.f / l0, inv1 = 1.f / l1;
    const int row0 = q0 + w * 16 + (lane >> 2);
    const size_t o0 = ((size_t)b * S_ + row0) * H_ + h * HD + cq;
    const size_t o1 = o0 + 8 * (size_t)H_;
    #pragma unroll
    for (int nt2 = 0; nt2 < 16; nt2++) {
        uint32_t hh0, hh1;
        CVTH2(hh0, O[nt2][0] * inv0, O[nt2][1] * inv0);
        CVTH2(hh1, O[nt2][2] * inv1, O[nt2][3] * inv1);
        *(uint32_t*)&C16[o0 + nt2 * 8] = hh0;
        *(uint32_t*)&C16[o1 + nt2 * 8] = hh1;
    }
}

// ---------------------------------------------------------------------------
// Launch (Wo transpose on s2; Wqkv transpose on s3 overlapping conv16)
// ---------------------------------------------------------------------------
extern "C" void kernel_launch(void* const* d_in, const int* in_sizes, int n_in,
                              void* d_out, int out_size)
{
    const float* x    = (const float*)d_in[0];
    const float* Wqkv = (const float*)d_in[1];
    const float* Wo   = (const float*)d_in[2];
    float* out = (float*)d_out;

    float *qkv, *rc, *rs;
    __half *x16, *wq16, *wo16, *c16;
    __half *q16, *k16, *vt16;
    cudaGetSymbolAddress((void**)&qkv, g_qkv);
    cudaGetSymbolAddress((void**)&rc, g_rcos);
    cudaGetSymbolAddress((void**)&rs, g_rsin);
    cudaGetSymbolAddress((void**)&x16, g_x16);
    cudaGetSymbolAddress((void**)&wq16, g_wq16);
    cudaGetSymbolAddress((void**)&wo16, g_wo16);
    cudaGetSymbolAddress((void**)&c16, g_c16);
    cudaGetSymbolAddress((void**)&q16, g_q16);
    cudaGetSymbolAddress((void**)&k16, g_k16);
    cudaGetSymbolAddress((void**)&vt16, g_vt16);

    cudaFuncSetAttribute(gemm_f16mma,
                         cudaFuncAttributeMaxDynamicSharedMemorySize, GEMM_SMEM);
    cudaFuncSetAttribute(prep_qkv,
                         cudaFuncAttributeMaxDynamicSharedMemorySize, PREP_SMEM);
    cudaFuncSetAttribute(flash_mma,
                         cudaFuncAttributeMaxDynamicSharedMemorySize, FLASH_SMEM);

    static cudaStream_t s2 = nullptr, s3 = nullptr;
    static cudaEvent_t e_fork = nullptr, e_wo = nullptr, e_wq = nullptr;
    if (s2 == nullptr) {
        cudaStreamCreateWithFlags(&s2, cudaStreamNonBlocking);
        cudaStreamCreateWithFlags(&s3, cudaStreamNonBlocking);
        cudaEventCreateWithFlags(&e_fork, cudaEventDisableTiming);
        cudaEventCreateWithFlags(&e_wo, cudaEventDisableTiming);
        cudaEventCreateWithFlags(&e_wq, cudaEventDisableTiming);
    }

    cudaEventRecord(e_fork, 0);
    cudaStreamWaitEvent(s2, e_fork, 0);
    cudaStreamWaitEvent(s3, e_fork, 0);

    // s2: Wo transpose (needed only by final GEMM)
    {
        dim3 grid(H_ / 32, H_ / 32), blk(32, 8);
        transpose16<<<grid, blk, 0, s2>>>(Wo, wo16, H_, H_);
    }
    cudaEventRecord(e_wo, s2);

    // s3: Wqkv transpose (needed by first GEMM), overlaps conv16/rope_tab
    {
        dim3 grid(QKV_N / 32, H_ / 32), blk(32, 8);
        transpose16<<<grid, blk, 0, s3>>>(Wqkv, wq16, H_, QKV_N);
    }
    cudaEventRecord(e_wq, s3);

    // main: x conversion + rope tables
    {
        const int n4 = (BS_ * H_) / 4;
        conv16_kernel<<<n4 / 256, 256>>>((const float4*)x, (uint2*)x16, n4);
    }
    rope_tab<<<(S_ * 64) / 256, 256>>>(rc, rs);

    cudaStreamWaitEvent(0, e_wq, 0);
    {
        dim3 grid(BS_ / 128, QKV_N / 256);
        gemm_f16mma<<<grid, 256, GEMM_SMEM>>>(x16, wq16, qkv, QKV_N, H_);
    }
    {
        dim3 grid(S_ / 128, B_ * NH);
        prep_qkv<<<grid, 256, PREP_SMEM>>>(qkv, rc, rs, q16, k16, vt16);
    }
    {
        dim3 grid(S_ / 128, B_ * NH);
        flash_mma<<<grid, 256, FLASH_SMEM>>>(q16, k16, vt16, c16);
    }

    cudaStreamWaitEvent(0, e_wo, 0);
    {
        dim3 grid(BS_ / 128, H_ / 256);
        gemm_f16mma<<<grid, 256, GEMM_SMEM>>>(c16, wo16, out, H_, H_);
    }
}